// round 4
// baseline (speedup 1.0000x reference)
#include <cuda_runtime.h>
#include <cuda_bf16.h>
#include <cstdint>

#define BATCH 2048
#define RPOS  60
#define KW    13
#define CIN   64
#define CMID  64
#define COUT  128
#define EPSV  1e-5f

// ---------------------------------------------------------------------------
// Device scratch: y tensors as bf16 hi/lo, layout [b][r][c] (128B rows)
// ---------------------------------------------------------------------------
__device__ __nv_bfloat16 g_y1h[BATCH * RPOS * CIN];
__device__ __nv_bfloat16 g_y1l[BATCH * RPOS * CIN];
__device__ __nv_bfloat16 g_y2h[BATCH * RPOS * CMID];
__device__ __nv_bfloat16 g_y2l[BATCH * RPOS * CMID];
__device__ __nv_bfloat16 g_y3h[BATCH * RPOS * CIN];
__device__ __nv_bfloat16 g_y3l[BATCH * RPOS * CIN];
// Packed weights: [hl][k][o][c] bf16, XOR-swizzle on 16B granules pre-applied.
__device__ __nv_bfloat16 g_W1p[2 * KW * CMID * CIN];
__device__ __nv_bfloat16 g_W2p[2 * KW * COUT * CMID];
__device__ __nv_bfloat16 g_W3p[2 * KW * COUT * CMID];

// ---------------------------------------------------------------------------
// PTX helpers (baseline features only)
// ---------------------------------------------------------------------------
__device__ __forceinline__ uint32_t smem_u32(const void* p) {
    uint32_t a;
    asm("{ .reg .u64 t; cvta.to.shared.u64 t, %1; cvt.u32.u64 %0, t; }" : "=r"(a) : "l"(p));
    return a;
}

#define CP_ASYNC16(dst, src) \
    asm volatile("cp.async.cg.shared.global [%0], [%1], 16;" :: "r"(dst), "l"(src) : "memory")
#define CP_COMMIT()  asm volatile("cp.async.commit_group;" ::: "memory")
#define CP_WAIT(n)   asm volatile("cp.async.wait_group %0;" :: "n"(n) : "memory")

#define LDMX4(r0, r1, r2, r3, addr) \
    asm volatile("ldmatrix.sync.aligned.m8n8.x4.shared.b16 {%0,%1,%2,%3}, [%4];" \
        : "=r"(r0), "=r"(r1), "=r"(r2), "=r"(r3) : "r"(addr))

__device__ __forceinline__ void mma16816(float* d, const uint32_t* a, const uint32_t* b) {
    asm volatile("mma.sync.aligned.m16n8k16.row.col.f32.bf16.bf16.f32 "
        "{%0,%1,%2,%3},{%4,%5,%6,%7},{%8,%9},{%0,%1,%2,%3};"
        : "+f"(d[0]), "+f"(d[1]), "+f"(d[2]), "+f"(d[3])
        : "r"(a[0]), "r"(a[1]), "r"(a[2]), "r"(a[3]), "r"(b[0]), "r"(b[1]));
}

__device__ __forceinline__ void split2(float a, float b, uint32_t& h, uint32_t& l) {
    __nv_bfloat16 ha = __float2bfloat16(a), hb = __float2bfloat16(b);
    __nv_bfloat16 la = __float2bfloat16(a - __bfloat162float(ha));
    __nv_bfloat16 lb = __float2bfloat16(b - __bfloat162float(hb));
    h = (uint32_t)__bfloat16_as_ushort(ha) | ((uint32_t)__bfloat16_as_ushort(hb) << 16);
    l = (uint32_t)__bfloat16_as_ushort(la) | ((uint32_t)__bfloat16_as_ushort(lb) << 16);
}

__device__ __forceinline__ void copy_row8(uint32_t dst, const char* src, int sw) {
#pragma unroll
    for (int g = 0; g < 8; g++) CP_ASYNC16(dst + (uint32_t)((g << 4) ^ sw), src + (g << 4));
}

// ---------------------------------------------------------------------------
// prep
// ---------------------------------------------------------------------------
__global__ void prep_kernel(const float* __restrict__ x,
                            const float* __restrict__ g1, const float* __restrict__ b1,
                            const float* __restrict__ m1, const float* __restrict__ v1,
                            const float* __restrict__ g3, const float* __restrict__ b3,
                            const float* __restrict__ m3, const float* __restrict__ v3)
{
    __shared__ float xs[64 * 61];
    __shared__ float s1a[64], s1b[64], s3a[64], s3b[64];
    int b = blockIdx.x, t = threadIdx.x;

    if (t < 64) {
        float i1 = g1[t] * rsqrtf(v1[t] + EPSV);
        s1a[t] = i1; s1b[t] = b1[t] - m1[t] * i1;
        float i3 = g3[t] * rsqrtf(v3[t] + EPSV);
        s3a[t] = i3; s3b[t] = b3[t] - m3[t] * i3;
    }
    const float* xb = x + (size_t)b * (CIN * RPOS);
    for (int i = t; i < CIN * RPOS; i += 256)
        xs[(i / RPOS) * 61 + (i % RPOS)] = xb[i];
    __syncthreads();

    uint32_t* y1h = (uint32_t*)g_y1h + (size_t)b * (RPOS * 32);
    uint32_t* y1l = (uint32_t*)g_y1l + (size_t)b * (RPOS * 32);
    uint32_t* y3h = (uint32_t*)g_y3h + (size_t)b * (RPOS * 32);
    uint32_t* y3l = (uint32_t*)g_y3l + (size_t)b * (RPOS * 32);
    for (int i = t; i < RPOS * 32; i += 256) {
        int j = i >> 5, c = (i & 31) * 2;
        float xa = xs[c * 61 + j], xc = xs[(c + 1) * 61 + j];
        float a1 = fmaxf(fmaf(xa, s1a[c], s1b[c]), 0.0f);
        float b1v = fmaxf(fmaf(xc, s1a[c + 1], s1b[c + 1]), 0.0f);
        float a3 = fmaxf(fmaf(xa, s3a[c], s3b[c]), 0.0f);
        float b3v = fmaxf(fmaf(xc, s3a[c + 1], s3b[c + 1]), 0.0f);
        uint32_t h, l;
        split2(a1, b1v, h, l); y1h[i] = h; y1l[i] = l;
        split2(a3, b3v, h, l); y3h[i] = h; y3l[i] = l;
    }
}

// ---------------------------------------------------------------------------
// packW
// ---------------------------------------------------------------------------
__global__ void packW_kernel(const float* __restrict__ W1, const float* __restrict__ W2,
                             const float* __restrict__ W3)
{
    int idx = blockIdx.x * 256 + threadIdx.x;
    const int n1 = KW * CMID * CIN, n2 = KW * COUT * CMID;
    const float* W; __nv_bfloat16* dst; int O, nloc;
    if (idx < n1)             { W = W1; dst = g_W1p; O = CMID; nloc = idx;           }
    else if (idx < n1 + n2)   { W = W2; dst = g_W2p; O = COUT; nloc = idx - n1;      }
    else if (idx < n1 + 2*n2) { W = W3; dst = g_W3p; O = COUT; nloc = idx - n1 - n2; }
    else return;
    int k = nloc / (O * 64), rem = nloc % (O * 64);
    int o = rem / 64, c = rem % 64;
    float v = W[o * (64 * KW) + c * KW + k];
    __nv_bfloat16 h = __float2bfloat16(v);
    __nv_bfloat16 l = __float2bfloat16(v - __bfloat162float(h));
    int sw = ((c >> 3) ^ (o & 7)) * 8 + (c & 7);
    int n = KW * O * 64;
    dst[(size_t)(k * O + o) * 64 + sw] = h;
    dst[(size_t)n + (size_t)(k * O + o) * 64 + sw] = l;
}

// ---------------------------------------------------------------------------
// conv_mid: 512 threads, 16 warps (4m x 4n), warp tile 32x16.
// CTA: 2 batches -> M=128 (120 real), N=64, 13 k-stages of K=64.
// ---------------------------------------------------------------------------
#define MID_SLOT 49152u
#define MID_NEI  98304u
#define MID_BIAS (98304u + 3136u)

__global__ __launch_bounds__(512, 1)
void conv_mid_kernel(const int* __restrict__ nei, const float* __restrict__ c1,
                     const float* __restrict__ g2, const float* __restrict__ b2,
                     const float* __restrict__ m2, const float* __restrict__ v2)
{
    extern __shared__ __align__(1024) char smb[];
    uint32_t sbase = smem_u32(smb);

    int t = threadIdx.x, wid = t >> 5, l = t & 31;
    int*   snei  = (int*)(smb + MID_NEI);
    float* sbias = (float*)(smb + MID_BIAS);

    for (int i = t; i < RPOS * KW; i += 512) snei[i] = nei[i];
    if (t < 64) {
        sbias[t] = c1[t];
        float iv = g2[t] * rsqrtf(v2[t] + EPSV);
        sbias[64 + t] = iv; sbias[128 + t] = b2[t] - m2[t] * iv;
    }
    __syncthreads();

    int b0 = blockIdx.x * 2;
    // copy role: t<256 -> A row, 256<=t<384 -> W row
    bool isA = t < 256;
    int hlA = (t >> 7) & 1, rowA = t & 127;
    int bbA = (rowA >= 60 && rowA < 120) ? 1 : 0;
    int rA  = rowA - bbA * 60 - (rowA >= 120 ? 120 : 0);
    const char* ybase = (const char*)(hlA ? g_y1l : g_y1h)
                      + (((size_t)(b0 + bbA) * RPOS) << 7);
    int swA = (rowA & 7) << 4;
    int hlW = (t >> 6) & 1, oW = t & 63;          // for t in [256,384)

    // stage 0
    {
        if (isA) {
            int j = snei[rA * KW + 0];
            copy_row8(sbase + (uint32_t)((hlA << 7) + rowA) * 128, ybase + ((size_t)j << 7), swA);
        } else if (t < 384) {
            const char* ws = (const char*)g_W1p + ((size_t)(hlW * KW * CMID + oW) << 7);
            copy_row8(sbase + 32768u + (uint32_t)((hlW << 6) + oW) * 128, ws, 0);
        }
        CP_COMMIT();
    }

    int m0 = (wid & 3) * 32, n0 = (wid >> 2) * 16;
    int lrA = l & 15, lgA = l >> 4;
    int lrB = (l & 7) + ((l >> 4) << 3), lgB = (l >> 3) & 1;

    float acc[2][2][4];
#pragma unroll
    for (int a = 0; a < 2; a++)
#pragma unroll
        for (int b = 0; b < 2; b++)
#pragma unroll
            for (int c = 0; c < 4; c++) acc[a][b][c] = 0.0f;

    for (int s = 0; s < KW; s++) {
        if (s + 1 < KW) {
            uint32_t slot = sbase + (uint32_t)((s + 1) & 1) * MID_SLOT;
            if (isA) {
                int j = snei[rA * KW + s + 1];
                copy_row8(slot + (uint32_t)((hlA << 7) + rowA) * 128, ybase + ((size_t)j << 7), swA);
            } else if (t < 384) {
                const char* ws = (const char*)g_W1p
                               + ((size_t)(hlW * KW * CMID + (s + 1) * CMID + oW) << 7);
                copy_row8(slot + 32768u + (uint32_t)((hlW << 6) + oW) * 128, ws, 0);
            }
            CP_COMMIT();
            CP_WAIT(1);
        } else {
            CP_WAIT(0);
        }
        __syncthreads();

        uint32_t Ab = sbase + (uint32_t)(s & 1) * MID_SLOT;
        uint32_t Wb = Ab + 32768u;
#pragma unroll
        for (int ks = 0; ks < 4; ks++) {
            uint32_t ah[2][4], al[2][4], bh[4], bl[4];
#pragma unroll
            for (int mt = 0; mt < 2; mt++) {
                int row = m0 + mt * 16 + lrA;
                uint32_t ad = Ab + (uint32_t)row * 128
                            + (uint32_t)((((ks << 1) + lgA) ^ (row & 7)) << 4);
                LDMX4(ah[mt][0], ah[mt][1], ah[mt][2], ah[mt][3], ad);
                LDMX4(al[mt][0], al[mt][1], al[mt][2], al[mt][3], ad + 16384u);
            }
            {
                int row = n0 + lrB;
                uint32_t bd = Wb + (uint32_t)row * 128
                            + (uint32_t)((((ks << 1) + lgB) ^ (row & 7)) << 4);
                LDMX4(bh[0], bh[1], bh[2], bh[3], bd);
                LDMX4(bl[0], bl[1], bl[2], bl[3], bd + 8192u);
            }
#pragma unroll
            for (int mt = 0; mt < 2; mt++)
#pragma unroll
                for (int nt = 0; nt < 2; nt++) {
                    float* d = acc[mt][nt];
                    const uint32_t* B0 = &bh[nt * 2];
                    const uint32_t* B1 = &bl[nt * 2];
                    mma16816(d, ah[mt], B0);
                    mma16816(d, ah[mt], B1);
                    mma16816(d, al[mt], B0);
                }
        }
        __syncthreads();
    }

    // epilogue: bn2+relu, split, store y2
#pragma unroll
    for (int mt = 0; mt < 2; mt++)
#pragma unroll
        for (int nt = 0; nt < 2; nt++) {
            float* d = acc[mt][nt];
            int o = n0 + nt * 8 + ((l & 3) << 1);
            float cv0 = sbias[o],       cv1 = sbias[o + 1];
            float i0  = sbias[64 + o],  i1  = sbias[65 + o];
            float a0  = sbias[128 + o], a1  = sbias[129 + o];
#pragma unroll
            for (int h = 0; h < 2; h++) {
                int m = m0 + mt * 16 + (l >> 2) + h * 8;
                if (m < 120) {
                    int bb = (m >= 60); int r = m - bb * 60;
                    float y0 = fmaxf(fmaf(d[h * 2]     + cv0, i0, a0), 0.0f);
                    float y1 = fmaxf(fmaf(d[h * 2 + 1] + cv1, i1, a1), 0.0f);
                    uint32_t hh, ll; split2(y0, y1, hh, ll);
                    size_t off = (((size_t)(b0 + bb) * RPOS + r) << 5) + (o >> 1);
                    ((uint32_t*)g_y2h)[off] = hh;
                    ((uint32_t*)g_y2l)[off] = ll;
                }
            }
        }
}

// ---------------------------------------------------------------------------
// conv_out: 512 threads, 16 warps (4m x 4n), warp tile 32x32.
// CTA: 2 batches -> M=128, N=128, 26 k-stages.
// ---------------------------------------------------------------------------
#define OUT_SLOT 65536u
#define OUT_NEI  131072u
#define OUT_BIAS (131072u + 3136u)

__global__ __launch_bounds__(512, 1)
void conv_out_kernel(const int* __restrict__ nei, const float* __restrict__ c2,
                     const float* __restrict__ c3, float* __restrict__ out)
{
    extern __shared__ __align__(1024) char smb[];
    uint32_t sbase = smem_u32(smb);

    int t = threadIdx.x, wid = t >> 5, l = t & 31;
    int*   snei  = (int*)(smb + OUT_NEI);
    float* sbias = (float*)(smb + OUT_BIAS);

    for (int i = t; i < RPOS * KW; i += 512) snei[i] = nei[i];
    if (t < 128) sbias[t] = c2[t] + c3[t];
    __syncthreads();

    int b0 = blockIdx.x * 2;
    bool isA = t < 256;
    int hlA = (t >> 7) & 1, rowA = t & 127;
    int bbA = (rowA >= 60 && rowA < 120) ? 1 : 0;
    int rA  = rowA - bbA * 60 - (rowA >= 120 ? 120 : 0);
    int swA = (rowA & 7) << 4;
    size_t ybOff = ((size_t)(b0 + bbA) * RPOS) << 7;
    int hlW = (t >> 7) & 1, oW = t & 127;         // for t in [256,512)

    // stage 0 (phase 0: y2 / W2)
    {
        if (isA) {
            int j = snei[rA * KW + 0];
            const char* ya = (const char*)(hlA ? g_y2l : g_y2h) + ybOff;
            copy_row8(sbase + (uint32_t)((hlA << 7) + rowA) * 128, ya + ((size_t)j << 7), swA);
        } else {
            const char* ws = (const char*)g_W2p + ((size_t)(hlW * KW * COUT + oW) << 7);
            copy_row8(sbase + 32768u + (uint32_t)((hlW << 7) + oW) * 128, ws, 0);
        }
        CP_COMMIT();
    }

    int m0 = (wid & 3) * 32, n0 = (wid >> 2) * 32;
    int lrA = l & 15, lgA = l >> 4;
    int lrB = (l & 7) + ((l >> 4) << 3), lgB = (l >> 3) & 1;

    float acc[2][4][4];
#pragma unroll
    for (int a = 0; a < 2; a++)
#pragma unroll
        for (int b = 0; b < 4; b++)
#pragma unroll
            for (int c = 0; c < 4; c++) acc[a][b][c] = 0.0f;

    const int S = 2 * KW;
    for (int s = 0; s < S; s++) {
        if (s + 1 < S) {
            int sn = s + 1;
            int ph = sn >= KW, k = sn - ph * KW;
            uint32_t slot = sbase + (uint32_t)(sn & 1) * OUT_SLOT;
            if (isA) {
                int j = snei[rA * KW + k];
                const char* ya = (const char*)(ph ? (hlA ? g_y3l : g_y3h)
                                                  : (hlA ? g_y2l : g_y2h)) + ybOff;
                copy_row8(slot + (uint32_t)((hlA << 7) + rowA) * 128, ya + ((size_t)j << 7), swA);
            } else {
                const char* ws = (const char*)(ph ? g_W3p : g_W2p)
                               + ((size_t)(hlW * KW * COUT + k * COUT + oW) << 7);
                copy_row8(slot + 32768u + (uint32_t)((hlW << 7) + oW) * 128, ws, 0);
            }
            CP_COMMIT();
            CP_WAIT(1);
        } else {
            CP_WAIT(0);
        }
        __syncthreads();

        uint32_t Ab = sbase + (uint32_t)(s & 1) * OUT_SLOT;
        uint32_t Wb = Ab + 32768u;
#pragma unroll
        for (int ks = 0; ks < 4; ks++) {
            uint32_t ah[2][4], al[2][4], bh[2][4], bl[2][4];
#pragma unroll
            for (int mt = 0; mt < 2; mt++) {
                int row = m0 + mt * 16 + lrA;
                uint32_t ad = Ab + (uint32_t)row * 128
                            + (uint32_t)((((ks << 1) + lgA) ^ (row & 7)) << 4);
                LDMX4(ah[mt][0], ah[mt][1], ah[mt][2], ah[mt][3], ad);
                LDMX4(al[mt][0], al[mt][1], al[mt][2], al[mt][3], ad + 16384u);
            }
#pragma unroll
            for (int q = 0; q < 2; q++) {
                int row = n0 + q * 16 + lrB;
                uint32_t bd = Wb + (uint32_t)row * 128
                            + (uint32_t)((((ks << 1) + lgB) ^ (row & 7)) << 4);
                LDMX4(bh[q][0], bh[q][1], bh[q][2], bh[q][3], bd);
                LDMX4(bl[q][0], bl[q][1], bl[q][2], bl[q][3], bd + 16384u);
            }
#pragma unroll
            for (int mt = 0; mt < 2; mt++)
#pragma unroll
                for (int nt = 0; nt < 4; nt++) {
                    float* d = acc[mt][nt];
                    const uint32_t* B0 = &bh[nt >> 1][(nt & 1) * 2];
                    const uint32_t* B1 = &bl[nt >> 1][(nt & 1) * 2];
                    mma16816(d, ah[mt], B0);
                    mma16816(d, ah[mt], B1);
                    mma16816(d, al[mt], B0);
                }
        }
        __syncthreads();
    }

    // epilogue: +bias, transpose in smem to [o][m] (stride 132), coalesced store
    float* T = (float*)smb;
#pragma unroll
    for (int mt = 0; mt < 2; mt++)
#pragma unroll
        for (int nt = 0; nt < 4; nt++) {
            float* d = acc[mt][nt];
            int o = n0 + nt * 8 + ((l & 3) << 1);
            float bv0 = sbias[o], bv1 = sbias[o + 1];
#pragma unroll
            for (int h = 0; h < 2; h++) {
                int m = m0 + mt * 16 + (l >> 2) + h * 8;
                T[(size_t)o * 132 + m]       = d[h * 2]     + bv0;
                T[(size_t)(o + 1) * 132 + m] = d[h * 2 + 1] + bv1;
            }
        }
    __syncthreads();

    if (t < 256) {
        int o = t >> 1, bb = t & 1;
        const float4* src = (const float4*)(T + (size_t)o * 132 + bb * 60);
        float4* dst = (float4*)(out + ((size_t)(b0 + bb) * COUT + o) * RPOS);
#pragma unroll
        for (int q = 0; q < 15; q++) dst[q] = src[q];
    }
}

// ---------------------------------------------------------------------------
extern "C" void kernel_launch(void* const* d_in, const int* in_sizes, int n_in,
                              void* d_out, int out_size)
{
    const float* x   = (const float*)d_in[0];
    const int*   nei = (const int*)d_in[1];
    const float* g1 = (const float*)d_in[2];
    const float* b1 = (const float*)d_in[3];
    const float* m1 = (const float*)d_in[4];
    const float* v1 = (const float*)d_in[5];
    const float* W1 = (const float*)d_in[6];
    const float* c1 = (const float*)d_in[7];
    const float* g2 = (const float*)d_in[8];
    const float* b2 = (const float*)d_in[9];
    const float* m2 = (const float*)d_in[10];
    const float* v2 = (const float*)d_in[11];
    const float* W2 = (const float*)d_in[12];
    const float* c2 = (const float*)d_in[13];
    const float* g3 = (const float*)d_in[14];
    const float* b3 = (const float*)d_in[15];
    const float* m3 = (const float*)d_in[16];
    const float* v3 = (const float*)d_in[17];
    const float* W3 = (const float*)d_in[18];
    const float* c3 = (const float*)d_in[19];
    float* out = (float*)d_out;

    const int smem_mid = (int)(MID_BIAS + 768 + 256);      // ~102.5 KB
    const int smem_out = (int)(OUT_BIAS + 512 + 256);      // ~135 KB
    cudaFuncSetAttribute(conv_mid_kernel, cudaFuncAttributeMaxDynamicSharedMemorySize, smem_mid);
    cudaFuncSetAttribute(conv_out_kernel, cudaFuncAttributeMaxDynamicSharedMemorySize, smem_out);

    prep_kernel<<<BATCH, 256>>>(x, g1, b1, m1, v1, g3, b3, m3, v3);
    packW_kernel<<<(KW * (CMID * CIN + 2 * COUT * CMID) + 255) / 256, 256>>>(W1, W2, W3);
    conv_mid_kernel<<<BATCH / 2, 512, smem_mid>>>(nei, c1, g2, b2, m2, v2);
    conv_out_kernel<<<BATCH / 2, 512, smem_out>>>(nei, c2, c3, out);
}

// round 5
// speedup vs baseline: 1.4487x; 1.4487x over previous
#include <cuda_runtime.h>
#include <cuda_bf16.h>
#include <cstdint>

#define BATCH 2048
#define RPOS  60
#define KW    13
#define CIN   64
#define CMID  64
#define COUT  128
#define EPSV  1e-5f

// ---------------------------------------------------------------------------
// Device scratch: y tensors as bf16 hi/lo, layout [b][r][c] (128B rows)
// ---------------------------------------------------------------------------
__device__ __align__(128) __nv_bfloat16 g_y1h[BATCH * RPOS * CIN];
__device__ __align__(128) __nv_bfloat16 g_y1l[BATCH * RPOS * CIN];
__device__ __align__(128) __nv_bfloat16 g_y2h[BATCH * RPOS * CMID];
__device__ __align__(128) __nv_bfloat16 g_y2l[BATCH * RPOS * CMID];
__device__ __align__(128) __nv_bfloat16 g_y3h[BATCH * RPOS * CIN];
__device__ __align__(128) __nv_bfloat16 g_y3l[BATCH * RPOS * CIN];
// Packed weights: [hl][k][o][c] bf16, XOR-swizzle on 16B granules pre-applied.
__device__ __align__(128) __nv_bfloat16 g_W1p[2 * KW * CMID * CIN];
__device__ __align__(128) __nv_bfloat16 g_W2p[2 * KW * COUT * CMID];
__device__ __align__(128) __nv_bfloat16 g_W3p[2 * KW * COUT * CMID];

// ---------------------------------------------------------------------------
// PTX helpers (baseline features only)
// ---------------------------------------------------------------------------
__device__ __forceinline__ uint32_t smem_u32(const void* p) {
    uint32_t a;
    asm("{ .reg .u64 t; cvta.to.shared.u64 t, %1; cvt.u32.u64 %0, t; }" : "=r"(a) : "l"(p));
    return a;
}

#define CP_ASYNC16(dst, src) \
    asm volatile("cp.async.cg.shared.global [%0], [%1], 16;" :: "r"(dst), "l"(src) : "memory")
#define CP_COMMIT()  asm volatile("cp.async.commit_group;" ::: "memory")
#define CP_WAIT(n)   asm volatile("cp.async.wait_group %0;" :: "n"(n) : "memory")

#define LDMX4(r0, r1, r2, r3, addr) \
    asm volatile("ldmatrix.sync.aligned.m8n8.x4.shared.b16 {%0,%1,%2,%3}, [%4];" \
        : "=r"(r0), "=r"(r1), "=r"(r2), "=r"(r3) : "r"(addr))

__device__ __forceinline__ void mma16816(float* d, const uint32_t* a, const uint32_t* b) {
    asm volatile("mma.sync.aligned.m16n8k16.row.col.f32.bf16.bf16.f32 "
        "{%0,%1,%2,%3},{%4,%5,%6,%7},{%8,%9},{%0,%1,%2,%3};"
        : "+f"(d[0]), "+f"(d[1]), "+f"(d[2]), "+f"(d[3])
        : "r"(a[0]), "r"(a[1]), "r"(a[2]), "r"(a[3]), "r"(b[0]), "r"(b[1]));
}

__device__ __forceinline__ void split2(float a, float b, uint32_t& h, uint32_t& l) {
    __nv_bfloat16 ha = __float2bfloat16(a), hb = __float2bfloat16(b);
    __nv_bfloat16 la = __float2bfloat16(a - __bfloat162float(ha));
    __nv_bfloat16 lb = __float2bfloat16(b - __bfloat162float(hb));
    h = (uint32_t)__bfloat16_as_ushort(ha) | ((uint32_t)__bfloat16_as_ushort(hb) << 16);
    l = (uint32_t)__bfloat16_as_ushort(la) | ((uint32_t)__bfloat16_as_ushort(lb) << 16);
}

// copy one 128B row, applying per-row XOR swizzle (key sw = (row&7)<<4)
__device__ __forceinline__ void copy_row8(uint32_t dst, const char* src, int sw) {
#pragma unroll
    for (int g = 0; g < 8; g++) CP_ASYNC16(dst + (uint32_t)((g << 4) ^ sw), src + (g << 4));
}

// ---------------------------------------------------------------------------
// prep
// ---------------------------------------------------------------------------
__global__ void prep_kernel(const float* __restrict__ x,
                            const float* __restrict__ g1, const float* __restrict__ b1,
                            const float* __restrict__ m1, const float* __restrict__ v1,
                            const float* __restrict__ g3, const float* __restrict__ b3,
                            const float* __restrict__ m3, const float* __restrict__ v3)
{
    __shared__ float xs[64 * 61];
    __shared__ float s1a[64], s1b[64], s3a[64], s3b[64];
    int b = blockIdx.x, t = threadIdx.x;

    if (t < 64) {
        float i1 = g1[t] * rsqrtf(v1[t] + EPSV);
        s1a[t] = i1; s1b[t] = b1[t] - m1[t] * i1;
        float i3 = g3[t] * rsqrtf(v3[t] + EPSV);
        s3a[t] = i3; s3b[t] = b3[t] - m3[t] * i3;
    }
    const float* xb = x + (size_t)b * (CIN * RPOS);
    for (int i = t; i < CIN * RPOS; i += 256)
        xs[(i / RPOS) * 61 + (i % RPOS)] = xb[i];
    __syncthreads();

    uint32_t* y1h = (uint32_t*)g_y1h + (size_t)b * (RPOS * 32);
    uint32_t* y1l = (uint32_t*)g_y1l + (size_t)b * (RPOS * 32);
    uint32_t* y3h = (uint32_t*)g_y3h + (size_t)b * (RPOS * 32);
    uint32_t* y3l = (uint32_t*)g_y3l + (size_t)b * (RPOS * 32);
    for (int i = t; i < RPOS * 32; i += 256) {
        int j = i >> 5, c = (i & 31) * 2;
        float xa = xs[c * 61 + j], xc = xs[(c + 1) * 61 + j];
        float a1 = fmaxf(fmaf(xa, s1a[c], s1b[c]), 0.0f);
        float b1v = fmaxf(fmaf(xc, s1a[c + 1], s1b[c + 1]), 0.0f);
        float a3 = fmaxf(fmaf(xa, s3a[c], s3b[c]), 0.0f);
        float b3v = fmaxf(fmaf(xc, s3a[c + 1], s3b[c + 1]), 0.0f);
        uint32_t h, l;
        split2(a1, b1v, h, l); y1h[i] = h; y1l[i] = l;
        split2(a3, b3v, h, l); y3h[i] = h; y3l[i] = l;
    }
}

// ---------------------------------------------------------------------------
// packW
// ---------------------------------------------------------------------------
__global__ void packW_kernel(const float* __restrict__ W1, const float* __restrict__ W2,
                             const float* __restrict__ W3)
{
    int idx = blockIdx.x * 256 + threadIdx.x;
    const int n1 = KW * CMID * CIN, n2 = KW * COUT * CMID;
    const float* W; __nv_bfloat16* dst; int O, nloc;
    if (idx < n1)             { W = W1; dst = g_W1p; O = CMID; nloc = idx;           }
    else if (idx < n1 + n2)   { W = W2; dst = g_W2p; O = COUT; nloc = idx - n1;      }
    else if (idx < n1 + 2*n2) { W = W3; dst = g_W3p; O = COUT; nloc = idx - n1 - n2; }
    else return;
    int k = nloc / (O * 64), rem = nloc % (O * 64);
    int o = rem / 64, c = rem % 64;
    float v = W[o * (64 * KW) + c * KW + k];
    __nv_bfloat16 h = __float2bfloat16(v);
    __nv_bfloat16 l = __float2bfloat16(v - __bfloat162float(h));
    int sw = ((c >> 3) ^ (o & 7)) * 8 + (c & 7);
    int n = KW * O * 64;
    dst[(size_t)(k * O + o) * 64 + sw] = h;
    dst[(size_t)n + (size_t)(k * O + o) * 64 + sw] = l;
}

// ---------------------------------------------------------------------------
// conv_mid: CTA = 4 batches (M=256, 240 real), N=64. 512 threads, 16 warps
// (8m x 2n), warp tile 32x32. y1 resident in smem; gather done via ldmatrix
// addressing. Only W is double-buffered per k-stage.
// smem: Y1 61440 | W 2x16384 | nei 3120 | bias 768
// ---------------------------------------------------------------------------
#define MIDY  61440u
#define MIDW  16384u
#define MIDNEI (MIDY + 2u * MIDW)
#define MIDBIAS (MIDNEI + 3136u)

__global__ __launch_bounds__(512, 1)
void conv_mid_kernel(const int* __restrict__ nei, const float* __restrict__ c1,
                     const float* __restrict__ g2, const float* __restrict__ b2,
                     const float* __restrict__ m2, const float* __restrict__ v2)
{
    extern __shared__ __align__(1024) char smb[];
    uint32_t sbase = smem_u32(smb);

    int t = threadIdx.x, wid = t >> 5, l = t & 31;
    int*   snei  = (int*)(smb + MIDNEI);
    float* sbias = (float*)(smb + MIDBIAS);

    for (int i = t; i < RPOS * KW; i += 512) snei[i] = nei[i];
    if (t < 64) {
        sbias[t] = c1[t];
        float iv = g2[t] * rsqrtf(v2[t] + EPSV);
        sbias[64 + t] = iv; sbias[128 + t] = b2[t] - m2[t] * iv;
    }

    int b0 = blockIdx.x * 4;

    // prologue: y1 (480 rows) + W stage 0, one cp.async group
    if (t < 480) {
        int hl = t / 240, rem = t % 240, bb = rem / 60, r = rem % 60;
        const char* src = (const char*)(hl ? g_y1l : g_y1h)
                        + (((size_t)(b0 + bb) * RPOS + r) << 7);
        copy_row8(sbase + (uint32_t)(hl * 30720 + bb * 7680 + r * 128), src, (r & 7) << 4);
    }
    if (t < 128) {
        int hl = t >> 6, o = t & 63;
        const char* ws = (const char*)g_W1p + ((size_t)(hl * KW * CMID + o) << 7);
        copy_row8(sbase + MIDY + (uint32_t)(hl * 8192 + o * 128), ws, 0);
    }
    CP_COMMIT();
    __syncthreads();   // snei visible

    int m0 = (wid & 7) * 32, n0 = (wid >> 3) * 32;
    int lrA = l & 15, lgA = l >> 4;
    int lrB = (l & 7) + ((l >> 4) << 3), lgB = (l >> 3) & 1;

    // per-lane A row precompute (2 m-subtiles)
    int rB13[2]; uint32_t bOff[2];
    {
#pragma unroll
        for (int mt = 0; mt < 2; mt++) {
            int m = m0 + mt * 16 + lrA;
            int bb = (m < 240) ? (m / 60) : 0;
            int r  = (m < 240) ? (m - bb * 60) : (m - 240);
            rB13[mt] = r * KW;
            bOff[mt] = (uint32_t)(bb * 7680);
        }
    }

    float acc[2][4][4];
#pragma unroll
    for (int a = 0; a < 2; a++)
#pragma unroll
        for (int b = 0; b < 4; b++)
#pragma unroll
            for (int c = 0; c < 4; c++) acc[a][b][c] = 0.0f;

    for (int s = 0; s < KW; s++) {
        if (s + 1 < KW) {
            if (t < 128) {
                int hl = t >> 6, o = t & 63;
                const char* ws = (const char*)g_W1p
                               + ((size_t)(hl * KW * CMID + (s + 1) * CMID + o) << 7);
                copy_row8(sbase + MIDY + (uint32_t)(((s + 1) & 1)) * MIDW
                          + (uint32_t)(hl * 8192 + o * 128), ws, 0);
            }
            CP_COMMIT();
            CP_WAIT(1);
        } else {
            CP_WAIT(0);
        }
        __syncthreads();

        uint32_t Wb = sbase + MIDY + (uint32_t)(s & 1) * MIDW;
        int j0 = snei[rB13[0] + s], j1 = snei[rB13[1] + s];
        uint32_t a0row = bOff[0] + (uint32_t)(j0 << 7);
        uint32_t a1row = bOff[1] + (uint32_t)(j1 << 7);
        int k0 = j0 & 7, k1 = j1 & 7;

#pragma unroll
        for (int ks = 0; ks < 4; ks++) {
            uint32_t ah[2][4], al[2][4];
            {
                uint32_t ad0 = sbase + a0row + (uint32_t)((((ks << 1) + lgA) ^ k0) << 4);
                LDMX4(ah[0][0], ah[0][1], ah[0][2], ah[0][3], ad0);
                LDMX4(al[0][0], al[0][1], al[0][2], al[0][3], ad0 + 30720u);
                uint32_t ad1 = sbase + a1row + (uint32_t)((((ks << 1) + lgA) ^ k1) << 4);
                LDMX4(ah[1][0], ah[1][1], ah[1][2], ah[1][3], ad1);
                LDMX4(al[1][0], al[1][1], al[1][2], al[1][3], ad1 + 30720u);
            }
#pragma unroll
            for (int q = 0; q < 2; q++) {
                uint32_t bh[4], bl[4];
                int row = n0 + q * 16 + lrB;
                uint32_t bd = Wb + (uint32_t)(row << 7)
                            + (uint32_t)((((ks << 1) + lgB) ^ (row & 7)) << 4);
                LDMX4(bh[0], bh[1], bh[2], bh[3], bd);
                LDMX4(bl[0], bl[1], bl[2], bl[3], bd + 8192u);
#pragma unroll
                for (int mt = 0; mt < 2; mt++)
#pragma unroll
                    for (int hf = 0; hf < 2; hf++) {
                        float* d = acc[mt][q * 2 + hf];
                        mma16816(d, ah[mt], &bh[hf * 2]);
                        mma16816(d, ah[mt], &bl[hf * 2]);
                        mma16816(d, al[mt], &bh[hf * 2]);
                    }
            }
        }
        __syncthreads();
    }

    // epilogue: bn2+relu, split, store y2
#pragma unroll
    for (int mt = 0; mt < 2; mt++)
#pragma unroll
        for (int nt = 0; nt < 4; nt++) {
            float* d = acc[mt][nt];
            int o = n0 + nt * 8 + ((l & 3) << 1);
            float cv0 = sbias[o],       cv1 = sbias[o + 1];
            float i0  = sbias[64 + o],  i1  = sbias[65 + o];
            float a0  = sbias[128 + o], a1  = sbias[129 + o];
#pragma unroll
            for (int h = 0; h < 2; h++) {
                int m = m0 + mt * 16 + (l >> 2) + h * 8;
                if (m < 240) {
                    int bb = m / 60; int r = m - bb * 60;
                    float y0 = fmaxf(fmaf(d[h * 2]     + cv0, i0, a0), 0.0f);
                    float y1 = fmaxf(fmaf(d[h * 2 + 1] + cv1, i1, a1), 0.0f);
                    uint32_t hh, ll; split2(y0, y1, hh, ll);
                    size_t off = (((size_t)(b0 + bb) * RPOS + r) << 5) + (o >> 1);
                    ((uint32_t*)g_y2h)[off] = hh;
                    ((uint32_t*)g_y2l)[off] = ll;
                }
            }
        }
}

// ---------------------------------------------------------------------------
// conv_out: CTA = 4 batches (M=256), N=128, 26 k-stages (y2/W2 then y3/W3).
// 256 threads, 8 warps (4m x 2n), warp tile 64x64 (acc 128 regs).
// y2 AND y3 resident in smem (loaded once); W double-buffered.
// smem: Y2 61440 | Y3 61440 | W 2x32768 | nei 3120 | bias 512
// ---------------------------------------------------------------------------
#define OUTY   61440u
#define OUTW   32768u
#define OUTWO  (2u * OUTY)
#define OUTNEI (OUTWO + 2u * OUTW)
#define OUTBIAS (OUTNEI + 3136u)

__global__ __launch_bounds__(256, 1)
void conv_out_kernel(const int* __restrict__ nei, const float* __restrict__ c2,
                     const float* __restrict__ c3, float* __restrict__ out)
{
    extern __shared__ __align__(1024) char smb[];
    uint32_t sbase = smem_u32(smb);

    int t = threadIdx.x, wid = t >> 5, l = t & 31;
    int*   snei  = (int*)(smb + OUTNEI);
    float* sbias = (float*)(smb + OUTBIAS);

    for (int i = t; i < RPOS * KW; i += 256) snei[i] = nei[i];
    if (t < 128) sbias[t] = c2[t] + c3[t];

    int b0 = blockIdx.x * 4;

    // prologue: y2 + y3 (960 rows) + W stage 0
    for (int i = t; i < 960; i += 256) {
        int ten = i / 480, rem = i % 480;
        int hl = rem / 240, rem2 = rem % 240, bb = rem2 / 60, r = rem2 % 60;
        const __nv_bfloat16* srcs[4] = {g_y2h, g_y2l, g_y3h, g_y3l};
        const char* src = (const char*)srcs[ten * 2 + hl]
                        + (((size_t)(b0 + bb) * RPOS + r) << 7);
        copy_row8(sbase + (uint32_t)(ten * OUTY + hl * 30720 + bb * 7680 + r * 128),
                  src, (r & 7) << 4);
    }
    {
        int hl = t >> 7, o = t & 127;
        const char* ws = (const char*)g_W2p + ((size_t)(hl * KW * COUT + o) << 7);
        copy_row8(sbase + OUTWO + (uint32_t)(hl * 16384 + o * 128), ws, 0);
    }
    CP_COMMIT();
    __syncthreads();   // snei visible

    int m0 = (wid & 3) * 64, n0 = (wid >> 2) * 64;
    int lrA = l & 15, lgA = l >> 4;
    int lrB = (l & 7) + ((l >> 4) << 3), lgB = (l >> 3) & 1;

    int rB13[4]; uint32_t bOff[4];
#pragma unroll
    for (int mt = 0; mt < 4; mt++) {
        int m = m0 + mt * 16 + lrA;
        int bb = (m < 240) ? (m / 60) : 0;
        int r  = (m < 240) ? (m - bb * 60) : (m - 240);
        rB13[mt] = r * KW;
        bOff[mt] = (uint32_t)(bb * 7680);
    }

    float acc[4][8][4];
#pragma unroll
    for (int a = 0; a < 4; a++)
#pragma unroll
        for (int b = 0; b < 8; b++)
#pragma unroll
            for (int c = 0; c < 4; c++) acc[a][b][c] = 0.0f;

    const int S = 2 * KW;
    for (int s = 0; s < S; s++) {
        if (s + 1 < S) {
            int sn = s + 1;
            int ph = sn >= KW, k = sn - (ph ? KW : 0);
            int hl = t >> 7, o = t & 127;
            const char* ws = (const char*)(ph ? g_W3p : g_W2p)
                           + ((size_t)(hl * KW * COUT + k * COUT + o) << 7);
            copy_row8(sbase + OUTWO + (uint32_t)(sn & 1) * OUTW
                      + (uint32_t)(hl * 16384 + o * 128), ws, 0);
            CP_COMMIT();
            CP_WAIT(1);
        } else {
            CP_WAIT(0);
        }
        __syncthreads();

        int ph = (s >= KW), k = s - (ph ? KW : 0);
        uint32_t Yb = sbase + (uint32_t)(ph ? OUTY : 0u);
        uint32_t Wb = sbase + OUTWO + (uint32_t)(s & 1) * OUTW;

        uint32_t arow[4]; int akey[4];
#pragma unroll
        for (int mt = 0; mt < 4; mt++) {
            int j = snei[rB13[mt] + k];
            arow[mt] = Yb + bOff[mt] + (uint32_t)(j << 7);
            akey[mt] = j & 7;
        }

#pragma unroll
        for (int ks = 0; ks < 4; ks++) {
            uint32_t ah[4][4], al[4][4];
#pragma unroll
            for (int mt = 0; mt < 4; mt++) {
                uint32_t ad = arow[mt] + (uint32_t)((((ks << 1) + lgA) ^ akey[mt]) << 4);
                LDMX4(ah[mt][0], ah[mt][1], ah[mt][2], ah[mt][3], ad);
                LDMX4(al[mt][0], al[mt][1], al[mt][2], al[mt][3], ad + 30720u);
            }
#pragma unroll
            for (int q = 0; q < 4; q++) {
                uint32_t bh[4], bl[4];
                int row = n0 + q * 16 + lrB;
                uint32_t bd = Wb + (uint32_t)(row << 7)
                            + (uint32_t)((((ks << 1) + lgB) ^ (row & 7)) << 4);
                LDMX4(bh[0], bh[1], bh[2], bh[3], bd);
                LDMX4(bl[0], bl[1], bl[2], bl[3], bd + 16384u);
#pragma unroll
                for (int mt = 0; mt < 4; mt++)
#pragma unroll
                    for (int hf = 0; hf < 2; hf++) {
                        float* d = acc[mt][q * 2 + hf];
                        mma16816(d, ah[mt], &bh[hf * 2]);
                        mma16816(d, ah[mt], &bl[hf * 2]);
                        mma16816(d, al[mt], &bh[hf * 2]);
                    }
            }
        }
        __syncthreads();
    }

    // epilogue: +bias, direct global stores (out [b][o][r])
#pragma unroll
    for (int mt = 0; mt < 4; mt++)
#pragma unroll
        for (int nc = 0; nc < 8; nc++) {
            float* d = acc[mt][nc];
            int o = n0 + nc * 8 + ((l & 3) << 1);
            float bv0 = sbias[o], bv1 = sbias[o + 1];
#pragma unroll
            for (int h = 0; h < 2; h++) {
                int m = m0 + mt * 16 + (l >> 2) + h * 8;
                if (m < 240) {
                    int bb = m / 60; int r = m - bb * 60;
                    float* dp = out + ((size_t)(b0 + bb) * COUT + o) * RPOS + r;
                    dp[0]    = d[h * 2]     + bv0;
                    dp[RPOS] = d[h * 2 + 1] + bv1;
                }
            }
        }
}

// ---------------------------------------------------------------------------
extern "C" void kernel_launch(void* const* d_in, const int* in_sizes, int n_in,
                              void* d_out, int out_size)
{
    const float* x   = (const float*)d_in[0];
    const int*   nei = (const int*)d_in[1];
    const float* g1 = (const float*)d_in[2];
    const float* b1 = (const float*)d_in[3];
    const float* m1 = (const float*)d_in[4];
    const float* v1 = (const float*)d_in[5];
    const float* W1 = (const float*)d_in[6];
    const float* c1 = (const float*)d_in[7];
    const float* g2 = (const float*)d_in[8];
    const float* b2 = (const float*)d_in[9];
    const float* m2 = (const float*)d_in[10];
    const float* v2 = (const float*)d_in[11];
    const float* W2 = (const float*)d_in[12];
    const float* c2 = (const float*)d_in[13];
    const float* g3 = (const float*)d_in[14];
    const float* b3 = (const float*)d_in[15];
    const float* m3 = (const float*)d_in[16];
    const float* v3 = (const float*)d_in[17];
    const float* W3 = (const float*)d_in[18];
    const float* c3 = (const float*)d_in[19];
    float* out = (float*)d_out;

    const int smem_mid = (int)(MIDBIAS + 768 + 256);      // ~99 KB
    const int smem_out = (int)(OUTBIAS + 512 + 256);      // ~192 KB
    cudaFuncSetAttribute(conv_mid_kernel, cudaFuncAttributeMaxDynamicSharedMemorySize, smem_mid);
    cudaFuncSetAttribute(conv_out_kernel, cudaFuncAttributeMaxDynamicSharedMemorySize, smem_out);

    prep_kernel<<<BATCH, 256>>>(x, g1, b1, m1, v1, g3, b3, m3, v3);
    packW_kernel<<<(KW * (CMID * CIN + 2 * COUT * CMID) + 255) / 256, 256>>>(W1, W2, W3);
    conv_mid_kernel<<<BATCH / 4, 512, smem_mid>>>(nei, c1, g2, b2, m2, v2);
    conv_out_kernel<<<BATCH / 4, 256, smem_out>>>(nei, c2, c3, out);
}

// round 6
// speedup vs baseline: 1.5536x; 1.0724x over previous
#include <cuda_runtime.h>
#include <cuda_bf16.h>
#include <cstdint>

#define BATCH 2048
#define RPOS  60
#define KW    13
#define CIN   64
#define CMID  64
#define COUT  128
#define EPSV  1e-5f

// ---------------------------------------------------------------------------
// Device scratch: y tensors as bf16 hi/lo, layout [b][r][c] (128B rows)
// ---------------------------------------------------------------------------
__device__ __align__(128) __nv_bfloat16 g_y1h[BATCH * RPOS * CIN];
__device__ __align__(128) __nv_bfloat16 g_y1l[BATCH * RPOS * CIN];
__device__ __align__(128) __nv_bfloat16 g_y2h[BATCH * RPOS * CMID];
__device__ __align__(128) __nv_bfloat16 g_y2l[BATCH * RPOS * CMID];
__device__ __align__(128) __nv_bfloat16 g_y3h[BATCH * RPOS * CIN];
__device__ __align__(128) __nv_bfloat16 g_y3l[BATCH * RPOS * CIN];
// Packed weights: [hl][k][o][c] bf16, XOR-swizzle on 16B granules pre-applied.
__device__ __align__(128) __nv_bfloat16 g_W1p[2 * KW * CMID * CIN];
__device__ __align__(128) __nv_bfloat16 g_W2p[2 * KW * COUT * CMID];
__device__ __align__(128) __nv_bfloat16 g_W3p[2 * KW * COUT * CMID];

// ---------------------------------------------------------------------------
// PTX helpers
// ---------------------------------------------------------------------------
__device__ __forceinline__ uint32_t smem_u32(const void* p) {
    uint32_t a;
    asm("{ .reg .u64 t; cvta.to.shared.u64 t, %1; cvt.u32.u64 %0, t; }" : "=r"(a) : "l"(p));
    return a;
}

#define CP_ASYNC16(dst, src) \
    asm volatile("cp.async.cg.shared.global [%0], [%1], 16;" :: "r"(dst), "l"(src) : "memory")
#define CP_COMMIT()  asm volatile("cp.async.commit_group;" ::: "memory")
#define CP_WAIT(n)   asm volatile("cp.async.wait_group %0;" :: "n"(n) : "memory")

#define LDMX4(r0, r1, r2, r3, addr) \
    asm volatile("ldmatrix.sync.aligned.m8n8.x4.shared.b16 {%0,%1,%2,%3}, [%4];" \
        : "=r"(r0), "=r"(r1), "=r"(r2), "=r"(r3) : "r"(addr))

__device__ __forceinline__ void mma16816(float* d, const uint32_t* a, const uint32_t* b) {
    asm volatile("mma.sync.aligned.m16n8k16.row.col.f32.bf16.bf16.f32 "
        "{%0,%1,%2,%3},{%4,%5,%6,%7},{%8,%9},{%0,%1,%2,%3};"
        : "+f"(d[0]), "+f"(d[1]), "+f"(d[2]), "+f"(d[3])
        : "r"(a[0]), "r"(a[1]), "r"(a[2]), "r"(a[3]), "r"(b[0]), "r"(b[1]));
}

__device__ __forceinline__ void split2(float a, float b, uint32_t& h, uint32_t& l) {
    __nv_bfloat16 ha = __float2bfloat16(a), hb = __float2bfloat16(b);
    __nv_bfloat16 la = __float2bfloat16(a - __bfloat162float(ha));
    __nv_bfloat16 lb = __float2bfloat16(b - __bfloat162float(hb));
    h = (uint32_t)__bfloat16_as_ushort(ha) | ((uint32_t)__bfloat16_as_ushort(hb) << 16);
    l = (uint32_t)__bfloat16_as_ushort(la) | ((uint32_t)__bfloat16_as_ushort(lb) << 16);
}

// copy one 128B row, applying per-row XOR swizzle (key sw = (row&7)<<4)
__device__ __forceinline__ void copy_row8(uint32_t dst, const char* src, int sw) {
#pragma unroll
    for (int g = 0; g < 8; g++) CP_ASYNC16(dst + (uint32_t)((g << 4) ^ sw), src + (g << 4));
}

// ---------------------------------------------------------------------------
// prep
// ---------------------------------------------------------------------------
__global__ void prep_kernel(const float* __restrict__ x,
                            const float* __restrict__ g1, const float* __restrict__ b1,
                            const float* __restrict__ m1, const float* __restrict__ v1,
                            const float* __restrict__ g3, const float* __restrict__ b3,
                            const float* __restrict__ m3, const float* __restrict__ v3)
{
    __shared__ float xs[64 * 61];
    __shared__ float s1a[64], s1b[64], s3a[64], s3b[64];
    int b = blockIdx.x, t = threadIdx.x;

    if (t < 64) {
        float i1 = g1[t] * rsqrtf(v1[t] + EPSV);
        s1a[t] = i1; s1b[t] = b1[t] - m1[t] * i1;
        float i3 = g3[t] * rsqrtf(v3[t] + EPSV);
        s3a[t] = i3; s3b[t] = b3[t] - m3[t] * i3;
    }
    const float* xb = x + (size_t)b * (CIN * RPOS);
    for (int i = t; i < CIN * RPOS; i += 256)
        xs[(i / RPOS) * 61 + (i % RPOS)] = xb[i];
    __syncthreads();

    uint32_t* y1h = (uint32_t*)g_y1h + (size_t)b * (RPOS * 32);
    uint32_t* y1l = (uint32_t*)g_y1l + (size_t)b * (RPOS * 32);
    uint32_t* y3h = (uint32_t*)g_y3h + (size_t)b * (RPOS * 32);
    uint32_t* y3l = (uint32_t*)g_y3l + (size_t)b * (RPOS * 32);
    for (int i = t; i < RPOS * 32; i += 256) {
        int j = i >> 5, c = (i & 31) * 2;
        float xa = xs[c * 61 + j], xc = xs[(c + 1) * 61 + j];
        float a1 = fmaxf(fmaf(xa, s1a[c], s1b[c]), 0.0f);
        float b1v = fmaxf(fmaf(xc, s1a[c + 1], s1b[c + 1]), 0.0f);
        float a3 = fmaxf(fmaf(xa, s3a[c], s3b[c]), 0.0f);
        float b3v = fmaxf(fmaf(xc, s3a[c + 1], s3b[c + 1]), 0.0f);
        uint32_t h, l;
        split2(a1, b1v, h, l); y1h[i] = h; y1l[i] = l;
        split2(a3, b3v, h, l); y3h[i] = h; y3l[i] = l;
    }
}

// ---------------------------------------------------------------------------
// packW
// ---------------------------------------------------------------------------
__global__ void packW_kernel(const float* __restrict__ W1, const float* __restrict__ W2,
                             const float* __restrict__ W3)
{
    int idx = blockIdx.x * 256 + threadIdx.x;
    const int n1 = KW * CMID * CIN, n2 = KW * COUT * CMID;
    const float* W; __nv_bfloat16* dst; int O, nloc;
    if (idx < n1)             { W = W1; dst = g_W1p; O = CMID; nloc = idx;           }
    else if (idx < n1 + n2)   { W = W2; dst = g_W2p; O = COUT; nloc = idx - n1;      }
    else if (idx < n1 + 2*n2) { W = W3; dst = g_W3p; O = COUT; nloc = idx - n1 - n2; }
    else return;
    int k = nloc / (O * 64), rem = nloc % (O * 64);
    int o = rem / 64, c = rem % 64;
    float v = W[o * (64 * KW) + c * KW + k];
    __nv_bfloat16 h = __float2bfloat16(v);
    __nv_bfloat16 l = __float2bfloat16(v - __bfloat162float(h));
    int sw = ((c >> 3) ^ (o & 7)) * 8 + (c & 7);
    int n = KW * O * 64;
    dst[(size_t)(k * O + o) * 64 + sw] = h;
    dst[(size_t)n + (size_t)(k * O + o) * 64 + sw] = l;
}

// ---------------------------------------------------------------------------
// conv_mid: CTA = 4 batches (M=256, 240 real), N=64. 512 threads, 16 warps
// (8m x 2n), warp tile 32x32. y1 resident in smem; gather via ldmatrix addr.
// ---------------------------------------------------------------------------
#define MIDY  61440u
#define MIDW  16384u
#define MIDNEI (MIDY + 2u * MIDW)
#define MIDBIAS (MIDNEI + 3136u)

__global__ __launch_bounds__(512)
void conv_mid_kernel(const int* __restrict__ nei, const float* __restrict__ c1,
                     const float* __restrict__ g2, const float* __restrict__ b2,
                     const float* __restrict__ m2, const float* __restrict__ v2)
{
    extern __shared__ __align__(1024) char smb[];
    uint32_t sbase = smem_u32(smb);

    int t = threadIdx.x, wid = t >> 5, l = t & 31;
    int*   snei  = (int*)(smb + MIDNEI);
    float* sbias = (float*)(smb + MIDBIAS);

    for (int i = t; i < RPOS * KW; i += 512) snei[i] = nei[i];
    if (t < 64) {
        sbias[t] = c1[t];
        float iv = g2[t] * rsqrtf(v2[t] + EPSV);
        sbias[64 + t] = iv; sbias[128 + t] = b2[t] - m2[t] * iv;
    }

    int b0 = blockIdx.x * 4;

    if (t < 480) {
        int hl = t / 240, rem = t % 240, bb = rem / 60, r = rem % 60;
        const char* src = (const char*)(hl ? g_y1l : g_y1h)
                        + (((size_t)(b0 + bb) * RPOS + r) << 7);
        copy_row8(sbase + (uint32_t)(hl * 30720 + bb * 7680 + r * 128), src, (r & 7) << 4);
    }
    if (t < 128) {
        int hl = t >> 6, o = t & 63;
        const char* ws = (const char*)g_W1p + ((size_t)(hl * KW * CMID + o) << 7);
        copy_row8(sbase + MIDY + (uint32_t)(hl * 8192 + o * 128), ws, 0);
    }
    CP_COMMIT();
    __syncthreads();

    int m0 = (wid & 7) * 32, n0 = (wid >> 3) * 32;
    int lrA = l & 15, lgA = l >> 4;
    int lrB = (l & 7) + ((l >> 4) << 3), lgB = (l >> 3) & 1;

    int rB13[2]; uint32_t bOff[2];
#pragma unroll
    for (int mt = 0; mt < 2; mt++) {
        int m = m0 + mt * 16 + lrA;
        int bb = (m < 240) ? (m / 60) : 0;
        int r  = (m < 240) ? (m - bb * 60) : (m - 240);
        rB13[mt] = r * KW;
        bOff[mt] = (uint32_t)(bb * 7680);
    }

    float acc[2][4][4];
#pragma unroll
    for (int a = 0; a < 2; a++)
#pragma unroll
        for (int b = 0; b < 4; b++)
#pragma unroll
            for (int c = 0; c < 4; c++) acc[a][b][c] = 0.0f;

    for (int s = 0; s < KW; s++) {
        if (s + 1 < KW) {
            if (t < 128) {
                int hl = t >> 6, o = t & 63;
                const char* ws = (const char*)g_W1p
                               + ((size_t)(hl * KW * CMID + (s + 1) * CMID + o) << 7);
                copy_row8(sbase + MIDY + (uint32_t)(((s + 1) & 1)) * MIDW
                          + (uint32_t)(hl * 8192 + o * 128), ws, 0);
            }
            CP_COMMIT();
            CP_WAIT(1);
        } else {
            CP_WAIT(0);
        }
        __syncthreads();

        uint32_t Wb = sbase + MIDY + (uint32_t)(s & 1) * MIDW;
        int j0 = snei[rB13[0] + s], j1 = snei[rB13[1] + s];
        uint32_t a0row = bOff[0] + (uint32_t)(j0 << 7);
        uint32_t a1row = bOff[1] + (uint32_t)(j1 << 7);
        int k0 = j0 & 7, k1 = j1 & 7;

#pragma unroll
        for (int ks = 0; ks < 4; ks++) {
            uint32_t ah[2][4], al[2][4];
            {
                uint32_t ad0 = sbase + a0row + (uint32_t)((((ks << 1) + lgA) ^ k0) << 4);
                LDMX4(ah[0][0], ah[0][1], ah[0][2], ah[0][3], ad0);
                LDMX4(al[0][0], al[0][1], al[0][2], al[0][3], ad0 + 30720u);
                uint32_t ad1 = sbase + a1row + (uint32_t)((((ks << 1) + lgA) ^ k1) << 4);
                LDMX4(ah[1][0], ah[1][1], ah[1][2], ah[1][3], ad1);
                LDMX4(al[1][0], al[1][1], al[1][2], al[1][3], ad1 + 30720u);
            }
#pragma unroll
            for (int q = 0; q < 2; q++) {
                uint32_t bh[4], bl[4];
                int row = n0 + q * 16 + lrB;
                uint32_t bd = Wb + (uint32_t)(row << 7)
                            + (uint32_t)((((ks << 1) + lgB) ^ (row & 7)) << 4);
                LDMX4(bh[0], bh[1], bh[2], bh[3], bd);
                LDMX4(bl[0], bl[1], bl[2], bl[3], bd + 8192u);
#pragma unroll
                for (int mt = 0; mt < 2; mt++)
#pragma unroll
                    for (int hf = 0; hf < 2; hf++) {
                        float* d = acc[mt][q * 2 + hf];
                        mma16816(d, ah[mt], &bh[hf * 2]);
                        mma16816(d, ah[mt], &bl[hf * 2]);
                        mma16816(d, al[mt], &bh[hf * 2]);
                    }
            }
        }
        __syncthreads();
    }

#pragma unroll
    for (int mt = 0; mt < 2; mt++)
#pragma unroll
        for (int nt = 0; nt < 4; nt++) {
            float* d = acc[mt][nt];
            int o = n0 + nt * 8 + ((l & 3) << 1);
            float cv0 = sbias[o],       cv1 = sbias[o + 1];
            float i0  = sbias[64 + o],  i1  = sbias[65 + o];
            float a0  = sbias[128 + o], a1  = sbias[129 + o];
#pragma unroll
            for (int h = 0; h < 2; h++) {
                int m = m0 + mt * 16 + (l >> 2) + h * 8;
                if (m < 240) {
                    int bb = m / 60; int r = m - bb * 60;
                    float y0 = fmaxf(fmaf(d[h * 2]     + cv0, i0, a0), 0.0f);
                    float y1 = fmaxf(fmaf(d[h * 2 + 1] + cv1, i1, a1), 0.0f);
                    uint32_t hh, ll; split2(y0, y1, hh, ll);
                    size_t off = (((size_t)(b0 + bb) * RPOS + r) << 5) + (o >> 1);
                    ((uint32_t*)g_y2h)[off] = hh;
                    ((uint32_t*)g_y2l)[off] = ll;
                }
            }
        }
}

// ---------------------------------------------------------------------------
// conv_out: CTA = 4 batches (M=256), N=128, 26 k-stages.
// 512 threads, 16 warps (8m x 2n), warp tile 32x64 -> acc 64 regs, no spills.
// y2 AND y3 resident; W double-buffered.
// ---------------------------------------------------------------------------
#define OUTY   61440u
#define OUTW   32768u
#define OUTWO  (2u * OUTY)
#define OUTNEI (OUTWO + 2u * OUTW)
#define OUTBIAS (OUTNEI + 3136u)

__global__ __launch_bounds__(512)
void conv_out_kernel(const int* __restrict__ nei, const float* __restrict__ c2,
                     const float* __restrict__ c3, float* __restrict__ out)
{
    extern __shared__ __align__(1024) char smb[];
    uint32_t sbase = smem_u32(smb);

    int t = threadIdx.x, wid = t >> 5, l = t & 31;
    int*   snei  = (int*)(smb + OUTNEI);
    float* sbias = (float*)(smb + OUTBIAS);

    for (int i = t; i < RPOS * KW; i += 512) snei[i] = nei[i];
    if (t < 128) sbias[t] = c2[t] + c3[t];

    int b0 = blockIdx.x * 4;

    // prologue: y2 + y3 (960 rows) + W stage 0
    for (int i = t; i < 960; i += 512) {
        int ten = i / 480, rem = i % 480;
        int hl = rem / 240, rem2 = rem % 240, bb = rem2 / 60, r = rem2 % 60;
        const __nv_bfloat16* srcs[4] = {g_y2h, g_y2l, g_y3h, g_y3l};
        const char* src = (const char*)srcs[ten * 2 + hl]
                        + (((size_t)(b0 + bb) * RPOS + r) << 7);
        copy_row8(sbase + (uint32_t)(ten * OUTY + hl * 30720 + bb * 7680 + r * 128),
                  src, (r & 7) << 4);
    }
    {   // W: 256 rows over 512 threads -> half-row each
        int row = t >> 1, half = t & 1;
        int hl = row >> 7, o = row & 127;
        const char* ws = (const char*)g_W2p + ((size_t)(hl * KW * COUT + o) << 7) + half * 64;
        uint32_t dst = sbase + OUTWO + (uint32_t)(hl * 16384 + o * 128) + (uint32_t)(half * 64);
#pragma unroll
        for (int g = 0; g < 4; g++) CP_ASYNC16(dst + (g << 4), ws + (g << 4));
    }
    CP_COMMIT();
    __syncthreads();

    int m0 = (wid & 7) * 32, n0 = (wid >> 3) * 64;
    int lrA = l & 15, lgA = l >> 4;
    int lrB = (l & 7) + ((l >> 4) << 3), lgB = (l >> 3) & 1;

    int rB13[2]; uint32_t bOff[2];
#pragma unroll
    for (int mt = 0; mt < 2; mt++) {
        int m = m0 + mt * 16 + lrA;
        int bb = (m < 240) ? (m / 60) : 0;
        int r  = (m < 240) ? (m - bb * 60) : (m - 240);
        rB13[mt] = r * KW;
        bOff[mt] = (uint32_t)(bb * 7680);
    }

    float acc[2][8][4];
#pragma unroll
    for (int a = 0; a < 2; a++)
#pragma unroll
        for (int b = 0; b < 8; b++)
#pragma unroll
            for (int c = 0; c < 4; c++) acc[a][b][c] = 0.0f;

    const int S = 2 * KW;
    for (int s = 0; s < S; s++) {
        if (s + 1 < S) {
            int sn = s + 1;
            int ph = sn >= KW, k = sn - (ph ? KW : 0);
            int row = t >> 1, half = t & 1;
            int hl = row >> 7, o = row & 127;
            const char* ws = (const char*)(ph ? g_W3p : g_W2p)
                           + ((size_t)(hl * KW * COUT + k * COUT + o) << 7) + half * 64;
            uint32_t dst = sbase + OUTWO + (uint32_t)(sn & 1) * OUTW
                         + (uint32_t)(hl * 16384 + o * 128) + (uint32_t)(half * 64);
#pragma unroll
            for (int g = 0; g < 4; g++) CP_ASYNC16(dst + (g << 4), ws + (g << 4));
            CP_COMMIT();
            CP_WAIT(1);
        } else {
            CP_WAIT(0);
        }
        __syncthreads();

        int ph = (s >= KW), k = s - (ph ? KW : 0);
        uint32_t Yb = sbase + (uint32_t)(ph ? OUTY : 0u);
        uint32_t Wb = sbase + OUTWO + (uint32_t)(s & 1) * OUTW;

        uint32_t arow[2]; int akey[2];
#pragma unroll
        for (int mt = 0; mt < 2; mt++) {
            int j = snei[rB13[mt] + k];
            arow[mt] = Yb + bOff[mt] + (uint32_t)(j << 7);
            akey[mt] = j & 7;
        }

#pragma unroll
        for (int ks = 0; ks < 4; ks++) {
            uint32_t ah[2][4], al[2][4];
#pragma unroll
            for (int mt = 0; mt < 2; mt++) {
                uint32_t ad = arow[mt] + (uint32_t)((((ks << 1) + lgA) ^ akey[mt]) << 4);
                LDMX4(ah[mt][0], ah[mt][1], ah[mt][2], ah[mt][3], ad);
                LDMX4(al[mt][0], al[mt][1], al[mt][2], al[mt][3], ad + 30720u);
            }
#pragma unroll
            for (int q = 0; q < 4; q++) {
                uint32_t bh[4], bl[4];
                int row = n0 + q * 16 + lrB;
                uint32_t bd = Wb + (uint32_t)(row << 7)
                            + (uint32_t)((((ks << 1) + lgB) ^ (row & 7)) << 4);
                LDMX4(bh[0], bh[1], bh[2], bh[3], bd);
                LDMX4(bl[0], bl[1], bl[2], bl[3], bd + 16384u);
#pragma unroll
                for (int mt = 0; mt < 2; mt++)
#pragma unroll
                    for (int hf = 0; hf < 2; hf++) {
                        float* d = acc[mt][q * 2 + hf];
                        mma16816(d, ah[mt], &bh[hf * 2]);
                        mma16816(d, ah[mt], &bl[hf * 2]);
                        mma16816(d, al[mt], &bh[hf * 2]);
                    }
            }
        }
        __syncthreads();
    }

    // epilogue: +bias, direct global stores (out [b][o][r])
#pragma unroll
    for (int mt = 0; mt < 2; mt++)
#pragma unroll
        for (int nc = 0; nc < 8; nc++) {
            float* d = acc[mt][nc];
            int o = n0 + nc * 8 + ((l & 3) << 1);
            float bv0 = sbias[o], bv1 = sbias[o + 1];
#pragma unroll
            for (int h = 0; h < 2; h++) {
                int m = m0 + mt * 16 + (l >> 2) + h * 8;
                if (m < 240) {
                    int bb = m / 60; int r = m - bb * 60;
                    float* dp = out + ((size_t)(b0 + bb) * COUT + o) * RPOS + r;
                    dp[0]    = d[h * 2]     + bv0;
                    dp[RPOS] = d[h * 2 + 1] + bv1;
                }
            }
        }
}

// ---------------------------------------------------------------------------
extern "C" void kernel_launch(void* const* d_in, const int* in_sizes, int n_in,
                              void* d_out, int out_size)
{
    const float* x   = (const float*)d_in[0];
    const int*   nei = (const int*)d_in[1];
    const float* g1 = (const float*)d_in[2];
    const float* b1 = (const float*)d_in[3];
    const float* m1 = (const float*)d_in[4];
    const float* v1 = (const float*)d_in[5];
    const float* W1 = (const float*)d_in[6];
    const float* c1 = (const float*)d_in[7];
    const float* g2 = (const float*)d_in[8];
    const float* b2 = (const float*)d_in[9];
    const float* m2 = (const float*)d_in[10];
    const float* v2 = (const float*)d_in[11];
    const float* W2 = (const float*)d_in[12];
    const float* c2 = (const float*)d_in[13];
    const float* g3 = (const float*)d_in[14];
    const float* b3 = (const float*)d_in[15];
    const float* m3 = (const float*)d_in[16];
    const float* v3 = (const float*)d_in[17];
    const float* W3 = (const float*)d_in[18];
    const float* c3 = (const float*)d_in[19];
    float* out = (float*)d_out;

    const int smem_mid = (int)(MIDBIAS + 768 + 256);      // ~99 KB
    const int smem_out = (int)(OUTBIAS + 512 + 256);      // ~192 KB
    cudaFuncSetAttribute(conv_mid_kernel, cudaFuncAttributeMaxDynamicSharedMemorySize, smem_mid);
    cudaFuncSetAttribute(conv_out_kernel, cudaFuncAttributeMaxDynamicSharedMemorySize, smem_out);

    prep_kernel<<<BATCH, 256>>>(x, g1, b1, m1, v1, g3, b3, m3, v3);
    packW_kernel<<<(KW * (CMID * CIN + 2 * COUT * CMID) + 255) / 256, 256>>>(W1, W2, W3);
    conv_mid_kernel<<<BATCH / 4, 512, smem_mid>>>(nei, c1, g2, b2, m2, v2);
    conv_out_kernel<<<BATCH / 4, 512, smem_out>>>(nei, c2, c3, out);
}

// round 7
// speedup vs baseline: 1.6195x; 1.0424x over previous
#include <cuda_runtime.h>
#include <cuda_bf16.h>
#include <cstdint>

#define BATCH 2048
#define RPOS  60
#define KW    13
#define CIN   64
#define CMID  64
#define COUT  128
#define EPSV  1e-5f

// ---------------------------------------------------------------------------
// Device scratch: y tensors as bf16 hi/lo, layout [b][r][c] (128B rows)
// ---------------------------------------------------------------------------
__device__ __align__(128) __nv_bfloat16 g_y1h[BATCH * RPOS * CIN];
__device__ __align__(128) __nv_bfloat16 g_y1l[BATCH * RPOS * CIN];
__device__ __align__(128) __nv_bfloat16 g_y2h[BATCH * RPOS * CMID];
__device__ __align__(128) __nv_bfloat16 g_y2l[BATCH * RPOS * CMID];
__device__ __align__(128) __nv_bfloat16 g_y3h[BATCH * RPOS * CIN];
__device__ __align__(128) __nv_bfloat16 g_y3l[BATCH * RPOS * CIN];
// Packed weights: [hl][k][o][c] bf16, XOR-swizzle on 16B granules pre-applied.
__device__ __align__(128) __nv_bfloat16 g_W1p[2 * KW * CMID * CIN];
__device__ __align__(128) __nv_bfloat16 g_W2p[2 * KW * COUT * CMID];
__device__ __align__(128) __nv_bfloat16 g_W3p[2 * KW * COUT * CMID];

// ---------------------------------------------------------------------------
// PTX helpers
// ---------------------------------------------------------------------------
__device__ __forceinline__ uint32_t smem_u32(const void* p) {
    uint32_t a;
    asm("{ .reg .u64 t; cvta.to.shared.u64 t, %1; cvt.u32.u64 %0, t; }" : "=r"(a) : "l"(p));
    return a;
}

#define CP_ASYNC16(dst, src) \
    asm volatile("cp.async.cg.shared.global [%0], [%1], 16;" :: "r"(dst), "l"(src) : "memory")
#define CP_COMMIT()  asm volatile("cp.async.commit_group;" ::: "memory")
#define CP_WAIT(n)   asm volatile("cp.async.wait_group %0;" :: "n"(n) : "memory")

#define LDMX4(r0, r1, r2, r3, addr) \
    asm volatile("ldmatrix.sync.aligned.m8n8.x4.shared.b16 {%0,%1,%2,%3}, [%4];" \
        : "=r"(r0), "=r"(r1), "=r"(r2), "=r"(r3) : "r"(addr))

__device__ __forceinline__ void mma16816(float* d, const uint32_t* a, const uint32_t* b) {
    asm volatile("mma.sync.aligned.m16n8k16.row.col.f32.bf16.bf16.f32 "
        "{%0,%1,%2,%3},{%4,%5,%6,%7},{%8,%9},{%0,%1,%2,%3};"
        : "+f"(d[0]), "+f"(d[1]), "+f"(d[2]), "+f"(d[3])
        : "r"(a[0]), "r"(a[1]), "r"(a[2]), "r"(a[3]), "r"(b[0]), "r"(b[1]));
}

__device__ __forceinline__ void split2(float a, float b, uint32_t& h, uint32_t& l) {
    __nv_bfloat16 ha = __float2bfloat16(a), hb = __float2bfloat16(b);
    __nv_bfloat16 la = __float2bfloat16(a - __bfloat162float(ha));
    __nv_bfloat16 lb = __float2bfloat16(b - __bfloat162float(hb));
    h = (uint32_t)__bfloat16_as_ushort(ha) | ((uint32_t)__bfloat16_as_ushort(hb) << 16);
    l = (uint32_t)__bfloat16_as_ushort(la) | ((uint32_t)__bfloat16_as_ushort(lb) << 16);
}

// copy one 128B row, applying per-row XOR swizzle (key sw = (row&7)<<4)
__device__ __forceinline__ void copy_row8(uint32_t dst, const char* src, int sw) {
#pragma unroll
    for (int g = 0; g < 8; g++) CP_ASYNC16(dst + (uint32_t)((g << 4) ^ sw), src + (g << 4));
}

// ---------------------------------------------------------------------------
// prep
// ---------------------------------------------------------------------------
__global__ void prep_kernel(const float* __restrict__ x,
                            const float* __restrict__ g1, const float* __restrict__ b1,
                            const float* __restrict__ m1, const float* __restrict__ v1,
                            const float* __restrict__ g3, const float* __restrict__ b3,
                            const float* __restrict__ m3, const float* __restrict__ v3)
{
    __shared__ float xs[64 * 61];
    __shared__ float s1a[64], s1b[64], s3a[64], s3b[64];
    int b = blockIdx.x, t = threadIdx.x;

    if (t < 64) {
        float i1 = g1[t] * rsqrtf(v1[t] + EPSV);
        s1a[t] = i1; s1b[t] = b1[t] - m1[t] * i1;
        float i3 = g3[t] * rsqrtf(v3[t] + EPSV);
        s3a[t] = i3; s3b[t] = b3[t] - m3[t] * i3;
    }
    const float* xb = x + (size_t)b * (CIN * RPOS);
    for (int i = t; i < CIN * RPOS; i += 256)
        xs[(i / RPOS) * 61 + (i % RPOS)] = xb[i];
    __syncthreads();

    uint32_t* y1h = (uint32_t*)g_y1h + (size_t)b * (RPOS * 32);
    uint32_t* y1l = (uint32_t*)g_y1l + (size_t)b * (RPOS * 32);
    uint32_t* y3h = (uint32_t*)g_y3h + (size_t)b * (RPOS * 32);
    uint32_t* y3l = (uint32_t*)g_y3l + (size_t)b * (RPOS * 32);
    for (int i = t; i < RPOS * 32; i += 256) {
        int j = i >> 5, c = (i & 31) * 2;
        float xa = xs[c * 61 + j], xc = xs[(c + 1) * 61 + j];
        float a1 = fmaxf(fmaf(xa, s1a[c], s1b[c]), 0.0f);
        float b1v = fmaxf(fmaf(xc, s1a[c + 1], s1b[c + 1]), 0.0f);
        float a3 = fmaxf(fmaf(xa, s3a[c], s3b[c]), 0.0f);
        float b3v = fmaxf(fmaf(xc, s3a[c + 1], s3b[c + 1]), 0.0f);
        uint32_t h, l;
        split2(a1, b1v, h, l); y1h[i] = h; y1l[i] = l;
        split2(a3, b3v, h, l); y3h[i] = h; y3l[i] = l;
    }
}

// ---------------------------------------------------------------------------
// packW
// ---------------------------------------------------------------------------
__global__ void packW_kernel(const float* __restrict__ W1, const float* __restrict__ W2,
                             const float* __restrict__ W3)
{
    int idx = blockIdx.x * 256 + threadIdx.x;
    const int n1 = KW * CMID * CIN, n2 = KW * COUT * CMID;
    const float* W; __nv_bfloat16* dst; int O, nloc;
    if (idx < n1)             { W = W1; dst = g_W1p; O = CMID; nloc = idx;           }
    else if (idx < n1 + n2)   { W = W2; dst = g_W2p; O = COUT; nloc = idx - n1;      }
    else if (idx < n1 + 2*n2) { W = W3; dst = g_W3p; O = COUT; nloc = idx - n1 - n2; }
    else return;
    int k = nloc / (O * 64), rem = nloc % (O * 64);
    int o = rem / 64, c = rem % 64;
    float v = W[o * (64 * KW) + c * KW + k];
    __nv_bfloat16 h = __float2bfloat16(v);
    __nv_bfloat16 l = __float2bfloat16(v - __bfloat162float(h));
    int sw = ((c >> 3) ^ (o & 7)) * 8 + (c & 7);
    int n = KW * O * 64;
    dst[(size_t)(k * O + o) * 64 + sw] = h;
    dst[(size_t)n + (size_t)(k * O + o) * 64 + sw] = l;
}

// ---------------------------------------------------------------------------
// conv_mid: CTA = 4 batches (M=256, 240 real), N=64. 512 threads, 16 warps
// (8m x 2n), warp tile 32x32. y1 resident; W TRIPLE-buffered, 1 sync/stage.
// ---------------------------------------------------------------------------
#define MIDY  61440u
#define MIDW  16384u
#define MIDNEI (MIDY + 3u * MIDW)
#define MIDBIAS (MIDNEI + 3136u)

__global__ __launch_bounds__(512)
void conv_mid_kernel(const int* __restrict__ nei, const float* __restrict__ c1,
                     const float* __restrict__ g2, const float* __restrict__ b2,
                     const float* __restrict__ m2, const float* __restrict__ v2)
{
    extern __shared__ __align__(1024) char smb[];
    uint32_t sbase = smem_u32(smb);

    int t = threadIdx.x, wid = t >> 5, l = t & 31;
    int*   snei  = (int*)(smb + MIDNEI);
    float* sbias = (float*)(smb + MIDBIAS);

    for (int i = t; i < RPOS * KW; i += 512) snei[i] = nei[i];
    if (t < 64) {
        sbias[t] = c1[t];
        float iv = g2[t] * rsqrtf(v2[t] + EPSV);
        sbias[64 + t] = iv; sbias[128 + t] = b2[t] - m2[t] * iv;
    }

    int b0 = blockIdx.x * 4;

    // W copy role: quarter rows, all 512 threads
    int wrow = t >> 2, wq = t & 3;
    int whl = wrow >> 6, wo = wrow & 63;
    uint32_t wdstoff = (uint32_t)(whl * 8192 + wo * 128 + wq * 32);
    size_t  wsrcoff = ((size_t)(whl * KW * CMID + wo) << 7) + (size_t)(wq * 32);

    // prologue: y1 + W(0) -> group0, W(1) -> group1
    if (t < 480) {
        int hl = t / 240, rem = t % 240, bb = rem / 60, r = rem % 60;
        const char* src = (const char*)(hl ? g_y1l : g_y1h)
                        + (((size_t)(b0 + bb) * RPOS + r) << 7);
        copy_row8(sbase + (uint32_t)(hl * 30720 + bb * 7680 + r * 128), src, (r & 7) << 4);
    }
    {
        const char* ws = (const char*)g_W1p + wsrcoff;   // k=0
        uint32_t dst = sbase + MIDY + wdstoff;
        CP_ASYNC16(dst, ws); CP_ASYNC16(dst + 16, ws + 16);
        CP_COMMIT();
        ws = (const char*)g_W1p + wsrcoff + ((size_t)CMID << 7);  // k=1
        dst = sbase + MIDY + MIDW + wdstoff;
        CP_ASYNC16(dst, ws); CP_ASYNC16(dst + 16, ws + 16);
        CP_COMMIT();
    }

    int m0 = (wid & 7) * 32, n0 = (wid >> 3) * 32;
    int lrA = l & 15, lgA = l >> 4;
    int lrB = (l & 7) + ((l >> 4) << 3), lgB = (l >> 3) & 1;

    int rB13[2]; uint32_t bOff[2];
#pragma unroll
    for (int mt = 0; mt < 2; mt++) {
        int m = m0 + mt * 16 + lrA;
        int bb = (m < 240) ? (m / 60) : 0;
        int r  = (m < 240) ? (m - bb * 60) : (m - 240);
        rB13[mt] = r * KW;
        bOff[mt] = (uint32_t)(bb * 7680);
    }

    float acc[2][4][4];
#pragma unroll
    for (int a = 0; a < 2; a++)
#pragma unroll
        for (int b = 0; b < 4; b++)
#pragma unroll
            for (int c = 0; c < 4; c++) acc[a][b][c] = 0.0f;

    int sc = 0;   // slot of current stage
    for (int s = 0; s < KW; s++) {
        if (s + 2 < KW) { CP_WAIT(1); } else { CP_WAIT(0); }
        __syncthreads();
        if (s + 2 < KW) {
            int slot_n = sc + 2; if (slot_n >= 3) slot_n -= 3;
            const char* ws = (const char*)g_W1p + wsrcoff + ((size_t)((s + 2) * CMID) << 7);
            uint32_t dst = sbase + MIDY + (uint32_t)slot_n * MIDW + wdstoff;
            CP_ASYNC16(dst, ws); CP_ASYNC16(dst + 16, ws + 16);
            CP_COMMIT();
        }

        uint32_t Wb = sbase + MIDY + (uint32_t)sc * MIDW;
        int j0 = snei[rB13[0] + s], j1 = snei[rB13[1] + s];
        uint32_t a0row = bOff[0] + (uint32_t)(j0 << 7);
        uint32_t a1row = bOff[1] + (uint32_t)(j1 << 7);
        int k0 = j0 & 7, k1 = j1 & 7;

#pragma unroll
        for (int ks = 0; ks < 4; ks++) {
            uint32_t ah[2][4], al[2][4];
            {
                uint32_t ad0 = sbase + a0row + (uint32_t)((((ks << 1) + lgA) ^ k0) << 4);
                LDMX4(ah[0][0], ah[0][1], ah[0][2], ah[0][3], ad0);
                LDMX4(al[0][0], al[0][1], al[0][2], al[0][3], ad0 + 30720u);
                uint32_t ad1 = sbase + a1row + (uint32_t)((((ks << 1) + lgA) ^ k1) << 4);
                LDMX4(ah[1][0], ah[1][1], ah[1][2], ah[1][3], ad1);
                LDMX4(al[1][0], al[1][1], al[1][2], al[1][3], ad1 + 30720u);
            }
#pragma unroll
            for (int q = 0; q < 2; q++) {
                uint32_t bh[4], bl[4];
                int row = n0 + q * 16 + lrB;
                uint32_t bd = Wb + (uint32_t)(row << 7)
                            + (uint32_t)((((ks << 1) + lgB) ^ (row & 7)) << 4);
                LDMX4(bh[0], bh[1], bh[2], bh[3], bd);
                LDMX4(bl[0], bl[1], bl[2], bl[3], bd + 8192u);
#pragma unroll
                for (int mt = 0; mt < 2; mt++)
#pragma unroll
                    for (int hf = 0; hf < 2; hf++) {
                        float* d = acc[mt][q * 2 + hf];
                        mma16816(d, ah[mt], &bh[hf * 2]);
                        mma16816(d, ah[mt], &bl[hf * 2]);
                        mma16816(d, al[mt], &bh[hf * 2]);
                    }
            }
        }
        sc = (sc == 2) ? 0 : sc + 1;
    }

#pragma unroll
    for (int mt = 0; mt < 2; mt++)
#pragma unroll
        for (int nt = 0; nt < 4; nt++) {
            float* d = acc[mt][nt];
            int o = n0 + nt * 8 + ((l & 3) << 1);
            float cv0 = sbias[o],       cv1 = sbias[o + 1];
            float i0  = sbias[64 + o],  i1  = sbias[65 + o];
            float a0  = sbias[128 + o], a1  = sbias[129 + o];
#pragma unroll
            for (int h = 0; h < 2; h++) {
                int m = m0 + mt * 16 + (l >> 2) + h * 8;
                if (m < 240) {
                    int bb = m / 60; int r = m - bb * 60;
                    float y0 = fmaxf(fmaf(d[h * 2]     + cv0, i0, a0), 0.0f);
                    float y1 = fmaxf(fmaf(d[h * 2 + 1] + cv1, i1, a1), 0.0f);
                    uint32_t hh, ll; split2(y0, y1, hh, ll);
                    size_t off = (((size_t)(b0 + bb) * RPOS + r) << 5) + (o >> 1);
                    ((uint32_t*)g_y2h)[off] = hh;
                    ((uint32_t*)g_y2l)[off] = ll;
                }
            }
        }
}

// ---------------------------------------------------------------------------
// conv_out: CTA = 4 batches (M=256), N=128, 26 k-stages.
// 512 threads, 16 warps (8m x 2n), warp tile 32x64.
// y2+y3 resident; W TRIPLE-buffered, 1 sync/stage, prefetch distance 2.
// smem: Y 122880 | W 3x32768 | nei 3136 | bias 512  (~225 KB)
// ---------------------------------------------------------------------------
#define OUTY   61440u
#define OUTW   32768u
#define OUTWO  (2u * OUTY)
#define OUTNEI (OUTWO + 3u * OUTW)
#define OUTBIAS (OUTNEI + 3136u)

__global__ __launch_bounds__(512)
void conv_out_kernel(const int* __restrict__ nei, const float* __restrict__ c2,
                     const float* __restrict__ c3, float* __restrict__ out)
{
    extern __shared__ __align__(1024) char smb[];
    uint32_t sbase = smem_u32(smb);

    int t = threadIdx.x, wid = t >> 5, l = t & 31;
    int*   snei  = (int*)(smb + OUTNEI);
    float* sbias = (float*)(smb + OUTBIAS);

    for (int i = t; i < RPOS * KW; i += 512) snei[i] = nei[i];
    if (t < 128) sbias[t] = c2[t] + c3[t];

    int b0 = blockIdx.x * 4;

    // W copy role: half rows, all 512 threads
    int wrow = t >> 1, whalf = t & 1;
    int whl = wrow >> 7, wo = wrow & 127;
    uint32_t wdstoff = (uint32_t)(whl * 16384 + wo * 128 + whalf * 64);
    size_t  wsrcoff = ((size_t)(whl * KW * COUT + wo) << 7) + (size_t)(whalf * 64);

    // prologue: y2 + y3 + W(0) -> group0, W(1) -> group1
    for (int i = t; i < 960; i += 512) {
        int ten = i / 480, rem = i % 480;
        int hl = rem / 240, rem2 = rem % 240, bb = rem2 / 60, r = rem2 % 60;
        const __nv_bfloat16* srcs[4] = {g_y2h, g_y2l, g_y3h, g_y3l};
        const char* src = (const char*)srcs[ten * 2 + hl]
                        + (((size_t)(b0 + bb) * RPOS + r) << 7);
        copy_row8(sbase + (uint32_t)(ten * OUTY + hl * 30720 + bb * 7680 + r * 128),
                  src, (r & 7) << 4);
    }
    {
        const char* ws = (const char*)g_W2p + wsrcoff;   // phase0 k=0
        uint32_t dst = sbase + OUTWO + wdstoff;
#pragma unroll
        for (int g = 0; g < 4; g++) CP_ASYNC16(dst + (g << 4), ws + (g << 4));
        CP_COMMIT();
        ws = (const char*)g_W2p + wsrcoff + ((size_t)COUT << 7);  // k=1
        dst = sbase + OUTWO + OUTW + wdstoff;
#pragma unroll
        for (int g = 0; g < 4; g++) CP_ASYNC16(dst + (g << 4), ws + (g << 4));
        CP_COMMIT();
    }

    int m0 = (wid & 7) * 32, n0 = (wid >> 3) * 64;
    int lrA = l & 15, lgA = l >> 4;
    int lrB = (l & 7) + ((l >> 4) << 3), lgB = (l >> 3) & 1;

    int rB13[2]; uint32_t bOff[2];
#pragma unroll
    for (int mt = 0; mt < 2; mt++) {
        int m = m0 + mt * 16 + lrA;
        int bb = (m < 240) ? (m / 60) : 0;
        int r  = (m < 240) ? (m - bb * 60) : (m - 240);
        rB13[mt] = r * KW;
        bOff[mt] = (uint32_t)(bb * 7680);
    }

    float acc[2][8][4];
#pragma unroll
    for (int a = 0; a < 2; a++)
#pragma unroll
        for (int b = 0; b < 8; b++)
#pragma unroll
            for (int c = 0; c < 4; c++) acc[a][b][c] = 0.0f;

    const int S = 2 * KW;
    int sc = 0;
    for (int s = 0; s < S; s++) {
        if (s + 2 < S) { CP_WAIT(1); } else { CP_WAIT(0); }
        __syncthreads();
        if (s + 2 < S) {
            int sn = s + 2;
            int phn = sn >= KW, kn = sn - (phn ? KW : 0);
            int slot_n = sc + 2; if (slot_n >= 3) slot_n -= 3;
            const char* ws = (const char*)(phn ? g_W3p : g_W2p) + wsrcoff
                           + ((size_t)(kn * COUT) << 7);
            uint32_t dst = sbase + OUTWO + (uint32_t)slot_n * OUTW + wdstoff;
#pragma unroll
            for (int g = 0; g < 4; g++) CP_ASYNC16(dst + (g << 4), ws + (g << 4));
            CP_COMMIT();
        }

        int ph = (s >= KW), k = s - (ph ? KW : 0);
        uint32_t Yb = sbase + (uint32_t)(ph ? OUTY : 0u);
        uint32_t Wb = sbase + OUTWO + (uint32_t)sc * OUTW;

        uint32_t arow[2]; int akey[2];
#pragma unroll
        for (int mt = 0; mt < 2; mt++) {
            int j = snei[rB13[mt] + k];
            arow[mt] = Yb + bOff[mt] + (uint32_t)(j << 7);
            akey[mt] = j & 7;
        }

#pragma unroll
        for (int ks = 0; ks < 4; ks++) {
            uint32_t ah[2][4], al[2][4];
#pragma unroll
            for (int mt = 0; mt < 2; mt++) {
                uint32_t ad = arow[mt] + (uint32_t)((((ks << 1) + lgA) ^ akey[mt]) << 4);
                LDMX4(ah[mt][0], ah[mt][1], ah[mt][2], ah[mt][3], ad);
                LDMX4(al[mt][0], al[mt][1], al[mt][2], al[mt][3], ad + 30720u);
            }
#pragma unroll
            for (int q = 0; q < 4; q++) {
                uint32_t bh[4], bl[4];
                int row = n0 + q * 16 + lrB;
                uint32_t bd = Wb + (uint32_t)(row << 7)
                            + (uint32_t)((((ks << 1) + lgB) ^ (row & 7)) << 4);
                LDMX4(bh[0], bh[1], bh[2], bh[3], bd);
                LDMX4(bl[0], bl[1], bl[2], bl[3], bd + 16384u);
#pragma unroll
                for (int mt = 0; mt < 2; mt++)
#pragma unroll
                    for (int hf = 0; hf < 2; hf++) {
                        float* d = acc[mt][q * 2 + hf];
                        mma16816(d, ah[mt], &bh[hf * 2]);
                        mma16816(d, ah[mt], &bl[hf * 2]);
                        mma16816(d, al[mt], &bh[hf * 2]);
                    }
            }
        }
        sc = (sc == 2) ? 0 : sc + 1;
    }

    // epilogue: +bias, direct global stores (out [b][o][r])
#pragma unroll
    for (int mt = 0; mt < 2; mt++)
#pragma unroll
        for (int nc = 0; nc < 8; nc++) {
            float* d = acc[mt][nc];
            int o = n0 + nc * 8 + ((l & 3) << 1);
            float bv0 = sbias[o], bv1 = sbias[o + 1];
#pragma unroll
            for (int h = 0; h < 2; h++) {
                int m = m0 + mt * 16 + (l >> 2) + h * 8;
                if (m < 240) {
                    int bb = m / 60; int r = m - bb * 60;
                    float* dp = out + ((size_t)(b0 + bb) * COUT + o) * RPOS + r;
                    dp[0]    = d[h * 2]     + bv0;
                    dp[RPOS] = d[h * 2 + 1] + bv1;
                }
            }
        }
}

// ---------------------------------------------------------------------------
extern "C" void kernel_launch(void* const* d_in, const int* in_sizes, int n_in,
                              void* d_out, int out_size)
{
    const float* x   = (const float*)d_in[0];
    const int*   nei = (const int*)d_in[1];
    const float* g1 = (const float*)d_in[2];
    const float* b1 = (const float*)d_in[3];
    const float* m1 = (const float*)d_in[4];
    const float* v1 = (const float*)d_in[5];
    const float* W1 = (const float*)d_in[6];
    const float* c1 = (const float*)d_in[7];
    const float* g2 = (const float*)d_in[8];
    const float* b2 = (const float*)d_in[9];
    const float* m2 = (const float*)d_in[10];
    const float* v2 = (const float*)d_in[11];
    const float* W2 = (const float*)d_in[12];
    const float* c2 = (const float*)d_in[13];
    const float* g3 = (const float*)d_in[14];
    const float* b3 = (const float*)d_in[15];
    const float* m3 = (const float*)d_in[16];
    const float* v3 = (const float*)d_in[17];
    const float* W3 = (const float*)d_in[18];
    const float* c3 = (const float*)d_in[19];
    float* out = (float*)d_out;

    const int smem_mid = (int)(MIDBIAS + 768 + 256);      // ~115 KB
    const int smem_out = (int)(OUTBIAS + 512 + 256);      // ~225 KB
    cudaFuncSetAttribute(conv_mid_kernel, cudaFuncAttributeMaxDynamicSharedMemorySize, smem_mid);
    cudaFuncSetAttribute(conv_out_kernel, cudaFuncAttributeMaxDynamicSharedMemorySize, smem_out);

    prep_kernel<<<BATCH, 256>>>(x, g1, b1, m1, v1, g3, b3, m3, v3);
    packW_kernel<<<(KW * (CMID * CIN + 2 * COUT * CMID) + 255) / 256, 256>>>(W1, W2, W3);
    conv_mid_kernel<<<BATCH / 4, 512, smem_mid>>>(nei, c1, g2, b2, m2, v2);
    conv_out_kernel<<<BATCH / 4, 512, smem_out>>>(nei, c2, c3, out);
}

// round 8
// speedup vs baseline: 2.0424x; 1.2612x over previous
#include <cuda_runtime.h>
#include <cuda_bf16.h>
#include <cuda_fp16.h>
#include <cstdint>

#define BATCH 2048
#define RPOS  60
#define KW    13
#define CIN   64
#define CMID  64
#define COUT  128
#define EPSV  1e-5f

// ---------------------------------------------------------------------------
// Device scratch
// y1: bf16 hi/lo (feeds bf16 3-pass conv_mid). y2,y3: single fp16 (feed
// fp16 2-pass conv_out). Layout [b][r][c], 128B rows.
// ---------------------------------------------------------------------------
__device__ __align__(128) __nv_bfloat16 g_y1h[BATCH * RPOS * CIN];
__device__ __align__(128) __nv_bfloat16 g_y1l[BATCH * RPOS * CIN];
__device__ __align__(128) __half        g_y2f[BATCH * RPOS * CMID];
__device__ __align__(128) __half        g_y3f[BATCH * RPOS * CIN];
// Packed weights: [hl][k][o][c] with 16B-granule XOR swizzle pre-applied.
__device__ __align__(128) __nv_bfloat16 g_W1p[2 * KW * CMID * CIN];   // bf16 h/l
__device__ __align__(128) __half        g_W2p[2 * KW * COUT * CMID];  // fp16 h/l
__device__ __align__(128) __half        g_W3p[2 * KW * COUT * CMID];  // fp16 h/l

// ---------------------------------------------------------------------------
// PTX helpers
// ---------------------------------------------------------------------------
__device__ __forceinline__ uint32_t smem_u32(const void* p) {
    uint32_t a;
    asm("{ .reg .u64 t; cvta.to.shared.u64 t, %1; cvt.u32.u64 %0, t; }" : "=r"(a) : "l"(p));
    return a;
}

#define CP_ASYNC16(dst, src) \
    asm volatile("cp.async.cg.shared.global [%0], [%1], 16;" :: "r"(dst), "l"(src) : "memory")
#define CP_COMMIT()  asm volatile("cp.async.commit_group;" ::: "memory")
#define CP_WAIT(n)   asm volatile("cp.async.wait_group %0;" :: "n"(n) : "memory")

#define LDMX4(r0, r1, r2, r3, addr) \
    asm volatile("ldmatrix.sync.aligned.m8n8.x4.shared.b16 {%0,%1,%2,%3}, [%4];" \
        : "=r"(r0), "=r"(r1), "=r"(r2), "=r"(r3) : "r"(addr))

__device__ __forceinline__ void mma_bf16(float* d, const uint32_t* a, const uint32_t* b) {
    asm volatile("mma.sync.aligned.m16n8k16.row.col.f32.bf16.bf16.f32 "
        "{%0,%1,%2,%3},{%4,%5,%6,%7},{%8,%9},{%0,%1,%2,%3};"
        : "+f"(d[0]), "+f"(d[1]), "+f"(d[2]), "+f"(d[3])
        : "r"(a[0]), "r"(a[1]), "r"(a[2]), "r"(a[3]), "r"(b[0]), "r"(b[1]));
}
__device__ __forceinline__ void mma_f16(float* d, const uint32_t* a, const uint32_t* b) {
    asm volatile("mma.sync.aligned.m16n8k16.row.col.f32.f16.f16.f32 "
        "{%0,%1,%2,%3},{%4,%5,%6,%7},{%8,%9},{%0,%1,%2,%3};"
        : "+f"(d[0]), "+f"(d[1]), "+f"(d[2]), "+f"(d[3])
        : "r"(a[0]), "r"(a[1]), "r"(a[2]), "r"(a[3]), "r"(b[0]), "r"(b[1]));
}

__device__ __forceinline__ void split2(float a, float b, uint32_t& h, uint32_t& l) {
    __nv_bfloat16 ha = __float2bfloat16(a), hb = __float2bfloat16(b);
    __nv_bfloat16 la = __float2bfloat16(a - __bfloat162float(ha));
    __nv_bfloat16 lb = __float2bfloat16(b - __bfloat162float(hb));
    h = (uint32_t)__bfloat16_as_ushort(ha) | ((uint32_t)__bfloat16_as_ushort(hb) << 16);
    l = (uint32_t)__bfloat16_as_ushort(la) | ((uint32_t)__bfloat16_as_ushort(lb) << 16);
}

// copy one 128B row, applying per-row XOR swizzle (key sw = (row&7)<<4)
__device__ __forceinline__ void copy_row8(uint32_t dst, const char* src, int sw) {
#pragma unroll
    for (int g = 0; g < 8; g++) CP_ASYNC16(dst + (uint32_t)((g << 4) ^ sw), src + (g << 4));
}

// ---------------------------------------------------------------------------
// prep: y1 = relu(bn1(x)) -> bf16 h/l ; y3 = relu(bn3(x)) -> fp16
// ---------------------------------------------------------------------------
__global__ void prep_kernel(const float* __restrict__ x,
                            const float* __restrict__ g1, const float* __restrict__ b1,
                            const float* __restrict__ m1, const float* __restrict__ v1,
                            const float* __restrict__ g3, const float* __restrict__ b3,
                            const float* __restrict__ m3, const float* __restrict__ v3)
{
    __shared__ float xs[64 * 61];
    __shared__ float s1a[64], s1b[64], s3a[64], s3b[64];
    int b = blockIdx.x, t = threadIdx.x;

    if (t < 64) {
        float i1 = g1[t] * rsqrtf(v1[t] + EPSV);
        s1a[t] = i1; s1b[t] = b1[t] - m1[t] * i1;
        float i3 = g3[t] * rsqrtf(v3[t] + EPSV);
        s3a[t] = i3; s3b[t] = b3[t] - m3[t] * i3;
    }
    const float* xb = x + (size_t)b * (CIN * RPOS);
    for (int i = t; i < CIN * RPOS; i += 256)
        xs[(i / RPOS) * 61 + (i % RPOS)] = xb[i];
    __syncthreads();

    uint32_t* y1h = (uint32_t*)g_y1h + (size_t)b * (RPOS * 32);
    uint32_t* y1l = (uint32_t*)g_y1l + (size_t)b * (RPOS * 32);
    __half2*  y3f = (__half2*)g_y3f  + (size_t)b * (RPOS * 32);
    for (int i = t; i < RPOS * 32; i += 256) {
        int j = i >> 5, c = (i & 31) * 2;
        float xa = xs[c * 61 + j], xc = xs[(c + 1) * 61 + j];
        float a1 = fmaxf(fmaf(xa, s1a[c], s1b[c]), 0.0f);
        float b1v = fmaxf(fmaf(xc, s1a[c + 1], s1b[c + 1]), 0.0f);
        float a3 = fmaxf(fmaf(xa, s3a[c], s3b[c]), 0.0f);
        float b3v = fmaxf(fmaf(xc, s3a[c + 1], s3b[c + 1]), 0.0f);
        uint32_t h, l;
        split2(a1, b1v, h, l); y1h[i] = h; y1l[i] = l;
        y3f[i] = __floats2half2_rn(a3, b3v);
    }
}

// ---------------------------------------------------------------------------
// packW: W1 -> bf16 h/l ; W2, W3 -> fp16 h/l. XOR swizzle pre-applied.
// ---------------------------------------------------------------------------
__global__ void packW_kernel(const float* __restrict__ W1, const float* __restrict__ W2,
                             const float* __restrict__ W3)
{
    int idx = blockIdx.x * 256 + threadIdx.x;
    const int n1 = KW * CMID * CIN, n2 = KW * COUT * CMID;
    if (idx < n1) {
        int k = idx / (CMID * 64), rem = idx % (CMID * 64);
        int o = rem / 64, c = rem % 64;
        float v = W1[o * (64 * KW) + c * KW + k];
        __nv_bfloat16 h = __float2bfloat16(v);
        __nv_bfloat16 l = __float2bfloat16(v - __bfloat162float(h));
        int sw = ((c >> 3) ^ (o & 7)) * 8 + (c & 7);
        g_W1p[(size_t)(k * CMID + o) * 64 + sw] = h;
        g_W1p[(size_t)n1 + (size_t)(k * CMID + o) * 64 + sw] = l;
    } else if (idx < n1 + 2 * n2) {
        int nloc = idx - n1;
        const float* W = (nloc < n2) ? W2 : W3;
        __half* dst = (nloc < n2) ? g_W2p : g_W3p;
        if (nloc >= n2) nloc -= n2;
        int k = nloc / (COUT * 64), rem = nloc % (COUT * 64);
        int o = rem / 64, c = rem % 64;
        float v = W[o * (64 * KW) + c * KW + k];
        __half h = __float2half_rn(v);
        __half l = __float2half_rn(v - __half2float(h));
        int sw = ((c >> 3) ^ (o & 7)) * 8 + (c & 7);
        dst[(size_t)(k * COUT + o) * 64 + sw] = h;
        dst[(size_t)n2 + (size_t)(k * COUT + o) * 64 + sw] = l;
    }
}

// ---------------------------------------------------------------------------
// conv_mid: bf16 3-pass (unchanged math). CTA = 4 batches, M=256, N=64.
// 512 threads, 16 warps (8m x 2n), warp tile 32x32. W triple-buffered.
// Epilogue stores y2 as fp16.
// ---------------------------------------------------------------------------
#define MIDY  61440u
#define MIDW  16384u
#define MIDNEI (MIDY + 3u * MIDW)
#define MIDBIAS (MIDNEI + 3136u)

__global__ __launch_bounds__(512)
void conv_mid_kernel(const int* __restrict__ nei, const float* __restrict__ c1,
                     const float* __restrict__ g2, const float* __restrict__ b2,
                     const float* __restrict__ m2, const float* __restrict__ v2)
{
    extern __shared__ __align__(1024) char smb[];
    uint32_t sbase = smem_u32(smb);

    int t = threadIdx.x, wid = t >> 5, l = t & 31;
    int*   snei  = (int*)(smb + MIDNEI);
    float* sbias = (float*)(smb + MIDBIAS);

    for (int i = t; i < RPOS * KW; i += 512) snei[i] = nei[i];
    if (t < 64) {
        sbias[t] = c1[t];
        float iv = g2[t] * rsqrtf(v2[t] + EPSV);
        sbias[64 + t] = iv; sbias[128 + t] = b2[t] - m2[t] * iv;
    }

    int b0 = blockIdx.x * 4;

    int wrow = t >> 2, wq = t & 3;
    int whl = wrow >> 6, wo = wrow & 63;
    uint32_t wdstoff = (uint32_t)(whl * 8192 + wo * 128 + wq * 32);
    size_t  wsrcoff = ((size_t)(whl * KW * CMID + wo) << 7) + (size_t)(wq * 32);

    if (t < 480) {
        int hl = t / 240, rem = t % 240, bb = rem / 60, r = rem % 60;
        const char* src = (const char*)(hl ? g_y1l : g_y1h)
                        + (((size_t)(b0 + bb) * RPOS + r) << 7);
        copy_row8(sbase + (uint32_t)(hl * 30720 + bb * 7680 + r * 128), src, (r & 7) << 4);
    }
    {
        const char* ws = (const char*)g_W1p + wsrcoff;
        uint32_t dst = sbase + MIDY + wdstoff;
        CP_ASYNC16(dst, ws); CP_ASYNC16(dst + 16, ws + 16);
        CP_COMMIT();
        ws = (const char*)g_W1p + wsrcoff + ((size_t)CMID << 7);
        dst = sbase + MIDY + MIDW + wdstoff;
        CP_ASYNC16(dst, ws); CP_ASYNC16(dst + 16, ws + 16);
        CP_COMMIT();
    }

    int m0 = (wid & 7) * 32, n0 = (wid >> 3) * 32;
    int lrA = l & 15, lgA = l >> 4;
    int lrB = (l & 7) + ((l >> 4) << 3), lgB = (l >> 3) & 1;

    int rB13[2]; uint32_t bOff[2];
#pragma unroll
    for (int mt = 0; mt < 2; mt++) {
        int m = m0 + mt * 16 + lrA;
        int bb = (m < 240) ? (m / 60) : 0;
        int r  = (m < 240) ? (m - bb * 60) : (m - 240);
        rB13[mt] = r * KW;
        bOff[mt] = (uint32_t)(bb * 7680);
    }

    float acc[2][4][4];
#pragma unroll
    for (int a = 0; a < 2; a++)
#pragma unroll
        for (int b = 0; b < 4; b++)
#pragma unroll
            for (int c = 0; c < 4; c++) acc[a][b][c] = 0.0f;

    int sc = 0;
    for (int s = 0; s < KW; s++) {
        if (s + 2 < KW) { CP_WAIT(1); } else { CP_WAIT(0); }
        __syncthreads();
        if (s + 2 < KW) {
            int slot_n = sc + 2; if (slot_n >= 3) slot_n -= 3;
            const char* ws = (const char*)g_W1p + wsrcoff + ((size_t)((s + 2) * CMID) << 7);
            uint32_t dst = sbase + MIDY + (uint32_t)slot_n * MIDW + wdstoff;
            CP_ASYNC16(dst, ws); CP_ASYNC16(dst + 16, ws + 16);
            CP_COMMIT();
        }

        uint32_t Wb = sbase + MIDY + (uint32_t)sc * MIDW;
        int j0 = snei[rB13[0] + s], j1 = snei[rB13[1] + s];
        uint32_t a0row = bOff[0] + (uint32_t)(j0 << 7);
        uint32_t a1row = bOff[1] + (uint32_t)(j1 << 7);
        int k0 = j0 & 7, k1 = j1 & 7;

#pragma unroll
        for (int ks = 0; ks < 4; ks++) {
            uint32_t ah[2][4], al[2][4];
            {
                uint32_t ad0 = sbase + a0row + (uint32_t)((((ks << 1) + lgA) ^ k0) << 4);
                LDMX4(ah[0][0], ah[0][1], ah[0][2], ah[0][3], ad0);
                LDMX4(al[0][0], al[0][1], al[0][2], al[0][3], ad0 + 30720u);
                uint32_t ad1 = sbase + a1row + (uint32_t)((((ks << 1) + lgA) ^ k1) << 4);
                LDMX4(ah[1][0], ah[1][1], ah[1][2], ah[1][3], ad1);
                LDMX4(al[1][0], al[1][1], al[1][2], al[1][3], ad1 + 30720u);
            }
#pragma unroll
            for (int q = 0; q < 2; q++) {
                uint32_t bh[4], bl[4];
                int row = n0 + q * 16 + lrB;
                uint32_t bd = Wb + (uint32_t)(row << 7)
                            + (uint32_t)((((ks << 1) + lgB) ^ (row & 7)) << 4);
                LDMX4(bh[0], bh[1], bh[2], bh[3], bd);
                LDMX4(bl[0], bl[1], bl[2], bl[3], bd + 8192u);
#pragma unroll
                for (int mt = 0; mt < 2; mt++)
#pragma unroll
                    for (int hf = 0; hf < 2; hf++) {
                        float* d = acc[mt][q * 2 + hf];
                        mma_bf16(d, ah[mt], &bh[hf * 2]);
                        mma_bf16(d, ah[mt], &bl[hf * 2]);
                        mma_bf16(d, al[mt], &bh[hf * 2]);
                    }
            }
        }
        sc = (sc == 2) ? 0 : sc + 1;
    }

    // epilogue: bn2+relu -> fp16 y2
#pragma unroll
    for (int mt = 0; mt < 2; mt++)
#pragma unroll
        for (int nt = 0; nt < 4; nt++) {
            float* d = acc[mt][nt];
            int o = n0 + nt * 8 + ((l & 3) << 1);
            float cv0 = sbias[o],       cv1 = sbias[o + 1];
            float i0  = sbias[64 + o],  i1  = sbias[65 + o];
            float a0  = sbias[128 + o], a1  = sbias[129 + o];
#pragma unroll
            for (int h = 0; h < 2; h++) {
                int m = m0 + mt * 16 + (l >> 2) + h * 8;
                if (m < 240) {
                    int bb = m / 60; int r = m - bb * 60;
                    float y0 = fmaxf(fmaf(d[h * 2]     + cv0, i0, a0), 0.0f);
                    float y1 = fmaxf(fmaf(d[h * 2 + 1] + cv1, i1, a1), 0.0f);
                    size_t off = (((size_t)(b0 + bb) * RPOS + r) << 5) + (o >> 1);
                    ((__half2*)g_y2f)[off] = __floats2half2_rn(y0, y1);
                }
            }
        }
}

// ---------------------------------------------------------------------------
// conv_out: fp16 2-pass. CTA = 4 batches (M=256), N=128, 26 k-stages.
// 512 threads, 16 warps (4m x 4n), warp tile 64x32.
// y2+y3 fp16 resident (1 matrix each); W fp16 h/l triple-buffered.
// smem: Y2 30720 | Y3 30720 | W 3x32768 | nei | bias  (~163 KB)
// ---------------------------------------------------------------------------
#define OY3   30720u
#define OWO   61440u
#define OW    32768u
#define ONEI  (OWO + 3u * OW)
#define OBIAS (ONEI + 3136u)

__global__ __launch_bounds__(512)
void conv_out_kernel(const int* __restrict__ nei, const float* __restrict__ c2,
                     const float* __restrict__ c3, float* __restrict__ out)
{
    extern __shared__ __align__(1024) char smb[];
    uint32_t sbase = smem_u32(smb);

    int t = threadIdx.x, wid = t >> 5, l = t & 31;
    int*   snei  = (int*)(smb + ONEI);
    float* sbias = (float*)(smb + OBIAS);

    for (int i = t; i < RPOS * KW; i += 512) snei[i] = nei[i];
    if (t < 128) sbias[t] = c2[t] + c3[t];

    int b0 = blockIdx.x * 4;

    // W copy role: half rows, all 512 threads
    int wrow = t >> 1, whalf = t & 1;
    int whl = wrow >> 7, wo = wrow & 127;
    uint32_t wdstoff = (uint32_t)(whl * 16384 + wo * 128 + whalf * 64);
    size_t  wsrcoff = ((size_t)(whl * KW * COUT + wo) << 7) + (size_t)(whalf * 64);

    // prologue: y2 + y3 (480 rows, fp16) + W(0), W(1)
    if (t < 480) {
        int ten = t / 240, rem = t % 240, bb = rem / 60, r = rem % 60;
        const char* src = (const char*)(ten ? (const void*)g_y3f : (const void*)g_y2f)
                        + (((size_t)(b0 + bb) * RPOS + r) << 7);
        copy_row8(sbase + (uint32_t)(ten ? OY3 : 0u) + (uint32_t)(bb * 7680 + r * 128),
                  src, (r & 7) << 4);
    }
    {
        const char* ws = (const char*)g_W2p + wsrcoff;
        uint32_t dst = sbase + OWO + wdstoff;
#pragma unroll
        for (int g = 0; g < 4; g++) CP_ASYNC16(dst + (g << 4), ws + (g << 4));
        CP_COMMIT();
        ws = (const char*)g_W2p + wsrcoff + ((size_t)COUT << 7);
        dst = sbase + OWO + OW + wdstoff;
#pragma unroll
        for (int g = 0; g < 4; g++) CP_ASYNC16(dst + (g << 4), ws + (g << 4));
        CP_COMMIT();
    }

    int m0 = (wid & 3) * 64, n0 = (wid >> 2) * 32;
    int lrA = l & 15, lgA = l >> 4;
    int lrB = (l & 7) + ((l >> 4) << 3), lgB = (l >> 3) & 1;

    int rB13[4]; uint32_t bOff[4];
#pragma unroll
    for (int mt = 0; mt < 4; mt++) {
        int m = m0 + mt * 16 + lrA;
        int bb = (m < 240) ? (m / 60) : 0;
        int r  = (m < 240) ? (m - bb * 60) : (m - 240);
        rB13[mt] = r * KW;
        bOff[mt] = (uint32_t)(bb * 7680);
    }

    float acc[4][4][4];
#pragma unroll
    for (int a = 0; a < 4; a++)
#pragma unroll
        for (int b = 0; b < 4; b++)
#pragma unroll
            for (int c = 0; c < 4; c++) acc[a][b][c] = 0.0f;

    const int S = 2 * KW;
    int sc = 0;
    for (int s = 0; s < S; s++) {
        if (s + 2 < S) { CP_WAIT(1); } else { CP_WAIT(0); }
        __syncthreads();
        if (s + 2 < S) {
            int sn = s + 2;
            int phn = sn >= KW, kn = sn - (phn ? KW : 0);
            int slot_n = sc + 2; if (slot_n >= 3) slot_n -= 3;
            const char* ws = (const char*)(phn ? g_W3p : g_W2p) + wsrcoff
                           + ((size_t)(kn * COUT) << 7);
            uint32_t dst = sbase + OWO + (uint32_t)slot_n * OW + wdstoff;
#pragma unroll
            for (int g = 0; g < 4; g++) CP_ASYNC16(dst + (g << 4), ws + (g << 4));
            CP_COMMIT();
        }

        int ph = (s >= KW), k = s - (ph ? KW : 0);
        uint32_t Yb = sbase + (uint32_t)(ph ? OY3 : 0u);
        uint32_t Wb = sbase + OWO + (uint32_t)sc * OW;

        uint32_t arow[4]; int akey[4];
#pragma unroll
        for (int mt = 0; mt < 4; mt++) {
            int j = snei[rB13[mt] + k];
            arow[mt] = Yb + bOff[mt] + (uint32_t)(j << 7);
            akey[mt] = j & 7;
        }

#pragma unroll
        for (int ks = 0; ks < 4; ks++) {
            uint32_t af[4][4];
#pragma unroll
            for (int mt = 0; mt < 4; mt++) {
                uint32_t ad = arow[mt] + (uint32_t)((((ks << 1) + lgA) ^ akey[mt]) << 4);
                LDMX4(af[mt][0], af[mt][1], af[mt][2], af[mt][3], ad);
            }
#pragma unroll
            for (int q = 0; q < 2; q++) {
                uint32_t bh[4], bl[4];
                int row = n0 + q * 16 + lrB;
                uint32_t bd = Wb + (uint32_t)(row << 7)
                            + (uint32_t)((((ks << 1) + lgB) ^ (row & 7)) << 4);
                LDMX4(bh[0], bh[1], bh[2], bh[3], bd);
                LDMX4(bl[0], bl[1], bl[2], bl[3], bd + 16384u);
#pragma unroll
                for (int mt = 0; mt < 4; mt++)
#pragma unroll
                    for (int hf = 0; hf < 2; hf++) {
                        float* d = acc[mt][q * 2 + hf];
                        mma_f16(d, af[mt], &bh[hf * 2]);
                        mma_f16(d, af[mt], &bl[hf * 2]);
                    }
            }
        }
        sc = (sc == 2) ? 0 : sc + 1;
    }

    // epilogue: +bias, direct global stores (out [b][o][r])
#pragma unroll
    for (int mt = 0; mt < 4; mt++)
#pragma unroll
        for (int nc = 0; nc < 4; nc++) {
            float* d = acc[mt][nc];
            int o = n0 + nc * 8 + ((l & 3) << 1);
            float bv0 = sbias[o], bv1 = sbias[o + 1];
#pragma unroll
            for (int h = 0; h < 2; h++) {
                int m = m0 + mt * 16 + (l >> 2) + h * 8;
                if (m < 240) {
                    int bb = m / 60; int r = m - bb * 60;
                    float* dp = out + ((size_t)(b0 + bb) * COUT + o) * RPOS + r;
                    dp[0]    = d[h * 2]     + bv0;
                    dp[RPOS] = d[h * 2 + 1] + bv1;
                }
            }
        }
}

// ---------------------------------------------------------------------------
extern "C" void kernel_launch(void* const* d_in, const int* in_sizes, int n_in,
                              void* d_out, int out_size)
{
    const float* x   = (const float*)d_in[0];
    const int*   nei = (const int*)d_in[1];
    const float* g1 = (const float*)d_in[2];
    const float* b1 = (const float*)d_in[3];
    const float* m1 = (const float*)d_in[4];
    const float* v1 = (const float*)d_in[5];
    const float* W1 = (const float*)d_in[6];
    const float* c1 = (const float*)d_in[7];
    const float* g2 = (const float*)d_in[8];
    const float* b2 = (const float*)d_in[9];
    const float* m2 = (const float*)d_in[10];
    const float* v2 = (const float*)d_in[11];
    const float* W2 = (const float*)d_in[12];
    const float* c2 = (const float*)d_in[13];
    const float* g3 = (const float*)d_in[14];
    const float* b3 = (const float*)d_in[15];
    const float* m3 = (const float*)d_in[16];
    const float* v3 = (const float*)d_in[17];
    const float* W3 = (const float*)d_in[18];
    const float* c3 = (const float*)d_in[19];
    float* out = (float*)d_out;

    const int smem_mid = (int)(MIDBIAS + 768 + 256);   // ~115 KB
    const int smem_out = (int)(OBIAS + 512 + 256);     // ~164 KB
    cudaFuncSetAttribute(conv_mid_kernel, cudaFuncAttributeMaxDynamicSharedMemorySize, smem_mid);
    cudaFuncSetAttribute(conv_out_kernel, cudaFuncAttributeMaxDynamicSharedMemorySize, smem_out);

    prep_kernel<<<BATCH, 256>>>(x, g1, b1, m1, v1, g3, b3, m3, v3);
    packW_kernel<<<(KW * (CMID * CIN + 2 * COUT * CMID) + 255) / 256, 256>>>(W1, W2, W3);
    conv_mid_kernel<<<BATCH / 4, 512, smem_mid>>>(nei, c1, g2, b2, m2, v2);
    conv_out_kernel<<<BATCH / 4, 512, smem_out>>>(nei, c2, c3, out);
}

// round 9
// speedup vs baseline: 3.3149x; 1.6230x over previous
#include <cuda_runtime.h>
#include <cuda_bf16.h>
#include <cuda_fp16.h>
#include <cstdint>

#define BATCH 2048
#define RPOS  60
#define KW    13
#define CIN   64
#define CMID  64
#define COUT  128
#define EPSV  1e-5f

// ---------------------------------------------------------------------------
// Device scratch: y tensors single fp16, layout [b][r][c] (128B rows)
// ---------------------------------------------------------------------------
__device__ __align__(128) __half g_y1f[BATCH * RPOS * CIN];
__device__ __align__(128) __half g_y2f[BATCH * RPOS * CMID];
__device__ __align__(128) __half g_y3f[BATCH * RPOS * CIN];
// Packed weights, fp16, 16B-granule XOR swizzle pre-applied.
// W1: hi/lo split [hl][k][o][c]. W2/W3: single [k][o][c].
__device__ __align__(128) __half g_W1p[2 * KW * CMID * CIN];
__device__ __align__(128) __half g_W2p[KW * COUT * CMID];
__device__ __align__(128) __half g_W3p[KW * COUT * CMID];

// ---------------------------------------------------------------------------
// PTX helpers
// ---------------------------------------------------------------------------
__device__ __forceinline__ uint32_t smem_u32(const void* p) {
    uint32_t a;
    asm("{ .reg .u64 t; cvta.to.shared.u64 t, %1; cvt.u32.u64 %0, t; }" : "=r"(a) : "l"(p));
    return a;
}

#define CP_ASYNC16(dst, src) \
    asm volatile("cp.async.cg.shared.global [%0], [%1], 16;" :: "r"(dst), "l"(src) : "memory")
#define CP_COMMIT()  asm volatile("cp.async.commit_group;" ::: "memory")
#define CP_WAIT(n)   asm volatile("cp.async.wait_group %0;" :: "n"(n) : "memory")

#define LDMX4(r0, r1, r2, r3, addr) \
    asm volatile("ldmatrix.sync.aligned.m8n8.x4.shared.b16 {%0,%1,%2,%3}, [%4];" \
        : "=r"(r0), "=r"(r1), "=r"(r2), "=r"(r3) : "r"(addr))

__device__ __forceinline__ void mma_f16(float* d, const uint32_t* a, const uint32_t* b) {
    asm volatile("mma.sync.aligned.m16n8k16.row.col.f32.f16.f16.f32 "
        "{%0,%1,%2,%3},{%4,%5,%6,%7},{%8,%9},{%0,%1,%2,%3};"
        : "+f"(d[0]), "+f"(d[1]), "+f"(d[2]), "+f"(d[3])
        : "r"(a[0]), "r"(a[1]), "r"(a[2]), "r"(a[3]), "r"(b[0]), "r"(b[1]));
}

// copy one 128B row, applying per-row XOR swizzle (key sw = (row&7)<<4)
__device__ __forceinline__ void copy_row8(uint32_t dst, const char* src, int sw) {
#pragma unroll
    for (int g = 0; g < 8; g++) CP_ASYNC16(dst + (uint32_t)((g << 4) ^ sw), src + (g << 4));
}

// ---------------------------------------------------------------------------
// prep: y1 = relu(bn1(x)) -> fp16 ; y3 = relu(bn3(x)) -> fp16
// ---------------------------------------------------------------------------
__global__ void prep_kernel(const float* __restrict__ x,
                            const float* __restrict__ g1, const float* __restrict__ b1,
                            const float* __restrict__ m1, const float* __restrict__ v1,
                            const float* __restrict__ g3, const float* __restrict__ b3,
                            const float* __restrict__ m3, const float* __restrict__ v3)
{
    __shared__ float xs[64 * 61];
    __shared__ float s1a[64], s1b[64], s3a[64], s3b[64];
    int b = blockIdx.x, t = threadIdx.x;

    if (t < 64) {
        float i1 = g1[t] * rsqrtf(v1[t] + EPSV);
        s1a[t] = i1; s1b[t] = b1[t] - m1[t] * i1;
        float i3 = g3[t] * rsqrtf(v3[t] + EPSV);
        s3a[t] = i3; s3b[t] = b3[t] - m3[t] * i3;
    }
    const float* xb = x + (size_t)b * (CIN * RPOS);
    for (int i = t; i < CIN * RPOS; i += 256)
        xs[(i / RPOS) * 61 + (i % RPOS)] = xb[i];
    __syncthreads();

    __half2* y1f = (__half2*)g_y1f + (size_t)b * (RPOS * 32);
    __half2* y3f = (__half2*)g_y3f + (size_t)b * (RPOS * 32);
    for (int i = t; i < RPOS * 32; i += 256) {
        int j = i >> 5, c = (i & 31) * 2;
        float xa = xs[c * 61 + j], xc = xs[(c + 1) * 61 + j];
        float a1 = fmaxf(fmaf(xa, s1a[c], s1b[c]), 0.0f);
        float b1v = fmaxf(fmaf(xc, s1a[c + 1], s1b[c + 1]), 0.0f);
        float a3 = fmaxf(fmaf(xa, s3a[c], s3b[c]), 0.0f);
        float b3v = fmaxf(fmaf(xc, s3a[c + 1], s3b[c + 1]), 0.0f);
        y1f[i] = __floats2half2_rn(a1, b1v);
        y3f[i] = __floats2half2_rn(a3, b3v);
    }
}

// ---------------------------------------------------------------------------
// packW: W1 -> fp16 hi/lo ; W2, W3 -> single fp16. XOR swizzle pre-applied.
// ---------------------------------------------------------------------------
__global__ void packW_kernel(const float* __restrict__ W1, const float* __restrict__ W2,
                             const float* __restrict__ W3)
{
    int idx = blockIdx.x * 256 + threadIdx.x;
    const int n1 = KW * CMID * CIN, n2 = KW * COUT * CMID;
    if (idx < n1) {
        int k = idx / (CMID * 64), rem = idx % (CMID * 64);
        int o = rem / 64, c = rem % 64;
        float v = W1[o * (64 * KW) + c * KW + k];
        __half h = __float2half_rn(v);
        __half l = __float2half_rn(v - __half2float(h));
        int sw = ((c >> 3) ^ (o & 7)) * 8 + (c & 7);
        g_W1p[(size_t)(k * CMID + o) * 64 + sw] = h;
        g_W1p[(size_t)n1 + (size_t)(k * CMID + o) * 64 + sw] = l;
    } else if (idx < n1 + 2 * n2) {
        int nloc = idx - n1;
        const float* W = (nloc < n2) ? W2 : W3;
        __half* dst = (nloc < n2) ? g_W2p : g_W3p;
        if (nloc >= n2) nloc -= n2;
        int k = nloc / (COUT * 64), rem = nloc % (COUT * 64);
        int o = rem / 64, c = rem % 64;
        float v = W[o * (64 * KW) + c * KW + k];
        int sw = ((c >> 3) ^ (o & 7)) * 8 + (c & 7);
        dst[(size_t)(k * COUT + o) * 64 + sw] = __float2half_rn(v);
    }
}

// ---------------------------------------------------------------------------
// conv_mid: fp16, A 1-pass + W1 hi/lo 2-pass. CTA = 4 batches, M=256, N=64.
// 512 threads, 16 warps (8m x 2n), warp tile 32x32. W triple-buffered.
// smem: Y1 30720 | W 3x16384 | nei | bias  (~82 KB)
// ---------------------------------------------------------------------------
#define MIDY  30720u
#define MIDW  16384u
#define MIDNEI (MIDY + 3u * MIDW)
#define MIDBIAS (MIDNEI + 3136u)

__global__ __launch_bounds__(512)
void conv_mid_kernel(const int* __restrict__ nei, const float* __restrict__ c1,
                     const float* __restrict__ g2, const float* __restrict__ b2,
                     const float* __restrict__ m2, const float* __restrict__ v2)
{
    extern __shared__ __align__(1024) char smb[];
    uint32_t sbase = smem_u32(smb);

    int t = threadIdx.x, wid = t >> 5, l = t & 31;
    int*   snei  = (int*)(smb + MIDNEI);
    float* sbias = (float*)(smb + MIDBIAS);

    for (int i = t; i < RPOS * KW; i += 512) snei[i] = nei[i];
    if (t < 64) {
        sbias[t] = c1[t];
        float iv = g2[t] * rsqrtf(v2[t] + EPSV);
        sbias[64 + t] = iv; sbias[128 + t] = b2[t] - m2[t] * iv;
    }

    int b0 = blockIdx.x * 4;

    // W copy: quarter rows (32B), 512 threads cover 128 rows (2hl x 64o)
    int wrow = t >> 2, wq = t & 3;
    int whl = wrow >> 6, wo = wrow & 63;
    uint32_t wdstoff = (uint32_t)(whl * 8192 + wo * 128 + wq * 32);
    size_t  wsrcoff = ((size_t)(whl * KW * CMID + wo) << 7) + (size_t)(wq * 32);

    // prologue: y1 (240 rows, fp16) + W(0) group0, W(1) group1
    if (t < 240) {
        int bb = t / 60, r = t % 60;
        const char* src = (const char*)g_y1f + (((size_t)(b0 + bb) * RPOS + r) << 7);
        copy_row8(sbase + (uint32_t)(bb * 7680 + r * 128), src, (r & 7) << 4);
    }
    {
        const char* ws = (const char*)g_W1p + wsrcoff;
        uint32_t dst = sbase + MIDY + wdstoff;
        CP_ASYNC16(dst, ws); CP_ASYNC16(dst + 16, ws + 16);
        CP_COMMIT();
        ws = (const char*)g_W1p + wsrcoff + ((size_t)CMID << 7);
        dst = sbase + MIDY + MIDW + wdstoff;
        CP_ASYNC16(dst, ws); CP_ASYNC16(dst + 16, ws + 16);
        CP_COMMIT();
    }

    int m0 = (wid & 7) * 32, n0 = (wid >> 3) * 32;
    int lrA = l & 15, lgA = l >> 4;
    int lrB = (l & 7) + ((l >> 4) << 3), lgB = (l >> 3) & 1;

    int rB13[2]; uint32_t bOff[2];
#pragma unroll
    for (int mt = 0; mt < 2; mt++) {
        int m = m0 + mt * 16 + lrA;
        int bb = (m < 240) ? (m / 60) : 0;
        int r  = (m < 240) ? (m - bb * 60) : (m - 240);
        rB13[mt] = r * KW;
        bOff[mt] = (uint32_t)(bb * 7680);
    }

    float acc[2][4][4];
#pragma unroll
    for (int a = 0; a < 2; a++)
#pragma unroll
        for (int b = 0; b < 4; b++)
#pragma unroll
            for (int c = 0; c < 4; c++) acc[a][b][c] = 0.0f;

    int sc = 0;
    for (int s = 0; s < KW; s++) {
        if (s + 2 < KW) { CP_WAIT(1); } else { CP_WAIT(0); }
        __syncthreads();
        if (s + 2 < KW) {
            int slot_n = sc + 2; if (slot_n >= 3) slot_n -= 3;
            const char* ws = (const char*)g_W1p + wsrcoff + ((size_t)((s + 2) * CMID) << 7);
            uint32_t dst = sbase + MIDY + (uint32_t)slot_n * MIDW + wdstoff;
            CP_ASYNC16(dst, ws); CP_ASYNC16(dst + 16, ws + 16);
            CP_COMMIT();
        }

        uint32_t Wb = sbase + MIDY + (uint32_t)sc * MIDW;
        int j0 = snei[rB13[0] + s], j1 = snei[rB13[1] + s];
        uint32_t a0row = sbase + bOff[0] + (uint32_t)(j0 << 7);
        uint32_t a1row = sbase + bOff[1] + (uint32_t)(j1 << 7);
        int k0 = j0 & 7, k1 = j1 & 7;

#pragma unroll
        for (int ks = 0; ks < 4; ks++) {
            uint32_t af[2][4];
            {
                uint32_t ad0 = a0row + (uint32_t)((((ks << 1) + lgA) ^ k0) << 4);
                LDMX4(af[0][0], af[0][1], af[0][2], af[0][3], ad0);
                uint32_t ad1 = a1row + (uint32_t)((((ks << 1) + lgA) ^ k1) << 4);
                LDMX4(af[1][0], af[1][1], af[1][2], af[1][3], ad1);
            }
#pragma unroll
            for (int q = 0; q < 2; q++) {
                uint32_t bh[4], bl[4];
                int row = n0 + q * 16 + lrB;
                uint32_t bd = Wb + (uint32_t)(row << 7)
                            + (uint32_t)((((ks << 1) + lgB) ^ (row & 7)) << 4);
                LDMX4(bh[0], bh[1], bh[2], bh[3], bd);
                LDMX4(bl[0], bl[1], bl[2], bl[3], bd + 8192u);
#pragma unroll
                for (int mt = 0; mt < 2; mt++)
#pragma unroll
                    for (int hf = 0; hf < 2; hf++) {
                        float* d = acc[mt][q * 2 + hf];
                        mma_f16(d, af[mt], &bh[hf * 2]);
                        mma_f16(d, af[mt], &bl[hf * 2]);
                    }
            }
        }
        sc = (sc == 2) ? 0 : sc + 1;
    }

    // epilogue: bn2+relu -> fp16 y2
#pragma unroll
    for (int mt = 0; mt < 2; mt++)
#pragma unroll
        for (int nt = 0; nt < 4; nt++) {
            float* d = acc[mt][nt];
            int o = n0 + nt * 8 + ((l & 3) << 1);
            float cv0 = sbias[o],       cv1 = sbias[o + 1];
            float i0  = sbias[64 + o],  i1  = sbias[65 + o];
            float a0  = sbias[128 + o], a1  = sbias[129 + o];
#pragma unroll
            for (int h = 0; h < 2; h++) {
                int m = m0 + mt * 16 + (l >> 2) + h * 8;
                if (m < 240) {
                    int bb = m / 60; int r = m - bb * 60;
                    float y0 = fmaxf(fmaf(d[h * 2]     + cv0, i0, a0), 0.0f);
                    float y1 = fmaxf(fmaf(d[h * 2 + 1] + cv1, i1, a1), 0.0f);
                    size_t off = (((size_t)(b0 + bb) * RPOS + r) << 5) + (o >> 1);
                    ((__half2*)g_y2f)[off] = __floats2half2_rn(y0, y1);
                }
            }
        }
}

// ---------------------------------------------------------------------------
// conv_out: fp16 1-pass (A single, W single). CTA = 4 batches, M=256, N=128.
// 512 threads, 16 warps (8m x 2n), warp tile 32x64. W triple-buffered.
// smem: Y2 30720 | Y3 30720 | W 3x16384 | nei | bias  (~112 KB)
// ---------------------------------------------------------------------------
#define OY3   30720u
#define OWO   61440u
#define OW    16384u
#define ONEI  (OWO + 3u * OW)
#define OBIAS (ONEI + 3136u)

__global__ __launch_bounds__(512)
void conv_out_kernel(const int* __restrict__ nei, const float* __restrict__ c2,
                     const float* __restrict__ c3, float* __restrict__ out)
{
    extern __shared__ __align__(1024) char smb[];
    uint32_t sbase = smem_u32(smb);

    int t = threadIdx.x, wid = t >> 5, l = t & 31;
    int*   snei  = (int*)(smb + ONEI);
    float* sbias = (float*)(smb + OBIAS);

    for (int i = t; i < RPOS * KW; i += 512) snei[i] = nei[i];
    if (t < 128) sbias[t] = c2[t] + c3[t];

    int b0 = blockIdx.x * 4;

    // W copy: quarter rows (32B), 512 threads cover 128 o-rows
    int wrow = t >> 2, wq = t & 3;
    uint32_t wdstoff = (uint32_t)(wrow * 128 + wq * 32);
    size_t  wsrcoff = ((size_t)wrow << 7) + (size_t)(wq * 32);

    // prologue: y2 + y3 (480 rows, fp16) + W(0), W(1)
    if (t < 480) {
        int ten = t / 240, rem = t % 240, bb = rem / 60, r = rem % 60;
        const char* src = (const char*)(ten ? (const void*)g_y3f : (const void*)g_y2f)
                        + (((size_t)(b0 + bb) * RPOS + r) << 7);
        copy_row8(sbase + (uint32_t)(ten ? OY3 : 0u) + (uint32_t)(bb * 7680 + r * 128),
                  src, (r & 7) << 4);
    }
    {
        const char* ws = (const char*)g_W2p + wsrcoff;   // k=0
        uint32_t dst = sbase + OWO + wdstoff;
        CP_ASYNC16(dst, ws); CP_ASYNC16(dst + 16, ws + 16);
        CP_COMMIT();
        ws = (const char*)g_W2p + wsrcoff + ((size_t)COUT << 7);  // k=1
        dst = sbase + OWO + OW + wdstoff;
        CP_ASYNC16(dst, ws); CP_ASYNC16(dst + 16, ws + 16);
        CP_COMMIT();
    }

    int m0 = (wid & 7) * 32, n0 = (wid >> 3) * 64;
    int lrA = l & 15, lgA = l >> 4;
    int lrB = (l & 7) + ((l >> 4) << 3), lgB = (l >> 3) & 1;

    int rB13[2]; uint32_t bOff[2];
#pragma unroll
    for (int mt = 0; mt < 2; mt++) {
        int m = m0 + mt * 16 + lrA;
        int bb = (m < 240) ? (m / 60) : 0;
        int r  = (m < 240) ? (m - bb * 60) : (m - 240);
        rB13[mt] = r * KW;
        bOff[mt] = (uint32_t)(bb * 7680);
    }

    float acc[2][8][4];
#pragma unroll
    for (int a = 0; a < 2; a++)
#pragma unroll
        for (int b = 0; b < 8; b++)
#pragma unroll
            for (int c = 0; c < 4; c++) acc[a][b][c] = 0.0f;

    const int S = 2 * KW;
    int sc = 0;
    for (int s = 0; s < S; s++) {
        if (s + 2 < S) { CP_WAIT(1); } else { CP_WAIT(0); }
        __syncthreads();
        if (s + 2 < S) {
            int sn = s + 2;
            int phn = sn >= KW, kn = sn - (phn ? KW : 0);
            int slot_n = sc + 2; if (slot_n >= 3) slot_n -= 3;
            const char* ws = (const char*)(phn ? g_W3p : g_W2p) + wsrcoff
                           + ((size_t)(kn * COUT) << 7);
            uint32_t dst = sbase + OWO + (uint32_t)slot_n * OW + wdstoff;
            CP_ASYNC16(dst, ws); CP_ASYNC16(dst + 16, ws + 16);
            CP_COMMIT();
        }

        int ph = (s >= KW), k = s - (ph ? KW : 0);
        uint32_t Yb = sbase + (uint32_t)(ph ? OY3 : 0u);
        uint32_t Wb = sbase + OWO + (uint32_t)sc * OW;

        uint32_t arow[2]; int akey[2];
#pragma unroll
        for (int mt = 0; mt < 2; mt++) {
            int j = snei[rB13[mt] + k];
            arow[mt] = Yb + bOff[mt] + (uint32_t)(j << 7);
            akey[mt] = j & 7;
        }

#pragma unroll
        for (int ks = 0; ks < 4; ks++) {
            uint32_t af[2][4];
#pragma unroll
            for (int mt = 0; mt < 2; mt++) {
                uint32_t ad = arow[mt] + (uint32_t)((((ks << 1) + lgA) ^ akey[mt]) << 4);
                LDMX4(af[mt][0], af[mt][1], af[mt][2], af[mt][3], ad);
            }
#pragma unroll
            for (int q = 0; q < 4; q++) {
                uint32_t bh[4];
                int row = n0 + q * 16 + lrB;
                uint32_t bd = Wb + (uint32_t)(row << 7)
                            + (uint32_t)((((ks << 1) + lgB) ^ (row & 7)) << 4);
                LDMX4(bh[0], bh[1], bh[2], bh[3], bd);
#pragma unroll
                for (int mt = 0; mt < 2; mt++)
#pragma unroll
                    for (int hf = 0; hf < 2; hf++)
                        mma_f16(acc[mt][q * 2 + hf], af[mt], &bh[hf * 2]);
            }
        }
        sc = (sc == 2) ? 0 : sc + 1;
    }

    // epilogue: +bias, direct global stores (out [b][o][r])
#pragma unroll
    for (int mt = 0; mt < 2; mt++)
#pragma unroll
        for (int nc = 0; nc < 8; nc++) {
            float* d = acc[mt][nc];
            int o = n0 + nc * 8 + ((l & 3) << 1);
            float bv0 = sbias[o], bv1 = sbias[o + 1];
#pragma unroll
            for (int h = 0; h < 2; h++) {
                int m = m0 + mt * 16 + (l >> 2) + h * 8;
                if (m < 240) {
                    int bb = m / 60; int r = m - bb * 60;
                    float* dp = out + ((size_t)(b0 + bb) * COUT + o) * RPOS + r;
                    dp[0]    = d[h * 2]     + bv0;
                    dp[RPOS] = d[h * 2 + 1] + bv1;
                }
            }
        }
}

// ---------------------------------------------------------------------------
extern "C" void kernel_launch(void* const* d_in, const int* in_sizes, int n_in,
                              void* d_out, int out_size)
{
    const float* x   = (const float*)d_in[0];
    const int*   nei = (const int*)d_in[1];
    const float* g1 = (const float*)d_in[2];
    const float* b1 = (const float*)d_in[3];
    const float* m1 = (const float*)d_in[4];
    const float* v1 = (const float*)d_in[5];
    const float* W1 = (const float*)d_in[6];
    const float* c1 = (const float*)d_in[7];
    const float* g2 = (const float*)d_in[8];
    const float* b2 = (const float*)d_in[9];
    const float* m2 = (const float*)d_in[10];
    const float* v2 = (const float*)d_in[11];
    const float* W2 = (const float*)d_in[12];
    const float* c2 = (const float*)d_in[13];
    const float* g3 = (const float*)d_in[14];
    const float* b3 = (const float*)d_in[15];
    const float* m3 = (const float*)d_in[16];
    const float* v3 = (const float*)d_in[17];
    const float* W3 = (const float*)d_in[18];
    const float* c3 = (const float*)d_in[19];
    float* out = (float*)d_out;

    const int smem_mid = (int)(MIDBIAS + 768 + 256);   // ~82 KB
    const int smem_out = (int)(OBIAS + 512 + 256);     // ~112 KB
    cudaFuncSetAttribute(conv_mid_kernel, cudaFuncAttributeMaxDynamicSharedMemorySize, smem_mid);
    cudaFuncSetAttribute(conv_out_kernel, cudaFuncAttributeMaxDynamicSharedMemorySize, smem_out);

    prep_kernel<<<BATCH, 256>>>(x, g1, b1, m1, v1, g3, b3, m3, v3);
    packW_kernel<<<(KW * (CMID * CIN + 2 * COUT * CMID) + 255) / 256, 256>>>(W1, W2, W3);
    conv_mid_kernel<<<BATCH / 4, 512, smem_mid>>>(nei, c1, g2, b2, m2, v2);
    conv_out_kernel<<<BATCH / 4, 512, smem_out>>>(nei, c2, c3, out);
}

// round 10
// speedup vs baseline: 3.4470x; 1.0399x over previous
#include <cuda_runtime.h>
#include <cuda_bf16.h>
#include <cuda_fp16.h>
#include <cstdint>

#define BATCH 2048
#define RPOS  60
#define KW    13
#define CIN   64
#define CMID  64
#define COUT  128
#define EPSV  1e-5f

// ---------------------------------------------------------------------------
// Device scratch: y tensors single fp16, layout [b][r][c] (128B rows)
// ---------------------------------------------------------------------------
__device__ __align__(128) __half g_y1f[BATCH * RPOS * CIN];
__device__ __align__(128) __half g_y2f[BATCH * RPOS * CMID];
__device__ __align__(128) __half g_y3f[BATCH * RPOS * CIN];
// Packed weights, single fp16, [k][o][c], 16B-granule XOR swizzle pre-applied.
__device__ __align__(128) __half g_W1p[KW * CMID * CIN];
__device__ __align__(128) __half g_W2p[KW * COUT * CMID];
__device__ __align__(128) __half g_W3p[KW * COUT * CMID];

// ---------------------------------------------------------------------------
// PTX helpers
// ---------------------------------------------------------------------------
__device__ __forceinline__ uint32_t smem_u32(const void* p) {
    uint32_t a;
    asm("{ .reg .u64 t; cvta.to.shared.u64 t, %1; cvt.u32.u64 %0, t; }" : "=r"(a) : "l"(p));
    return a;
}

#define CP_ASYNC16(dst, src) \
    asm volatile("cp.async.cg.shared.global [%0], [%1], 16;" :: "r"(dst), "l"(src) : "memory")
#define CP_COMMIT()  asm volatile("cp.async.commit_group;" ::: "memory")
#define CP_WAIT(n)   asm volatile("cp.async.wait_group %0;" :: "n"(n) : "memory")

#define LDMX4(r0, r1, r2, r3, addr) \
    asm volatile("ldmatrix.sync.aligned.m8n8.x4.shared.b16 {%0,%1,%2,%3}, [%4];" \
        : "=r"(r0), "=r"(r1), "=r"(r2), "=r"(r3) : "r"(addr))

__device__ __forceinline__ void mma_f16(float* d, const uint32_t* a, const uint32_t* b) {
    asm volatile("mma.sync.aligned.m16n8k16.row.col.f32.f16.f16.f32 "
        "{%0,%1,%2,%3},{%4,%5,%6,%7},{%8,%9},{%0,%1,%2,%3};"
        : "+f"(d[0]), "+f"(d[1]), "+f"(d[2]), "+f"(d[3])
        : "r"(a[0]), "r"(a[1]), "r"(a[2]), "r"(a[3]), "r"(b[0]), "r"(b[1]));
}

// copy one 128B row, applying per-row XOR swizzle (key sw = (row&7)<<4)
__device__ __forceinline__ void copy_row8(uint32_t dst, const char* src, int sw) {
#pragma unroll
    for (int g = 0; g < 8; g++) CP_ASYNC16(dst + (uint32_t)((g << 4) ^ sw), src + (g << 4));
}

// ---------------------------------------------------------------------------
// prep: y1 = relu(bn1(x)) -> fp16 ; y3 = relu(bn3(x)) -> fp16
// ---------------------------------------------------------------------------
__global__ void prep_kernel(const float* __restrict__ x,
                            const float* __restrict__ g1, const float* __restrict__ b1,
                            const float* __restrict__ m1, const float* __restrict__ v1,
                            const float* __restrict__ g3, const float* __restrict__ b3,
                            const float* __restrict__ m3, const float* __restrict__ v3)
{
    __shared__ float xs[64 * 61];
    __shared__ float s1a[64], s1b[64], s3a[64], s3b[64];
    int b = blockIdx.x, t = threadIdx.x;

    if (t < 64) {
        float i1 = g1[t] * rsqrtf(v1[t] + EPSV);
        s1a[t] = i1; s1b[t] = b1[t] - m1[t] * i1;
        float i3 = g3[t] * rsqrtf(v3[t] + EPSV);
        s3a[t] = i3; s3b[t] = b3[t] - m3[t] * i3;
    }
    const float* xb = x + (size_t)b * (CIN * RPOS);
    for (int i = t; i < CIN * RPOS; i += 256)
        xs[(i / RPOS) * 61 + (i % RPOS)] = xb[i];
    __syncthreads();

    __half2* y1f = (__half2*)g_y1f + (size_t)b * (RPOS * 32);
    __half2* y3f = (__half2*)g_y3f + (size_t)b * (RPOS * 32);
    for (int i = t; i < RPOS * 32; i += 256) {
        int j = i >> 5, c = (i & 31) * 2;
        float xa = xs[c * 61 + j], xc = xs[(c + 1) * 61 + j];
        float a1 = fmaxf(fmaf(xa, s1a[c], s1b[c]), 0.0f);
        float b1v = fmaxf(fmaf(xc, s1a[c + 1], s1b[c + 1]), 0.0f);
        float a3 = fmaxf(fmaf(xa, s3a[c], s3b[c]), 0.0f);
        float b3v = fmaxf(fmaf(xc, s3a[c + 1], s3b[c + 1]), 0.0f);
        y1f[i] = __floats2half2_rn(a1, b1v);
        y3f[i] = __floats2half2_rn(a3, b3v);
    }
}

// ---------------------------------------------------------------------------
// packW: all weights single fp16, XOR swizzle pre-applied.
// ---------------------------------------------------------------------------
__global__ void packW_kernel(const float* __restrict__ W1, const float* __restrict__ W2,
                             const float* __restrict__ W3)
{
    int idx = blockIdx.x * 256 + threadIdx.x;
    const int n1 = KW * CMID * CIN, n2 = KW * COUT * CMID;
    const float* W; __half* dst; int O, nloc;
    if (idx < n1)              { W = W1; dst = g_W1p; O = CMID; nloc = idx;           }
    else if (idx < n1 + n2)    { W = W2; dst = g_W2p; O = COUT; nloc = idx - n1;      }
    else if (idx < n1 + 2*n2)  { W = W3; dst = g_W3p; O = COUT; nloc = idx - n1 - n2; }
    else return;
    int k = nloc / (O * 64), rem = nloc % (O * 64);
    int o = rem / 64, c = rem % 64;
    float v = W[o * (64 * KW) + c * KW + k];
    int sw = ((c >> 3) ^ (o & 7)) * 8 + (c & 7);
    dst[(size_t)(k * O + o) * 64 + sw] = __float2half_rn(v);
}

// ---------------------------------------------------------------------------
// conv_mid: fp16 1-pass. CTA = 4 batches, M=256, N=64. 512 threads, 16 warps
// (8m x 2n), warp tile 32x32. W triple-buffered; fragment ping-pong pipeline.
// smem: Y1 30720 | W 3x8192 | nei | bias
// ---------------------------------------------------------------------------
#define MIDY  30720u
#define MIDW  8192u
#define MIDNEI (MIDY + 3u * MIDW)
#define MIDBIAS (MIDNEI + 3136u)

__global__ __launch_bounds__(512)
void conv_mid_kernel(const int* __restrict__ nei, const float* __restrict__ c1,
                     const float* __restrict__ g2, const float* __restrict__ b2,
                     const float* __restrict__ m2, const float* __restrict__ v2)
{
    extern __shared__ __align__(1024) char smb[];
    uint32_t sbase = smem_u32(smb);

    int t = threadIdx.x, wid = t >> 5, l = t & 31;
    int*   snei  = (int*)(smb + MIDNEI);
    float* sbias = (float*)(smb + MIDBIAS);

    for (int i = t; i < RPOS * KW; i += 512) snei[i] = nei[i];
    if (t < 64) {
        sbias[t] = c1[t];
        float iv = g2[t] * rsqrtf(v2[t] + EPSV);
        sbias[64 + t] = iv; sbias[128 + t] = b2[t] - m2[t] * iv;
    }

    int b0 = blockIdx.x * 4;

    // W copy: 64 rows x 128B = 512 x 16B chunks, one per thread
    int wrow = t >> 3, wch = t & 7;
    uint32_t wdstoff = (uint32_t)(wrow * 128 + wch * 16);
    size_t  wsrcoff = ((size_t)wrow << 7) + (size_t)(wch * 16);

    if (t < 240) {
        int bb = t / 60, r = t % 60;
        const char* src = (const char*)g_y1f + (((size_t)(b0 + bb) * RPOS + r) << 7);
        copy_row8(sbase + (uint32_t)(bb * 7680 + r * 128), src, (r & 7) << 4);
    }
    {
        CP_ASYNC16(sbase + MIDY + wdstoff, (const char*)g_W1p + wsrcoff);
        CP_COMMIT();
        CP_ASYNC16(sbase + MIDY + MIDW + wdstoff,
                   (const char*)g_W1p + wsrcoff + ((size_t)CMID << 7));
        CP_COMMIT();
    }

    int m0 = (wid & 7) * 32, n0 = (wid >> 3) * 32;
    int lrA = l & 15, lgA = l >> 4;
    int lrB = (l & 7) + ((l >> 4) << 3), lgB = (l >> 3) & 1;
    int bkey = lrB & 7;
    uint32_t browoff[2];
#pragma unroll
    for (int q = 0; q < 2; q++) browoff[q] = (uint32_t)((n0 + q * 16 + lrB) << 7);

    int rB13[2]; uint32_t bOff[2];
#pragma unroll
    for (int mt = 0; mt < 2; mt++) {
        int m = m0 + mt * 16 + lrA;
        int bb = (m < 240) ? (m / 60) : 0;
        int r  = (m < 240) ? (m - bb * 60) : (m - 240);
        rB13[mt] = r * KW;
        bOff[mt] = (uint32_t)(bb * 7680);
    }

    float acc[2][4][4];
#pragma unroll
    for (int a = 0; a < 2; a++)
#pragma unroll
        for (int b = 0; b < 4; b++)
#pragma unroll
            for (int c = 0; c < 4; c++) acc[a][b][c] = 0.0f;

    int sc = 0;
    for (int s = 0; s < KW; s++) {
        if (s + 2 < KW) { CP_WAIT(1); } else { CP_WAIT(0); }
        __syncthreads();
        if (s + 2 < KW) {
            int slot_n = sc + 2; if (slot_n >= 3) slot_n -= 3;
            CP_ASYNC16(sbase + MIDY + (uint32_t)slot_n * MIDW + wdstoff,
                       (const char*)g_W1p + wsrcoff + ((size_t)((s + 2) * CMID) << 7));
            CP_COMMIT();
        }

        uint32_t Wb = sbase + MIDY + (uint32_t)sc * MIDW;
        uint32_t arow[2]; int akey[2];
#pragma unroll
        for (int mt = 0; mt < 2; mt++) {
            int j = snei[rB13[mt] + s];
            arow[mt] = sbase + bOff[mt] + (uint32_t)(j << 7);
            akey[mt] = j & 7;
        }

#define MLOAD_A(buf, kss) do {                                                  \
    _Pragma("unroll")                                                           \
    for (int _mt = 0; _mt < 2; _mt++) {                                         \
        uint32_t _ad = arow[_mt]                                                \
            + (uint32_t)(((((kss) << 1) + lgA) ^ akey[_mt]) << 4);              \
        LDMX4((buf)[_mt][0], (buf)[_mt][1], (buf)[_mt][2], (buf)[_mt][3], _ad); \
    } } while (0)
#define MLOAD_B(buf, kss, qq) do {                                              \
    uint32_t _bd = Wb + browoff[qq]                                             \
        + (uint32_t)(((((kss) << 1) + lgB) ^ bkey) << 4);                       \
    LDMX4((buf)[0], (buf)[1], (buf)[2], (buf)[3], _bd); } while (0)

        uint32_t af2[2][2][4], b2r[2][4];
        MLOAD_A(af2[0], 0);
        MLOAD_B(b2r[0], 0, 0);
#pragma unroll
        for (int ks = 0; ks < 4; ks++) {
            if (ks < 3) MLOAD_A(af2[(ks + 1) & 1], ks + 1);
#pragma unroll
            for (int q = 0; q < 2; q++) {
                int idx = (ks * 2 + q) & 1;
                if (q < 1)       MLOAD_B(b2r[idx ^ 1], ks, 1);
                else if (ks < 3) MLOAD_B(b2r[idx ^ 1], ks + 1, 0);
#pragma unroll
                for (int mt = 0; mt < 2; mt++)
#pragma unroll
                    for (int hf = 0; hf < 2; hf++)
                        mma_f16(acc[mt][q * 2 + hf], af2[ks & 1][mt], &b2r[idx][hf * 2]);
            }
        }
#undef MLOAD_A
#undef MLOAD_B
        sc = (sc == 2) ? 0 : sc + 1;
    }

    // epilogue: bn2+relu -> fp16 y2
#pragma unroll
    for (int mt = 0; mt < 2; mt++)
#pragma unroll
        for (int nt = 0; nt < 4; nt++) {
            float* d = acc[mt][nt];
            int o = n0 + nt * 8 + ((l & 3) << 1);
            float cv0 = sbias[o],       cv1 = sbias[o + 1];
            float i0  = sbias[64 + o],  i1  = sbias[65 + o];
            float a0  = sbias[128 + o], a1  = sbias[129 + o];
#pragma unroll
            for (int h = 0; h < 2; h++) {
                int m = m0 + mt * 16 + (l >> 2) + h * 8;
                if (m < 240) {
                    int bb = m / 60; int r = m - bb * 60;
                    float y0 = fmaxf(fmaf(d[h * 2]     + cv0, i0, a0), 0.0f);
                    float y1 = fmaxf(fmaf(d[h * 2 + 1] + cv1, i1, a1), 0.0f);
                    size_t off = (((size_t)(b0 + bb) * RPOS + r) << 5) + (o >> 1);
                    ((__half2*)g_y2f)[off] = __floats2half2_rn(y0, y1);
                }
            }
        }
}

// ---------------------------------------------------------------------------
// conv_out: fp16 1-pass. CTA = 4 batches, M=256, N=128, 26 k-stages.
// 512 threads, 16 warps (8m x 2n), warp tile 32x64. W triple-buffered;
// fragment ping-pong pipeline.
// smem: Y2 30720 | Y3 30720 | W 3x16384 | nei | bias
// ---------------------------------------------------------------------------
#define OY3   30720u
#define OWO   61440u
#define OW    16384u
#define ONEI  (OWO + 3u * OW)
#define OBIAS (ONEI + 3136u)

__global__ __launch_bounds__(512)
void conv_out_kernel(const int* __restrict__ nei, const float* __restrict__ c2,
                     const float* __restrict__ c3, float* __restrict__ out)
{
    extern __shared__ __align__(1024) char smb[];
    uint32_t sbase = smem_u32(smb);

    int t = threadIdx.x, wid = t >> 5, l = t & 31;
    int*   snei  = (int*)(smb + ONEI);
    float* sbias = (float*)(smb + OBIAS);

    for (int i = t; i < RPOS * KW; i += 512) snei[i] = nei[i];
    if (t < 128) sbias[t] = c2[t] + c3[t];

    int b0 = blockIdx.x * 4;

    // W copy: 128 rows x 128B = 512 x 32B, quarter rows
    int wrow = t >> 2, wq = t & 3;
    uint32_t wdstoff = (uint32_t)(wrow * 128 + wq * 32);
    size_t  wsrcoff = ((size_t)wrow << 7) + (size_t)(wq * 32);

    if (t < 480) {
        int ten = t / 240, rem = t % 240, bb = rem / 60, r = rem % 60;
        const char* src = (const char*)(ten ? (const void*)g_y3f : (const void*)g_y2f)
                        + (((size_t)(b0 + bb) * RPOS + r) << 7);
        copy_row8(sbase + (uint32_t)(ten ? OY3 : 0u) + (uint32_t)(bb * 7680 + r * 128),
                  src, (r & 7) << 4);
    }
    {
        const char* ws = (const char*)g_W2p + wsrcoff;
        uint32_t dst = sbase + OWO + wdstoff;
        CP_ASYNC16(dst, ws); CP_ASYNC16(dst + 16, ws + 16);
        CP_COMMIT();
        ws = (const char*)g_W2p + wsrcoff + ((size_t)COUT << 7);
        dst = sbase + OWO + OW + wdstoff;
        CP_ASYNC16(dst, ws); CP_ASYNC16(dst + 16, ws + 16);
        CP_COMMIT();
    }

    int m0 = (wid & 7) * 32, n0 = (wid >> 3) * 64;
    int lrA = l & 15, lgA = l >> 4;
    int lrB = (l & 7) + ((l >> 4) << 3), lgB = (l >> 3) & 1;
    int bkey = lrB & 7;
    uint32_t browoff[4];
#pragma unroll
    for (int q = 0; q < 4; q++) browoff[q] = (uint32_t)((n0 + q * 16 + lrB) << 7);

    int rB13[2]; uint32_t bOff[2];
#pragma unroll
    for (int mt = 0; mt < 2; mt++) {
        int m = m0 + mt * 16 + lrA;
        int bb = (m < 240) ? (m / 60) : 0;
        int r  = (m < 240) ? (m - bb * 60) : (m - 240);
        rB13[mt] = r * KW;
        bOff[mt] = (uint32_t)(bb * 7680);
    }

    float acc[2][8][4];
#pragma unroll
    for (int a = 0; a < 2; a++)
#pragma unroll
        for (int b = 0; b < 8; b++)
#pragma unroll
            for (int c = 0; c < 4; c++) acc[a][b][c] = 0.0f;

    const int S = 2 * KW;
    int sc = 0;
    for (int s = 0; s < S; s++) {
        if (s + 2 < S) { CP_WAIT(1); } else { CP_WAIT(0); }
        __syncthreads();
        if (s + 2 < S) {
            int sn = s + 2;
            int phn = sn >= KW, kn = sn - (phn ? KW : 0);
            int slot_n = sc + 2; if (slot_n >= 3) slot_n -= 3;
            const char* ws = (const char*)(phn ? g_W3p : g_W2p) + wsrcoff
                           + ((size_t)(kn * COUT) << 7);
            uint32_t dst = sbase + OWO + (uint32_t)slot_n * OW + wdstoff;
            CP_ASYNC16(dst, ws); CP_ASYNC16(dst + 16, ws + 16);
            CP_COMMIT();
        }

        int ph = (s >= KW), k = s - (ph ? KW : 0);
        uint32_t Yb = sbase + (uint32_t)(ph ? OY3 : 0u);
        uint32_t Wb = sbase + OWO + (uint32_t)sc * OW;

        uint32_t arow[2]; int akey[2];
#pragma unroll
        for (int mt = 0; mt < 2; mt++) {
            int j = snei[rB13[mt] + k];
            arow[mt] = Yb + bOff[mt] + (uint32_t)(j << 7);
            akey[mt] = j & 7;
        }

#define OLOAD_A(buf, kss) do {                                                  \
    _Pragma("unroll")                                                           \
    for (int _mt = 0; _mt < 2; _mt++) {                                         \
        uint32_t _ad = arow[_mt]                                                \
            + (uint32_t)(((((kss) << 1) + lgA) ^ akey[_mt]) << 4);              \
        LDMX4((buf)[_mt][0], (buf)[_mt][1], (buf)[_mt][2], (buf)[_mt][3], _ad); \
    } } while (0)
#define OLOAD_B(buf, kss, qq) do {                                              \
    uint32_t _bd = Wb + browoff[qq]                                             \
        + (uint32_t)(((((kss) << 1) + lgB) ^ bkey) << 4);                       \
    LDMX4((buf)[0], (buf)[1], (buf)[2], (buf)[3], _bd); } while (0)

        uint32_t af2[2][2][4], b2r[2][4];
        OLOAD_A(af2[0], 0);
        OLOAD_B(b2r[0], 0, 0);
#pragma unroll
        for (int ks = 0; ks < 4; ks++) {
            if (ks < 3) OLOAD_A(af2[(ks + 1) & 1], ks + 1);
#pragma unroll
            for (int q = 0; q < 4; q++) {
                int idx = (ks * 4 + q) & 1;
                if (q < 3)       OLOAD_B(b2r[idx ^ 1], ks, q + 1);
                else if (ks < 3) OLOAD_B(b2r[idx ^ 1], ks + 1, 0);
#pragma unroll
                for (int mt = 0; mt < 2; mt++)
#pragma unroll
                    for (int hf = 0; hf < 2; hf++)
                        mma_f16(acc[mt][q * 2 + hf], af2[ks & 1][mt], &b2r[idx][hf * 2]);
            }
        }
#undef OLOAD_A
#undef OLOAD_B
        sc = (sc == 2) ? 0 : sc + 1;
    }

    // epilogue: +bias, direct global stores (out [b][o][r])
#pragma unroll
    for (int mt = 0; mt < 2; mt++)
#pragma unroll
        for (int nc = 0; nc < 8; nc++) {
            float* d = acc[mt][nc];
            int o = n0 + nc * 8 + ((l & 3) << 1);
            float bv0 = sbias[o], bv1 = sbias[o + 1];
#pragma unroll
            for (int h = 0; h < 2; h++) {
                int m = m0 + mt * 16 + (l >> 2) + h * 8;
                if (m < 240) {
                    int bb = m / 60; int r = m - bb * 60;
                    float* dp = out + ((size_t)(b0 + bb) * COUT + o) * RPOS + r;
                    dp[0]    = d[h * 2]     + bv0;
                    dp[RPOS] = d[h * 2 + 1] + bv1;
                }
            }
        }
}

// ---------------------------------------------------------------------------
extern "C" void kernel_launch(void* const* d_in, const int* in_sizes, int n_in,
                              void* d_out, int out_size)
{
    const float* x   = (const float*)d_in[0];
    const int*   nei = (const int*)d_in[1];
    const float* g1 = (const float*)d_in[2];
    const float* b1 = (const float*)d_in[3];
    const float* m1 = (const float*)d_in[4];
    const float* v1 = (const float*)d_in[5];
    const float* W1 = (const float*)d_in[6];
    const float* c1 = (const float*)d_in[7];
    const float* g2 = (const float*)d_in[8];
    const float* b2 = (const float*)d_in[9];
    const float* m2 = (const float*)d_in[10];
    const float* v2 = (const float*)d_in[11];
    const float* W2 = (const float*)d_in[12];
    const float* c2 = (const float*)d_in[13];
    const float* g3 = (const float*)d_in[14];
    const float* b3 = (const float*)d_in[15];
    const float* m3 = (const float*)d_in[16];
    const float* v3 = (const float*)d_in[17];
    const float* W3 = (const float*)d_in[18];
    const float* c3 = (const float*)d_in[19];
    float* out = (float*)d_out;

    const int smem_mid = (int)(MIDBIAS + 768 + 256);
    const int smem_out = (int)(OBIAS + 512 + 256);
    cudaFuncSetAttribute(conv_mid_kernel, cudaFuncAttributeMaxDynamicSharedMemorySize, smem_mid);
    cudaFuncSetAttribute(conv_out_kernel, cudaFuncAttributeMaxDynamicSharedMemorySize, smem_out);

    prep_kernel<<<BATCH, 256>>>(x, g1, b1, m1, v1, g3, b3, m3, v3);
    packW_kernel<<<(KW * (CMID * CIN + 2 * COUT * CMID) + 255) / 256, 256>>>(W1, W2, W3);
    conv_mid_kernel<<<BATCH / 4, 512, smem_mid>>>(nei, c1, g2, b2, m2, v2);
    conv_out_kernel<<<BATCH / 4, 512, smem_out>>>(nei, c2, c3, out);
}

// round 11
// speedup vs baseline: 3.9739x; 1.1528x over previous
#include <cuda_runtime.h>
#include <cuda_bf16.h>
#include <cuda_fp16.h>
#include <cstdint>

#define BATCH 2048
#define RPOS  60
#define KW    13
#define CIN   64
#define CMID  64
#define COUT  128
#define EPSV  1e-5f

// ---------------------------------------------------------------------------
// Device scratch: y tensors single fp16, layout [b][r][c] (128B rows)
// ---------------------------------------------------------------------------
__device__ __align__(128) __half g_y1f[BATCH * RPOS * CIN];
__device__ __align__(128) __half g_y2f[BATCH * RPOS * CMID];
__device__ __align__(128) __half g_y3f[BATCH * RPOS * CIN];
// Packed weights, single fp16, [k][o][c], 16B-granule XOR swizzle pre-applied.
__device__ __align__(128) __half g_W1p[KW * CMID * CIN];
__device__ __align__(128) __half g_W2p[KW * COUT * CMID];
__device__ __align__(128) __half g_W3p[KW * COUT * CMID];

// ---------------------------------------------------------------------------
// PTX helpers
// ---------------------------------------------------------------------------
__device__ __forceinline__ uint32_t smem_u32(const void* p) {
    uint32_t a;
    asm("{ .reg .u64 t; cvta.to.shared.u64 t, %1; cvt.u32.u64 %0, t; }" : "=r"(a) : "l"(p));
    return a;
}

#define CP_ASYNC16(dst, src) \
    asm volatile("cp.async.cg.shared.global [%0], [%1], 16;" :: "r"(dst), "l"(src) : "memory")
#define CP_COMMIT()  asm volatile("cp.async.commit_group;" ::: "memory")
#define CP_WAIT(n)   asm volatile("cp.async.wait_group %0;" :: "n"(n) : "memory")

#define LDMX4(r0, r1, r2, r3, addr) \
    asm volatile("ldmatrix.sync.aligned.m8n8.x4.shared.b16 {%0,%1,%2,%3}, [%4];" \
        : "=r"(r0), "=r"(r1), "=r"(r2), "=r"(r3) : "r"(addr))

__device__ __forceinline__ void mma_f16(float* d, const uint32_t* a, const uint32_t* b) {
    asm volatile("mma.sync.aligned.m16n8k16.row.col.f32.f16.f16.f32 "
        "{%0,%1,%2,%3},{%4,%5,%6,%7},{%8,%9},{%0,%1,%2,%3};"
        : "+f"(d[0]), "+f"(d[1]), "+f"(d[2]), "+f"(d[3])
        : "r"(a[0]), "r"(a[1]), "r"(a[2]), "r"(a[3]), "r"(b[0]), "r"(b[1]));
}

// copy one 128B row, applying per-row XOR swizzle (key sw = (row&7)<<4)
__device__ __forceinline__ void copy_row8(uint32_t dst, const char* src, int sw) {
#pragma unroll
    for (int g = 0; g < 8; g++) CP_ASYNC16(dst + (uint32_t)((g << 4) ^ sw), src + (g << 4));
}

// ---------------------------------------------------------------------------
// prep: y1 = relu(bn1(x)) -> fp16 ; y3 = relu(bn3(x)) -> fp16
// ---------------------------------------------------------------------------
__global__ void prep_kernel(const float* __restrict__ x,
                            const float* __restrict__ g1, const float* __restrict__ b1,
                            const float* __restrict__ m1, const float* __restrict__ v1,
                            const float* __restrict__ g3, const float* __restrict__ b3,
                            const float* __restrict__ m3, const float* __restrict__ v3)
{
    __shared__ float xs[64 * 61];
    __shared__ float s1a[64], s1b[64], s3a[64], s3b[64];
    int b = blockIdx.x, t = threadIdx.x;

    if (t < 64) {
        float i1 = g1[t] * rsqrtf(v1[t] + EPSV);
        s1a[t] = i1; s1b[t] = b1[t] - m1[t] * i1;
        float i3 = g3[t] * rsqrtf(v3[t] + EPSV);
        s3a[t] = i3; s3b[t] = b3[t] - m3[t] * i3;
    }
    const float* xb = x + (size_t)b * (CIN * RPOS);
    for (int i = t; i < CIN * RPOS; i += 256)
        xs[(i / RPOS) * 61 + (i % RPOS)] = xb[i];
    __syncthreads();

    __half2* y1f = (__half2*)g_y1f + (size_t)b * (RPOS * 32);
    __half2* y3f = (__half2*)g_y3f + (size_t)b * (RPOS * 32);
    for (int i = t; i < RPOS * 32; i += 256) {
        int j = i >> 5, c = (i & 31) * 2;
        float xa = xs[c * 61 + j], xc = xs[(c + 1) * 61 + j];
        float a1 = fmaxf(fmaf(xa, s1a[c], s1b[c]), 0.0f);
        float b1v = fmaxf(fmaf(xc, s1a[c + 1], s1b[c + 1]), 0.0f);
        float a3 = fmaxf(fmaf(xa, s3a[c], s3b[c]), 0.0f);
        float b3v = fmaxf(fmaf(xc, s3a[c + 1], s3b[c + 1]), 0.0f);
        y1f[i] = __floats2half2_rn(a1, b1v);
        y3f[i] = __floats2half2_rn(a3, b3v);
    }
}

// ---------------------------------------------------------------------------
// packW: all weights single fp16, XOR swizzle pre-applied.
// ---------------------------------------------------------------------------
__global__ void packW_kernel(const float* __restrict__ W1, const float* __restrict__ W2,
                             const float* __restrict__ W3)
{
    int idx = blockIdx.x * 256 + threadIdx.x;
    const int n1 = KW * CMID * CIN, n2 = KW * COUT * CMID;
    const float* W; __half* dst; int O, nloc;
    if (idx < n1)              { W = W1; dst = g_W1p; O = CMID; nloc = idx;           }
    else if (idx < n1 + n2)    { W = W2; dst = g_W2p; O = COUT; nloc = idx - n1;      }
    else if (idx < n1 + 2*n2)  { W = W3; dst = g_W3p; O = COUT; nloc = idx - n1 - n2; }
    else return;
    int k = nloc / (O * 64), rem = nloc % (O * 64);
    int o = rem / 64, c = rem % 64;
    float v = W[o * (64 * KW) + c * KW + k];
    int sw = ((c >> 3) ^ (o & 7)) * 8 + (c & 7);
    dst[(size_t)(k * O + o) * 64 + sw] = __float2half_rn(v);
}

// ---------------------------------------------------------------------------
// conv_mid: fp16 1-pass. CTA = 2 batches, M=128 (120 real), N=64.
// 256 threads, 8 warps (4m x 2n), warp tile 32x32. W triple-buffered.
// 2 CTAs/SM (independent barrier domains -> LDSM/MMA phase overlap).
// smem: Y1 15360 | W 3x8192 | nei | bias  (~44 KB/CTA)
// ---------------------------------------------------------------------------
#define MIDY  15360u
#define MIDW  8192u
#define MIDNEI (MIDY + 3u * MIDW)
#define MIDBIAS (MIDNEI + 3136u)

__global__ __launch_bounds__(256, 2)
void conv_mid_kernel(const int* __restrict__ nei, const float* __restrict__ c1,
                     const float* __restrict__ g2, const float* __restrict__ b2,
                     const float* __restrict__ m2, const float* __restrict__ v2)
{
    extern __shared__ __align__(1024) char smb[];
    uint32_t sbase = smem_u32(smb);

    int t = threadIdx.x, wid = t >> 5, l = t & 31;
    int*   snei  = (int*)(smb + MIDNEI);
    float* sbias = (float*)(smb + MIDBIAS);

    for (int i = t; i < RPOS * KW; i += 256) snei[i] = nei[i];
    if (t < 64) {
        sbias[t] = c1[t];
        float iv = g2[t] * rsqrtf(v2[t] + EPSV);
        sbias[64 + t] = iv; sbias[128 + t] = b2[t] - m2[t] * iv;
    }

    int b0 = blockIdx.x * 2;

    // W copy: 64 rows x 128B = 8192B; 256 threads -> 32B each
    int wrow = t >> 2, wq = t & 3;
    uint32_t wdstoff = (uint32_t)(wrow * 128 + wq * 32);
    size_t  wsrcoff = ((size_t)wrow << 7) + (size_t)(wq * 32);

    if (t < 120) {
        int bb = t / 60, r = t % 60;
        const char* src = (const char*)g_y1f + (((size_t)(b0 + bb) * RPOS + r) << 7);
        copy_row8(sbase + (uint32_t)(bb * 7680 + r * 128), src, (r & 7) << 4);
    }
    {
        const char* ws = (const char*)g_W1p + wsrcoff;
        uint32_t dst = sbase + MIDY + wdstoff;
        CP_ASYNC16(dst, ws); CP_ASYNC16(dst + 16, ws + 16);
        CP_COMMIT();
        ws = (const char*)g_W1p + wsrcoff + ((size_t)CMID << 7);
        dst = sbase + MIDY + MIDW + wdstoff;
        CP_ASYNC16(dst, ws); CP_ASYNC16(dst + 16, ws + 16);
        CP_COMMIT();
    }

    int m0 = (wid & 3) * 32, n0 = (wid >> 2) * 32;
    int lrA = l & 15, lgA = l >> 4;
    int lrB = (l & 7) + ((l >> 4) << 3), lgB = (l >> 3) & 1;
    int bkey = lrB & 7;
    uint32_t browoff[2];
#pragma unroll
    for (int q = 0; q < 2; q++) browoff[q] = (uint32_t)((n0 + q * 16 + lrB) << 7);

    int rB13[2]; uint32_t bOff[2];
#pragma unroll
    for (int mt = 0; mt < 2; mt++) {
        int m = m0 + mt * 16 + lrA;
        int bb = (m < 120) ? (m / 60) : 0;
        int r  = (m < 120) ? (m - bb * 60) : (m - 120);
        rB13[mt] = r * KW;
        bOff[mt] = (uint32_t)(bb * 7680);
    }

    float acc[2][4][4];
#pragma unroll
    for (int a = 0; a < 2; a++)
#pragma unroll
        for (int b = 0; b < 4; b++)
#pragma unroll
            for (int c = 0; c < 4; c++) acc[a][b][c] = 0.0f;

    int sc = 0;
    for (int s = 0; s < KW; s++) {
        if (s + 2 < KW) { CP_WAIT(1); } else { CP_WAIT(0); }
        __syncthreads();
        if (s + 2 < KW) {
            int slot_n = sc + 2; if (slot_n >= 3) slot_n -= 3;
            const char* ws = (const char*)g_W1p + wsrcoff + ((size_t)((s + 2) * CMID) << 7);
            uint32_t dst = sbase + MIDY + (uint32_t)slot_n * MIDW + wdstoff;
            CP_ASYNC16(dst, ws); CP_ASYNC16(dst + 16, ws + 16);
            CP_COMMIT();
        }

        uint32_t Wb = sbase + MIDY + (uint32_t)sc * MIDW;
        uint32_t arow[2]; int akey[2];
#pragma unroll
        for (int mt = 0; mt < 2; mt++) {
            int j = snei[rB13[mt] + s];
            arow[mt] = sbase + bOff[mt] + (uint32_t)(j << 7);
            akey[mt] = j & 7;
        }

#pragma unroll
        for (int ks = 0; ks < 4; ks++) {
            uint32_t af[2][4];
#pragma unroll
            for (int mt = 0; mt < 2; mt++) {
                uint32_t ad = arow[mt] + (uint32_t)((((ks << 1) + lgA) ^ akey[mt]) << 4);
                LDMX4(af[mt][0], af[mt][1], af[mt][2], af[mt][3], ad);
            }
#pragma unroll
            for (int q = 0; q < 2; q++) {
                uint32_t bh[4];
                uint32_t bd = Wb + browoff[q]
                            + (uint32_t)((((ks << 1) + lgB) ^ bkey) << 4);
                LDMX4(bh[0], bh[1], bh[2], bh[3], bd);
#pragma unroll
                for (int mt = 0; mt < 2; mt++)
#pragma unroll
                    for (int hf = 0; hf < 2; hf++)
                        mma_f16(acc[mt][q * 2 + hf], af[mt], &bh[hf * 2]);
            }
        }
        sc = (sc == 2) ? 0 : sc + 1;
    }

    // epilogue: bn2+relu -> fp16 y2
#pragma unroll
    for (int mt = 0; mt < 2; mt++)
#pragma unroll
        for (int nt = 0; nt < 4; nt++) {
            float* d = acc[mt][nt];
            int o = n0 + nt * 8 + ((l & 3) << 1);
            float cv0 = sbias[o],       cv1 = sbias[o + 1];
            float i0  = sbias[64 + o],  i1  = sbias[65 + o];
            float a0  = sbias[128 + o], a1  = sbias[129 + o];
#pragma unroll
            for (int h = 0; h < 2; h++) {
                int m = m0 + mt * 16 + (l >> 2) + h * 8;
                if (m < 120) {
                    int bb = m / 60; int r = m - bb * 60;
                    float y0 = fmaxf(fmaf(d[h * 2]     + cv0, i0, a0), 0.0f);
                    float y1 = fmaxf(fmaf(d[h * 2 + 1] + cv1, i1, a1), 0.0f);
                    size_t off = (((size_t)(b0 + bb) * RPOS + r) << 5) + (o >> 1);
                    ((__half2*)g_y2f)[off] = __floats2half2_rn(y0, y1);
                }
            }
        }
}

// ---------------------------------------------------------------------------
// conv_out: fp16 1-pass. CTA = 2 batches, M=128 (120 real), N=128, 26 stages.
// 256 threads, 8 warps (4m x 2n), warp tile 32x64. W triple-buffered.
// 2 CTAs/SM. smem: Y2 15360 | Y3 15360 | W 3x16384 | nei | bias (~84 KB/CTA)
// ---------------------------------------------------------------------------
#define OY3   15360u
#define OWO   30720u
#define OW    16384u
#define ONEI  (OWO + 3u * OW)
#define OBIAS (ONEI + 3136u)

__global__ __launch_bounds__(256, 2)
void conv_out_kernel(const int* __restrict__ nei, const float* __restrict__ c2,
                     const float* __restrict__ c3, float* __restrict__ out)
{
    extern __shared__ __align__(1024) char smb[];
    uint32_t sbase = smem_u32(smb);

    int t = threadIdx.x, wid = t >> 5, l = t & 31;
    int*   snei  = (int*)(smb + ONEI);
    float* sbias = (float*)(smb + OBIAS);

    for (int i = t; i < RPOS * KW; i += 256) snei[i] = nei[i];
    if (t < 128) sbias[t] = c2[t] + c3[t];

    int b0 = blockIdx.x * 2;

    // W copy: 128 rows x 128B; 256 threads -> 64B each (half rows)
    int wrow = t >> 1, whalf = t & 1;
    uint32_t wdstoff = (uint32_t)(wrow * 128 + whalf * 64);
    size_t  wsrcoff = ((size_t)wrow << 7) + (size_t)(whalf * 64);

    // prologue: y2 + y3 (240 rows, fp16) + W(0), W(1)
    if (t < 240) {
        int ten = t / 120, rem = t % 120, bb = rem / 60, r = rem % 60;
        const char* src = (const char*)(ten ? (const void*)g_y3f : (const void*)g_y2f)
                        + (((size_t)(b0 + bb) * RPOS + r) << 7);
        copy_row8(sbase + (uint32_t)(ten ? OY3 : 0u) + (uint32_t)(bb * 7680 + r * 128),
                  src, (r & 7) << 4);
    }
    {
        const char* ws = (const char*)g_W2p + wsrcoff;
        uint32_t dst = sbase + OWO + wdstoff;
#pragma unroll
        for (int g = 0; g < 4; g++) CP_ASYNC16(dst + (g << 4), ws + (g << 4));
        CP_COMMIT();
        ws = (const char*)g_W2p + wsrcoff + ((size_t)COUT << 7);
        dst = sbase + OWO + OW + wdstoff;
#pragma unroll
        for (int g = 0; g < 4; g++) CP_ASYNC16(dst + (g << 4), ws + (g << 4));
        CP_COMMIT();
    }

    int m0 = (wid & 3) * 32, n0 = (wid >> 2) * 64;
    int lrA = l & 15, lgA = l >> 4;
    int lrB = (l & 7) + ((l >> 4) << 3), lgB = (l >> 3) & 1;
    int bkey = lrB & 7;
    uint32_t browoff[4];
#pragma unroll
    for (int q = 0; q < 4; q++) browoff[q] = (uint32_t)((n0 + q * 16 + lrB) << 7);

    int rB13[2]; uint32_t bOff[2];
#pragma unroll
    for (int mt = 0; mt < 2; mt++) {
        int m = m0 + mt * 16 + lrA;
        int bb = (m < 120) ? (m / 60) : 0;
        int r  = (m < 120) ? (m - bb * 60) : (m - 120);
        rB13[mt] = r * KW;
        bOff[mt] = (uint32_t)(bb * 7680);
    }

    float acc[2][8][4];
#pragma unroll
    for (int a = 0; a < 2; a++)
#pragma unroll
        for (int b = 0; b < 8; b++)
#pragma unroll
            for (int c = 0; c < 4; c++) acc[a][b][c] = 0.0f;

    const int S = 2 * KW;
    int sc = 0;
    for (int s = 0; s < S; s++) {
        if (s + 2 < S) { CP_WAIT(1); } else { CP_WAIT(0); }
        __syncthreads();
        if (s + 2 < S) {
            int sn = s + 2;
            int phn = sn >= KW, kn = sn - (phn ? KW : 0);
            int slot_n = sc + 2; if (slot_n >= 3) slot_n -= 3;
            const char* ws = (const char*)(phn ? g_W3p : g_W2p) + wsrcoff
                           + ((size_t)(kn * COUT) << 7);
            uint32_t dst = sbase + OWO + (uint32_t)slot_n * OW + wdstoff;
#pragma unroll
            for (int g = 0; g < 4; g++) CP_ASYNC16(dst + (g << 4), ws + (g << 4));
            CP_COMMIT();
        }

        int ph = (s >= KW), k = s - (ph ? KW : 0);
        uint32_t Yb = sbase + (uint32_t)(ph ? OY3 : 0u);
        uint32_t Wb = sbase + OWO + (uint32_t)sc * OW;

        uint32_t arow[2]; int akey[2];
#pragma unroll
        for (int mt = 0; mt < 2; mt++) {
            int j = snei[rB13[mt] + k];
            arow[mt] = Yb + bOff[mt] + (uint32_t)(j << 7);
            akey[mt] = j & 7;
        }

#pragma unroll
        for (int ks = 0; ks < 4; ks++) {
            uint32_t af[2][4];
#pragma unroll
            for (int mt = 0; mt < 2; mt++) {
                uint32_t ad = arow[mt] + (uint32_t)((((ks << 1) + lgA) ^ akey[mt]) << 4);
                LDMX4(af[mt][0], af[mt][1], af[mt][2], af[mt][3], ad);
            }
#pragma unroll
            for (int q = 0; q < 4; q++) {
                uint32_t bh[4];
                uint32_t bd = Wb + browoff[q]
                            + (uint32_t)((((ks << 1) + lgB) ^ bkey) << 4);
                LDMX4(bh[0], bh[1], bh[2], bh[3], bd);
#pragma unroll
                for (int mt = 0; mt < 2; mt++)
#pragma unroll
                    for (int hf = 0; hf < 2; hf++)
                        mma_f16(acc[mt][q * 2 + hf], af[mt], &bh[hf * 2]);
            }
        }
        sc = (sc == 2) ? 0 : sc + 1;
    }

    // epilogue: +bias, direct global stores (out [b][o][r])
#pragma unroll
    for (int mt = 0; mt < 2; mt++)
#pragma unroll
        for (int nc = 0; nc < 8; nc++) {
            float* d = acc[mt][nc];
            int o = n0 + nc * 8 + ((l & 3) << 1);
            float bv0 = sbias[o], bv1 = sbias[o + 1];
#pragma unroll
            for (int h = 0; h < 2; h++) {
                int m = m0 + mt * 16 + (l >> 2) + h * 8;
                if (m < 120) {
                    int bb = m / 60; int r = m - bb * 60;
                    float* dp = out + ((size_t)(b0 + bb) * COUT + o) * RPOS + r;
                    dp[0]    = d[h * 2]     + bv0;
                    dp[RPOS] = d[h * 2 + 1] + bv1;
                }
            }
        }
}

// ---------------------------------------------------------------------------
extern "C" void kernel_launch(void* const* d_in, const int* in_sizes, int n_in,
                              void* d_out, int out_size)
{
    const float* x   = (const float*)d_in[0];
    const int*   nei = (const int*)d_in[1];
    const float* g1 = (const float*)d_in[2];
    const float* b1 = (const float*)d_in[3];
    const float* m1 = (const float*)d_in[4];
    const float* v1 = (const float*)d_in[5];
    const float* W1 = (const float*)d_in[6];
    const float* c1 = (const float*)d_in[7];
    const float* g2 = (const float*)d_in[8];
    const float* b2 = (const float*)d_in[9];
    const float* m2 = (const float*)d_in[10];
    const float* v2 = (const float*)d_in[11];
    const float* W2 = (const float*)d_in[12];
    const float* c2 = (const float*)d_in[13];
    const float* g3 = (const float*)d_in[14];
    const float* b3 = (const float*)d_in[15];
    const float* m3 = (const float*)d_in[16];
    const float* v3 = (const float*)d_in[17];
    const float* W3 = (const float*)d_in[18];
    const float* c3 = (const float*)d_in[19];
    float* out = (float*)d_out;

    const int smem_mid = (int)(MIDBIAS + 768 + 256);   // ~44 KB
    const int smem_out = (int)(OBIAS + 512 + 256);     // ~84 KB
    cudaFuncSetAttribute(conv_mid_kernel, cudaFuncAttributeMaxDynamicSharedMemorySize, smem_mid);
    cudaFuncSetAttribute(conv_out_kernel, cudaFuncAttributeMaxDynamicSharedMemorySize, smem_out);

    prep_kernel<<<BATCH, 256>>>(x, g1, b1, m1, v1, g3, b3, m3, v3);
    packW_kernel<<<(KW * (CMID * CIN + 2 * COUT * CMID) + 255) / 256, 256>>>(W1, W2, W3);
    conv_mid_kernel<<<BATCH / 2, 256, smem_mid>>>(nei, c1, g2, b2, m2, v2);
    conv_out_kernel<<<BATCH / 2, 256, smem_out>>>(nei, c2, c3, out);
}

// round 13
// speedup vs baseline: 4.1735x; 1.0502x over previous
#include <cuda_runtime.h>
#include <cuda_fp16.h>
#include <cstdint>

#define BATCH 2048
#define RPOS  60
#define KW    13
#define CIN   64
#define CMID  64
#define COUT  128
#define EPSV  1e-5f

__device__ __align__(128) __half g_W1p[KW * CMID * CIN];
__device__ __align__(128) __half g_W2p[KW * COUT * CMID];
__device__ __align__(128) __half g_W3p[KW * COUT * CMID];

__device__ __forceinline__ uint32_t smem_u32(const void* p) {
    uint32_t a;
    asm("{ .reg .u64 t; cvta.to.shared.u64 t, %1; cvt.u32.u64 %0, t; }" : "=r"(a) : "l"(p));
    return a;
}

#define CP_ASYNC16(dst, src) \
    asm volatile("cp.async.cg.shared.global [%0], [%1], 16;" :: "r"(dst), "l"(src) : "memory")
#define CP_COMMIT()  asm volatile("cp.async.commit_group;" ::: "memory")
#define CP_WAIT(n)   asm volatile("cp.async.wait_group %0;" :: "n"(n) : "memory")

#define LDMX4(r0, r1, r2, r3, addr) \
    asm volatile("ldmatrix.sync.aligned.m8n8.x4.shared.b16 {%0,%1,%2,%3}, [%4];" \
        : "=r"(r0), "=r"(r1), "=r"(r2), "=r"(r3) : "r"(addr))

__device__ __forceinline__ void mma_f16(float* d, const uint32_t* a, const uint32_t* b) {
    asm volatile("mma.sync.aligned.m16n8k16.row.col.f32.f16.f16.f32 "
        "{%0,%1,%2,%3},{%4,%5,%6,%7},{%8,%9},{%0,%1,%2,%3};"
        : "+f"(d[0]), "+f"(d[1]), "+f"(d[2]), "+f"(d[3])
        : "r"(a[0]), "r"(a[1]), "r"(a[2]), "r"(a[3]), "r"(b[0]), "r"(b[1]));
}

__global__ void packW_kernel(const float* __restrict__ W1, const float* __restrict__ W2,
                             const float* __restrict__ W3)
{
    int idx = blockIdx.x * 256 + threadIdx.x;
    const int n1 = KW * CMID * CIN, n2 = KW * COUT * CMID;
    const float* W; __half* dst; int O, nloc;
    if (idx < n1)              { W = W1; dst = g_W1p; O = CMID; nloc = idx;           }
    else if (idx < n1 + n2)    { W = W2; dst = g_W2p; O = COUT; nloc = idx - n1;      }
    else if (idx < n1 + 2*n2)  { W = W3; dst = g_W3p; O = COUT; nloc = idx - n1 - n2; }
    else return;
    int k = nloc / (O * 64), rem = nloc % (O * 64);
    int o = rem / 64, c = rem % 64;
    float v = W[o * (64 * KW) + c * KW + k];
    int sw = ((c >> 3) ^ (o & 7)) * 8 + (c & 7);
    dst[(size_t)(k * O + o) * 64 + sw] = __float2half_rn(v);
}

#define FY1   0u
#define FY2   15360u
#define FY3   30720u
#define FWO   46080u
#define FNEI  (46080u + 49152u)
#define FBIAS (FNEI + 3200u)
#define FTOT  (FBIAS + 2304u)

__global__ __launch_bounds__(256, 2)
void fused_kernel(const float* __restrict__ x, const int* __restrict__ nei,
                  const float* __restrict__ g1, const float* __restrict__ b1,
                  const float* __restrict__ m1, const float* __restrict__ v1,
                  const float* __restrict__ c1,
                  const float* __restrict__ g2, const float* __restrict__ b2,
                  const float* __restrict__ m2, const float* __restrict__ v2,
                  const float* __restrict__ g3, const float* __restrict__ b3,
                  const float* __restrict__ m3, const float* __restrict__ v3,
                  const float* __restrict__ cc2, const float* __restrict__ cc3,
                  float* __restrict__ out)
{
    extern __shared__ __align__(1024) char smb[];
    uint32_t sbase = smem_u32(smb);

    int t = threadIdx.x, wid = t >> 5, l = t & 31;
    int*   snei = (int*)(smb + FNEI);
    float* sb   = (float*)(smb + FBIAS);

    for (int i = t; i < RPOS * KW; i += 256) snei[i] = nei[i];
    if (t < 64) {
        sb[t] = c1[t];
        float iv = g2[t] * rsqrtf(v2[t] + EPSV);
        sb[64 + t] = iv; sb[128 + t] = b2[t] - m2[t] * iv;
        float i1 = g1[t] * rsqrtf(v1[t] + EPSV);
        sb[192 + t] = i1; sb[256 + t] = b1[t] - m1[t] * i1;
        float i3 = g3[t] * rsqrtf(v3[t] + EPSV);
        sb[320 + t] = i3; sb[384 + t] = b3[t] - m3[t] * i3;
    }
    if (t < 128) sb[448 + t] = cc2[t] + cc3[t];

    int b0 = blockIdx.x * 2;

    // prologue A: stage x into W-slot region (floats, [bb][c][j] stride 61)
    float* xs = (float*)(smb + FWO);
    const float* xsrc = x + (size_t)b0 * (CIN * RPOS);
    for (int i = t; i < 2 * CIN * RPOS; i += 256) {
        int bb = i / 3840, rem = i - bb * 3840;
        int c = rem / 60, j = rem - c * 60;
        xs[(bb * 64 + c) * 61 + j] = xsrc[i];
    }
    __syncthreads();

    // prologue B: y1, y3 fp16 tiles (per-row swizzle key = r&7, r within batch)
    for (int i = t; i < 2 * RPOS * 32; i += 256) {
        int bb = i / 1920, rem = i - bb * 1920;
        int r = rem >> 5, cp = rem & 31, c = cp * 2;
        const float* xc = xs + (bb * 64 + c) * 61 + r;
        float xa = xc[0], xb2 = xc[61];
        float a1  = fmaxf(fmaf(xa,  sb[192 + c], sb[256 + c]), 0.0f);
        float b1v = fmaxf(fmaf(xb2, sb[193 + c], sb[257 + c]), 0.0f);
        float a3  = fmaxf(fmaf(xa,  sb[320 + c], sb[384 + c]), 0.0f);
        float b3v = fmaxf(fmaf(xb2, sb[321 + c], sb[385 + c]), 0.0f);
        uint32_t off = (uint32_t)((bb * 60 + r) * 128
                     + (((cp >> 2) ^ (r & 7)) << 4) + ((cp & 3) << 2));
        *(__half2*)(smb + FY1 + off) = __floats2half2_rn(a1, b1v);
        *(__half2*)(smb + FY3 + off) = __floats2half2_rn(a3, b3v);
    }
    __syncthreads();   // xs consumed; W prefetch may overwrite

    int wrow1 = t >> 2, wq1 = t & 3;
    int wrow2 = t >> 1, wh2 = t & 1;

    {   // prefetch stages 0,1 (W1 k0,k1)
        const char* ws = (const char*)g_W1p + ((size_t)wrow1 << 7) + (size_t)(wq1 * 32);
        uint32_t dst = sbase + FWO + (uint32_t)(wrow1 * 128 + wq1 * 32);
        CP_ASYNC16(dst, ws); CP_ASYNC16(dst + 16, ws + 16);
        CP_COMMIT();
        ws = (const char*)g_W1p + ((size_t)(CMID + wrow1) << 7) + (size_t)(wq1 * 32);
        dst = sbase + FWO + 16384u + (uint32_t)(wrow1 * 128 + wq1 * 32);
        CP_ASYNC16(dst, ws); CP_ASYNC16(dst + 16, ws + 16);
        CP_COMMIT();
    }

    int m0 = (wid & 3) * 32;
    int n1_0 = (wid >> 2) * 32;
    int n2_0 = (wid >> 2) * 64;
    int lrA = l & 15, lgA = l >> 4;
    int lrB = (l & 7) + ((l >> 4) << 3), lgB = (l >> 3) & 1;
    int bkey = lrB & 7;
    uint32_t brow1[2], brow2[4];
#pragma unroll
    for (int q = 0; q < 2; q++) brow1[q] = (uint32_t)((n1_0 + q * 16 + lrB) << 7);
#pragma unroll
    for (int q = 0; q < 4; q++) brow2[q] = (uint32_t)((n2_0 + q * 16 + lrB) << 7);

    int rB13[2]; uint32_t bOff[2];
#pragma unroll
    for (int mt = 0; mt < 2; mt++) {
        int m = m0 + mt * 16 + lrA;
        int bb = (m < 120) ? (m / 60) : 0;
        int r  = (m < 120) ? (m - bb * 60) : (m - 120);
        rB13[mt] = r * KW;
        bOff[mt] = (uint32_t)(bb * 7680);
    }

    // unified accumulator: conv1 uses groups [0,4), conv2 all 8
    float acc[2][8][4];
#pragma unroll
    for (int a = 0; a < 2; a++)
#pragma unroll
        for (int b = 0; b < 8; b++)
#pragma unroll
            for (int c = 0; c < 4; c++) acc[a][b][c] = 0.0f;

    const int S = 3 * KW;   // 39
    int sc = 0;
    for (int s = 0; s < S; s++) {
        if (s + 2 < S) { CP_WAIT(1); } else { CP_WAIT(0); }
        __syncthreads();

        if (s + 2 < S) {
            int sn = s + 2;
            int slot_n = sc + 2; if (slot_n >= 3) slot_n -= 3;
            uint32_t slot = sbase + FWO + (uint32_t)slot_n * 16384u;
            if (sn < KW) {
                const char* ws = (const char*)g_W1p
                               + ((size_t)(sn * CMID + wrow1) << 7) + (size_t)(wq1 * 32);
                uint32_t dst = slot + (uint32_t)(wrow1 * 128 + wq1 * 32);
                CP_ASYNC16(dst, ws); CP_ASYNC16(dst + 16, ws + 16);
            } else {
                int k = sn - KW;
                const __half* Wp = g_W2p;
                if (k >= KW) { k -= KW; Wp = g_W3p; }
                const char* ws = (const char*)Wp
                               + ((size_t)(k * COUT + wrow2) << 7) + (size_t)(wh2 * 64);
                uint32_t dst = slot + (uint32_t)(wrow2 * 128 + wh2 * 64);
#pragma unroll
                for (int g = 0; g < 4; g++) CP_ASYNC16(dst + (g << 4), ws + (g << 4));
            }
            CP_COMMIT();
        }

        if (s == KW) {
            // conv1 epilogue: y2 = relu(bn2(conv1 + c1)) -> smem tile.
            // Swizzle key MUST be r&7 (row within batch) to match readers.
#pragma unroll
            for (int mt = 0; mt < 2; mt++)
#pragma unroll
                for (int nt = 0; nt < 4; nt++) {
                    float* d = acc[mt][nt];
                    int o = n1_0 + nt * 8 + ((l & 3) << 1);
                    float cv0 = sb[o],       cv1 = sb[o + 1];
                    float i0  = sb[64 + o],  i1  = sb[65 + o];
                    float a0  = sb[128 + o], a1  = sb[129 + o];
#pragma unroll
                    for (int h = 0; h < 2; h++) {
                        int m = m0 + mt * 16 + (l >> 2) + h * 8;
                        if (m < 120) {
                            int r = (m >= 60) ? (m - 60) : m;
                            float y0 = fmaxf(fmaf(d[h * 2]     + cv0, i0, a0), 0.0f);
                            float y1 = fmaxf(fmaf(d[h * 2 + 1] + cv1, i1, a1), 0.0f);
                            uint32_t off = (uint32_t)(m * 128
                                         + (((o >> 3) ^ (r & 7)) << 4) + ((o & 7) << 1));
                            *(__half2*)(smb + FY2 + off) = __floats2half2_rn(y0, y1);
                        }
                    }
                }
            // reset ALL accumulator groups for conv2
#pragma unroll
            for (int a = 0; a < 2; a++)
#pragma unroll
                for (int b = 0; b < 8; b++)
#pragma unroll
                    for (int c = 0; c < 4; c++) acc[a][b][c] = 0.0f;
            __syncthreads();
        }

        uint32_t Wb = sbase + FWO + (uint32_t)sc * 16384u;

        if (s < KW) {
            uint32_t arow[2]; int akey[2];
#pragma unroll
            for (int mt = 0; mt < 2; mt++) {
                int j = snei[rB13[mt] + s];
                arow[mt] = sbase + FY1 + bOff[mt] + (uint32_t)(j << 7);
                akey[mt] = j & 7;
            }
#pragma unroll
            for (int ks = 0; ks < 4; ks++) {
                uint32_t af[2][4];
#pragma unroll
                for (int mt = 0; mt < 2; mt++) {
                    uint32_t ad = arow[mt] + (uint32_t)((((ks << 1) + lgA) ^ akey[mt]) << 4);
                    LDMX4(af[mt][0], af[mt][1], af[mt][2], af[mt][3], ad);
                }
#pragma unroll
                for (int q = 0; q < 2; q++) {
                    uint32_t bh[4];
                    uint32_t bd = Wb + brow1[q]
                                + (uint32_t)((((ks << 1) + lgB) ^ bkey) << 4);
                    LDMX4(bh[0], bh[1], bh[2], bh[3], bd);
#pragma unroll
                    for (int mt = 0; mt < 2; mt++)
#pragma unroll
                        for (int hf = 0; hf < 2; hf++)
                            mma_f16(acc[mt][q * 2 + hf], af[mt], &bh[hf * 2]);
                }
            }
        } else {
            int ph = (s >= 2 * KW);
            int kk = s - (ph ? 2 * KW : KW);
            uint32_t Yb = sbase + (ph ? FY3 : FY2);
            uint32_t arow[2]; int akey[2];
#pragma unroll
            for (int mt = 0; mt < 2; mt++) {
                int j = snei[rB13[mt] + kk];
                arow[mt] = Yb + bOff[mt] + (uint32_t)(j << 7);
                akey[mt] = j & 7;
            }
#pragma unroll
            for (int ks = 0; ks < 4; ks++) {
                uint32_t af[2][4];
#pragma unroll
                for (int mt = 0; mt < 2; mt++) {
                    uint32_t ad = arow[mt] + (uint32_t)((((ks << 1) + lgA) ^ akey[mt]) << 4);
                    LDMX4(af[mt][0], af[mt][1], af[mt][2], af[mt][3], ad);
                }
#pragma unroll
                for (int q = 0; q < 4; q++) {
                    uint32_t bh[4];
                    uint32_t bd = Wb + brow2[q]
                                + (uint32_t)((((ks << 1) + lgB) ^ bkey) << 4);
                    LDMX4(bh[0], bh[1], bh[2], bh[3], bd);
#pragma unroll
                    for (int mt = 0; mt < 2; mt++)
#pragma unroll
                        for (int hf = 0; hf < 2; hf++)
                            mma_f16(acc[mt][q * 2 + hf], af[mt], &bh[hf * 2]);
                }
            }
        }
        sc = (sc == 2) ? 0 : sc + 1;
    }

    // final epilogue: +(c2+c3), out [b][o][r]
#pragma unroll
    for (int mt = 0; mt < 2; mt++)
#pragma unroll
        for (int nc = 0; nc < 8; nc++) {
            float* d = acc[mt][nc];
            int o = n2_0 + nc * 8 + ((l & 3) << 1);
            float bv0 = sb[448 + o], bv1 = sb[449 + o];
#pragma unroll
            for (int h = 0; h < 2; h++) {
                int m = m0 + mt * 16 + (l >> 2) + h * 8;
                if (m < 120) {
                    int bb = m / 60; int r = m - bb * 60;
                    float* dp = out + ((size_t)(b0 + bb) * COUT + o) * RPOS + r;
                    dp[0]    = d[h * 2]     + bv0;
                    dp[RPOS] = d[h * 2 + 1] + bv1;
                }
            }
        }
}

extern "C" void kernel_launch(void* const* d_in, const int* in_sizes, int n_in,
                              void* d_out, int out_size)
{
    const float* x   = (const float*)d_in[0];
    const int*   nei = (const int*)d_in[1];
    const float* g1 = (const float*)d_in[2];
    const float* b1 = (const float*)d_in[3];
    const float* m1 = (const float*)d_in[4];
    const float* v1 = (const float*)d_in[5];
    const float* W1 = (const float*)d_in[6];
    const float* c1 = (const float*)d_in[7];
    const float* g2 = (const float*)d_in[8];
    const float* b2 = (const float*)d_in[9];
    const float* m2 = (const float*)d_in[10];
    const float* v2 = (const float*)d_in[11];
    const float* W2 = (const float*)d_in[12];
    const float* c2 = (const float*)d_in[13];
    const float* g3 = (const float*)d_in[14];
    const float* b3 = (const float*)d_in[15];
    const float* m3 = (const float*)d_in[16];
    const float* v3 = (const float*)d_in[17];
    const float* W3 = (const float*)d_in[18];
    const float* c3 = (const float*)d_in[19];
    float* out = (float*)d_out;

    const int smem_fused = (int)FTOT + 256;
    cudaFuncSetAttribute(fused_kernel, cudaFuncAttributeMaxDynamicSharedMemorySize, smem_fused);

    packW_kernel<<<(KW * (CMID * CIN + 2 * COUT * CMID) + 255) / 256, 256>>>(W1, W2, W3);
    fused_kernel<<<BATCH / 2, 256, smem_fused>>>(x, nei,
        g1, b1, m1, v1, c1, g2, b2, m2, v2, g3, b3, m3, v3, c2, c3, out);
}